// round 2
// baseline (speedup 1.0000x reference)
#include <cuda_runtime.h>
#include <math.h>

#define CD 128
#define MTOT 4096

struct Job { const float* in; const float* wt; const float* res; const float* bias; float* out; };

__device__ float g_y1[MTOT*CD], g_qb[MTOT*CD], g_kb[MTOT*CD], g_vb[MTOT*CD];
__device__ float g_attn[MTOT*CD], g_hb[MTOT*CD], g_a1[MTOT*CD], g_a2[MTOT*CD], g_a3[MTOT*CD];
__device__ float g_x2[MTOT*CD], g_y2[MTOT*CD], g_xm[MTOT];
__device__ float g_wq[27*CD*CD], g_wk[8*CD*CD], g_wv[CD*CD];
__device__ float g_wr1[27*CD*CD], g_wr2[8*CD*CD], g_wr3[CD*CD], g_wp[CD*CD];

// (co,ci,taps) -> [tap][ci][co]
__global__ void wtrans_kernel(const float* __restrict__ src, float* __restrict__ dst, int KK) {
    int idx = blockIdx.x * 256 + threadIdx.x;
    if (idx >= CD*CD*KK) return;
    int tap = idx / (CD*CD); int rem = idx - tap*(CD*CD);
    int ci = rem >> 7, co = rem & 127;
    dst[idx] = src[(co*CD + ci)*KK + tap];
}

__global__ void ln_kernel(const float* __restrict__ in, float* __restrict__ out,
                          const float* __restrict__ gam, const float* __restrict__ bet,
                          float* __restrict__ xm, float eps) {
    int m = blockIdx.x, c = threadIdx.x, lane = c & 31, wid = c >> 5;
    float v = in[m*CD + c], s = v, sq = v*v;
    #pragma unroll
    for (int o = 16; o > 0; o >>= 1) { s += __shfl_xor_sync(~0u, s, o); sq += __shfl_xor_sync(~0u, sq, o); }
    __shared__ float ss[4], sqq[4], ys[4];
    if (lane == 0) { ss[wid] = s; sqq[wid] = sq; }
    __syncthreads();
    float S = ss[0]+ss[1]+ss[2]+ss[3], SQ = sqq[0]+sqq[1]+sqq[2]+sqq[3];
    float mean = S*(1.0f/CD), var = SQ*(1.0f/CD) - mean*mean, rs = rsqrtf(var + eps);
    float y = (v - mean)*rs*gam[c] + bet[c];
    out[m*CD + c] = y;
    if (xm) {
        float t = y;
        #pragma unroll
        for (int o = 16; o > 0; o >>= 1) t += __shfl_xor_sync(~0u, t, o);
        if (lane == 0) ys[wid] = t;
        __syncthreads();
        if (c == 0) xm[m] = (ys[0]+ys[1]+ys[2]+ys[3])*(1.0f/CD);
    }
}

__global__ void bn_kernel(float* __restrict__ buf, const float* __restrict__ gam,
                          const float* __restrict__ bet) {
    int ch = blockIdx.x, tid = threadIdx.x;
    float s = 0.f, sq = 0.f;
    for (int m = tid; m < MTOT; m += 256) { float v = buf[m*CD + ch]; s += v; sq += v*v; }
    int lane = tid & 31, wid = tid >> 5;
    #pragma unroll
    for (int o = 16; o > 0; o >>= 1) { s += __shfl_xor_sync(~0u, s, o); sq += __shfl_xor_sync(~0u, sq, o); }
    __shared__ float ss[8], sqq[8];
    if (lane == 0) { ss[wid] = s; sqq[wid] = sq; }
    __syncthreads();
    float S = 0.f, SQ = 0.f;
    #pragma unroll
    for (int w = 0; w < 8; w++) { S += ss[w]; SQ += sqq[w]; }
    float mean = S*(1.0f/MTOT), var = SQ*(1.0f/MTOT) - mean*mean;
    float scale = gam[ch]*rsqrtf(var + 1e-5f), shift = bet[ch] - mean*scale;
    for (int m = tid; m < MTOT; m += 256) buf[m*CD + ch] = buf[m*CD + ch]*scale + shift;
}

template<int KS>
__global__ void conv_gemm_kernel(Job j0, Job j1) {
    constexpr int K = KS*KS*KS*CD;
    Job jb = (blockIdx.z == 0) ? j0 : j1;
    const int m0 = blockIdx.y << 6, n0 = blockIdx.x << 6;
    __shared__ float As[16][64], Bs[16][64];
    const int tid = threadIdx.x;
    const int am = tid & 63, kgrp = tid >> 6;
    const int gm = m0 + am, bb = gm >> 11, p = gm & 2047;
    const int tt = p >> 4, ii = (p >> 2) & 3, jj = p & 3;
    const int brow = tid >> 4, bcol = (tid & 15) << 2;
    const int ty = tid >> 4, tx = tid & 15;
    float acc[4][4] = {};
    const float* wptr = jb.wt + brow*CD + n0 + bcol;
    for (int kt = 0; kt < K; kt += 16) {
        float4 bv = *(const float4*)(wptr + kt*CD);
        int kg = kt + (kgrp << 2);
        int tap = kg >> 7, ci = kg & 127;
        int dt, di, dj;
        if (KS == 3) { dt = tap/9 - 1; int r9 = tap%9; di = r9/3 - 1; dj = r9%3 - 1; }
        else if (KS == 2) { dt = (tap>>2) - 1; di = ((tap>>1)&1) - 1; dj = (tap&1) - 1; }
        else { dt = di = dj = 0; }
        int t2 = tt + dt, i2 = ii + di, j2 = jj + dj;
        float4 av = make_float4(0.f,0.f,0.f,0.f);
        if ((unsigned)t2 < 128u && (unsigned)i2 < 4u && (unsigned)j2 < 4u)
            av = *(const float4*)(jb.in + ((((bb<<11) + (t2<<4)+(i2<<2)+j2)) << 7) + ci);
        __syncthreads();
        int k4 = kgrp << 2;
        As[k4+0][am] = av.x; As[k4+1][am] = av.y; As[k4+2][am] = av.z; As[k4+3][am] = av.w;
        *(float4*)&Bs[brow][bcol] = bv;
        __syncthreads();
        #pragma unroll
        for (int kk = 0; kk < 16; kk++) {
            float4 a = *(const float4*)&As[kk][ty<<2];
            float4 b = *(const float4*)&Bs[kk][tx<<2];
            acc[0][0] += a.x*b.x; acc[0][1] += a.x*b.y; acc[0][2] += a.x*b.z; acc[0][3] += a.x*b.w;
            acc[1][0] += a.y*b.x; acc[1][1] += a.y*b.y; acc[1][2] += a.y*b.z; acc[1][3] += a.y*b.w;
            acc[2][0] += a.z*b.x; acc[2][1] += a.z*b.y; acc[2][2] += a.z*b.z; acc[2][3] += a.z*b.w;
            acc[3][0] += a.w*b.x; acc[3][1] += a.w*b.y; acc[3][2] += a.w*b.z; acc[3][3] += a.w*b.w;
        }
    }
    int c0 = n0 + (tx << 2);
    float4 bias4 = make_float4(0.f,0.f,0.f,0.f);
    if (jb.bias) bias4 = *(const float4*)(jb.bias + c0);
    #pragma unroll
    for (int r = 0; r < 4; r++) {
        int m = m0 + (ty<<2) + r;
        float4 o = make_float4(acc[r][0]+bias4.x, acc[r][1]+bias4.y, acc[r][2]+bias4.z, acc[r][3]+bias4.w);
        if (jb.res) {
            float4 rr = *(const float4*)(jb.res + m*CD + c0);
            o.x += rr.x; o.y += rr.y; o.z += rr.z; o.w += rr.w;
        }
        *(float4*)(jb.out + m*CD + c0) = o;
    }
}

// flash attention, head dim 16, plus fused conv_atten epilogue
__global__ void flash_kernel(const float* __restrict__ q, const float* __restrict__ k,
                             const float* __restrict__ v, float* __restrict__ out) {
    int bh = blockIdx.y, b = bh >> 3, h = bh & 7;
    int qbase = blockIdx.x << 6;
    __shared__ float4 ks[128][4], vs[128][4];
    int tid = threadIdx.x, wid = tid >> 5, lane = tid & 31;
    int r = lane >> 2, g = lane & 3;
    int qrow = qbase + (wid << 3) + r;
    const float* qp = q + (((b<<11) + qrow) << 7) + (h << 4);
    float4 q0 = *(const float4*)(qp), q1 = *(const float4*)(qp+4);
    float4 q2 = *(const float4*)(qp+8), q3 = *(const float4*)(qp+12);
    float acc[16];
    #pragma unroll
    for (int d = 0; d < 16; d++) acc[d] = 0.f;
    float mrow = -1e30f, lsum = 0.f;
    const float* kbase = k + (((size_t)b << 11) << 7) + (h << 4);
    const float* vbase = v + (((size_t)b << 11) << 7) + (h << 4);
    for (int kt = 0; kt < 2048; kt += 128) {
        __syncthreads();
        #pragma unroll
        for (int u = 0; u < 2; u++) {
            int idx = tid + (u << 8);
            int row = idx >> 2, c4 = idx & 3;
            ks[row][c4] = *(const float4*)(kbase + (size_t)(kt+row)*CD + (c4<<2));
            vs[row][c4] = *(const float4*)(vbase + (size_t)(kt+row)*CD + (c4<<2));
        }
        __syncthreads();
        float s[32], tmax = -1e30f;
        #pragma unroll
        for (int i = 0; i < 32; i++) {
            int kc = (i << 2) + g;
            float4 ka = ks[kc][0], kb = ks[kc][1], kc2 = ks[kc][2], kd = ks[kc][3];
            float d = q0.x*ka.x + q0.y*ka.y + q0.z*ka.z + q0.w*ka.w
                    + q1.x*kb.x + q1.y*kb.y + q1.z*kb.z + q1.w*kb.w
                    + q2.x*kc2.x + q2.y*kc2.y + q2.z*kc2.z + q2.w*kc2.w
                    + q3.x*kd.x + q3.y*kd.y + q3.z*kd.z + q3.w*kd.w;
            s[i] = d; tmax = fmaxf(tmax, d);
        }
        tmax = fmaxf(tmax, __shfl_xor_sync(~0u, tmax, 1));
        tmax = fmaxf(tmax, __shfl_xor_sync(~0u, tmax, 2));
        float mnew = fmaxf(mrow, tmax);
        float corr = __expf(mrow - mnew);
        mrow = mnew; lsum *= corr;
        #pragma unroll
        for (int d = 0; d < 16; d++) acc[d] *= corr;
        #pragma unroll
        for (int i = 0; i < 32; i++) {
            float pv = __expf(s[i] - mnew);
            lsum += pv;
            int kc = (i << 2) + g;
            float4 va = vs[kc][0], vb = vs[kc][1], vc = vs[kc][2], vd = vs[kc][3];
            acc[0] += pv*va.x; acc[1] += pv*va.y; acc[2] += pv*va.z; acc[3] += pv*va.w;
            acc[4] += pv*vb.x; acc[5] += pv*vb.y; acc[6] += pv*vb.z; acc[7] += pv*vb.w;
            acc[8] += pv*vc.x; acc[9] += pv*vc.y; acc[10] += pv*vc.z; acc[11] += pv*vc.w;
            acc[12] += pv*vd.x; acc[13] += pv*vd.y; acc[14] += pv*vd.z; acc[15] += pv*vd.w;
        }
    }
    #pragma unroll
    for (int d = 0; d < 16; d++) {
        acc[d] += __shfl_xor_sync(~0u, acc[d], 1);
        acc[d] += __shfl_xor_sync(~0u, acc[d], 2);
    }
    lsum += __shfl_xor_sync(~0u, lsum, 1);
    lsum += __shfl_xor_sync(~0u, lsum, 2);
    float inv = 1.0f / lsum;
    float a0, a1, a2, a3;
    if (g == 0)      { a0=acc[0];  a1=acc[1];  a2=acc[2];  a3=acc[3];  }
    else if (g == 1) { a0=acc[4];  a1=acc[5];  a2=acc[6];  a3=acc[7];  }
    else if (g == 2) { a0=acc[8];  a1=acc[9];  a2=acc[10]; a3=acc[11]; }
    else             { a0=acc[12]; a1=acc[13]; a2=acc[14]; a3=acc[15]; }
    size_t base = ((size_t)((b<<11) + qrow) << 7) + (h << 4);
    float av2[4] = {a0, a1, a2, a3}, ov[4];
    #pragma unroll
    for (int u = 0; u < 4; u++) {
        int w2 = (g << 2) + u;
        float ca = 0.f;
        #pragma unroll
        for (int s2 = 0; s2 < 3; s2++) {
            int f = w2 + (s2 << 4);
            int sel = f % 3;
            const float* tp = (sel == 0) ? q : ((sel == 1) ? k : v);
            ca += tp[base + f/3];
        }
        ov[u] = av2[u]*inv + ca*(1.0f/3.0f);
    }
    *(float4*)(out + base + (g << 2)) = make_float4(ov[0], ov[1], ov[2], ov[3]);
}

__global__ void combine_kernel(const float* __restrict__ a1, const float* __restrict__ a2,
                               const float* __restrict__ a3, const float* __restrict__ hh,
                               float* __restrict__ x2) {
    int idx = blockIdx.x * 256 + threadIdx.x;
    int m = idx >> 7, ch2 = idx & 127;
    float sacc = 0.f;
    #pragma unroll
    for (int s2 = 0; s2 < 3; s2++) {
        int f = ch2*3 + s2;
        const float* ap = (f >> 7) == 0 ? a1 : ((f >> 7) == 1 ? a2 : a3);
        sacc += ap[(m << 7) + (f & 127)];
    }
    x2[idx] = sacc*(1.0f/3.0f) + hh[idx];
}

__global__ void final_kernel(const float* __restrict__ x2, const float* __restrict__ y2,
                             const float* __restrict__ xm, const float* __restrict__ st1,
                             const float* __restrict__ st2, const float* __restrict__ st3,
                             float* __restrict__ out) {
    int m = blockIdx.x, b = m >> 11, p = m & 2047;
    int t = p >> 4, ii = (p >> 2) & 3, jj = p & 3;
    __shared__ float sg;
    if (threadIdx.x == 0) {
        float gg = st1[0] * xm[m];
        #pragma unroll
        for (int kd = 0; kd < 2; kd++)
        for (int kh = 0; kh < 2; kh++)
        for (int kw = 0; kw < 2; kw++) {
            int t2 = t + kd - 1, i2 = ii + kh - 1, j2 = jj + kw - 1;
            if ((unsigned)t2 < 128u && (unsigned)i2 < 4u && (unsigned)j2 < 4u)
                gg += st2[kd*4 + kh*2 + kw] * xm[(b<<11) + (t2<<4) + (i2<<2) + j2];
        }
        #pragma unroll
        for (int kd = 0; kd < 3; kd++)
        for (int kh = 0; kh < 3; kh++)
        for (int kw = 0; kw < 3; kw++) {
            int t2 = t + kd - 1, i2 = ii + kh - 1, j2 = jj + kw - 1;
            if ((unsigned)t2 < 128u && (unsigned)i2 < 4u && (unsigned)j2 < 4u)
                gg += st3[kd*9 + kh*3 + kw] * xm[(b<<11) + (t2<<4) + (i2<<2) + j2];
        }
        sg = 1.0f / (1.0f + __expf(-gg));
    }
    __syncthreads();
    int idx = m*CD + threadIdx.x;
    out[idx] = x2[idx] + y2[idx]*sg;
}

extern "C" void kernel_launch(void* const* d_in, const int* in_sizes, int n_in,
                              void* d_out, int out_size) {
    const float* x       = (const float*)d_in[0];
    const float* n1g     = (const float*)d_in[1];
    const float* n1b     = (const float*)d_in[2];
    const float* q_w     = (const float*)d_in[3];
    const float* qbg     = (const float*)d_in[4];
    const float* qbb     = (const float*)d_in[5];
    const float* k_w     = (const float*)d_in[6];
    const float* kbg     = (const float*)d_in[7];
    const float* kbb     = (const float*)d_in[8];
    const float* v_w     = (const float*)d_in[9];
    const float* proj_w  = (const float*)d_in[10];
    const float* proj_b  = (const float*)d_in[11];
    const float* r1_w    = (const float*)d_in[12];
    const float* r2_w    = (const float*)d_in[13];
    const float* r3_w    = (const float*)d_in[14];
    const float* n2g     = (const float*)d_in[15];
    const float* n2b     = (const float*)d_in[16];
    const float* st1     = (const float*)d_in[17];
    const float* st2     = (const float*)d_in[18];
    const float* st3     = (const float*)d_in[19];
    float* out = (float*)d_out;

    float *y1, *qb, *kb, *vb, *attn, *hb, *a1, *a2, *a3, *x2, *y2, *xm;
    float *wq, *wk, *wv, *wr1, *wr2, *wr3, *wp;
    cudaGetSymbolAddress((void**)&y1, g_y1);   cudaGetSymbolAddress((void**)&qb, g_qb);
    cudaGetSymbolAddress((void**)&kb, g_kb);   cudaGetSymbolAddress((void**)&vb, g_vb);
    cudaGetSymbolAddress((void**)&attn, g_attn); cudaGetSymbolAddress((void**)&hb, g_hb);
    cudaGetSymbolAddress((void**)&a1, g_a1);   cudaGetSymbolAddress((void**)&a2, g_a2);
    cudaGetSymbolAddress((void**)&a3, g_a3);   cudaGetSymbolAddress((void**)&x2, g_x2);
    cudaGetSymbolAddress((void**)&y2, g_y2);   cudaGetSymbolAddress((void**)&xm, g_xm);
    cudaGetSymbolAddress((void**)&wq, g_wq);   cudaGetSymbolAddress((void**)&wk, g_wk);
    cudaGetSymbolAddress((void**)&wv, g_wv);   cudaGetSymbolAddress((void**)&wr1, g_wr1);
    cudaGetSymbolAddress((void**)&wr2, g_wr2); cudaGetSymbolAddress((void**)&wr3, g_wr3);
    cudaGetSymbolAddress((void**)&wp, g_wp);

    auto cdiv = [](int a, int b){ return (a + b - 1) / b; };
    wtrans_kernel<<<cdiv(CD*CD*27,256),256>>>(q_w, wq, 27);
    wtrans_kernel<<<cdiv(CD*CD*8,256),256>>>(k_w, wk, 8);
    wtrans_kernel<<<cdiv(CD*CD*1,256),256>>>(v_w, wv, 1);
    wtrans_kernel<<<cdiv(CD*CD*27,256),256>>>(r1_w, wr1, 27);
    wtrans_kernel<<<cdiv(CD*CD*8,256),256>>>(r2_w, wr2, 8);
    wtrans_kernel<<<cdiv(CD*CD*1,256),256>>>(r3_w, wr3, 1);
    wtrans_kernel<<<cdiv(CD*CD*1,256),256>>>(proj_w, wp, 1);

    ln_kernel<<<MTOT, 128>>>(x, y1, n1g, n1b, nullptr, 1e-6f);

    Job jq  = { y1, wq, nullptr, nullptr, qb };
    Job jr1 = { x,  wr1, x,      nullptr, a1 };
    conv_gemm_kernel<3><<<dim3(2,64,2), 256>>>(jq, jr1);
    bn_kernel<<<CD, 256>>>(qb, qbg, qbb);

    Job jk  = { y1, wk, nullptr, nullptr, kb };
    Job jr2 = { a1, wr2, a1,     nullptr, a2 };
    conv_gemm_kernel<2><<<dim3(2,64,2), 256>>>(jk, jr2);
    bn_kernel<<<CD, 256>>>(kb, kbg, kbb);

    Job jv  = { y1, wv, nullptr, nullptr, vb };
    Job jr3 = { a2, wr3, a2,     nullptr, a3 };
    conv_gemm_kernel<1><<<dim3(2,64,2), 256>>>(jv, jr3);

    flash_kernel<<<dim3(32,16), 256>>>(qb, kb, vb, attn);

    Job jp = { attn, wp, nullptr, proj_b, hb };
    conv_gemm_kernel<1><<<dim3(2,64,1), 256>>>(jp, jp);

    combine_kernel<<<MTOT*CD/256, 256>>>(a1, a2, a3, hb, x2);
    ln_kernel<<<MTOT, 128>>>(x2, y2, n2g, n2b, xm, 1e-6f);
    final_kernel<<<MTOT, 128>>>(x2, y2, xm, st1, st2, st3, out);
}

// round 3
// speedup vs baseline: 1.0809x; 1.0809x over previous
#include <cuda_runtime.h>
#include <math.h>

#define CD 128
#define MTOT 4096

struct Job  { const float* in; const float* wt; const float* res; const float* bias; float* out; };
struct WJob { const float* src; float* dst; int KK; int n; };

__device__ float g_y1[MTOT*CD], g_qb[MTOT*CD], g_kb[MTOT*CD], g_vb[MTOT*CD];
__device__ float g_attn[MTOT*CD], g_hb[MTOT*CD], g_a1[MTOT*CD], g_a2[MTOT*CD], g_a3[MTOT*CD];
__device__ float g_x2[MTOT*CD], g_y2[MTOT*CD], g_xm[MTOT];
__device__ float g_wq[27*CD*CD], g_wk[8*CD*CD], g_wv[CD*CD];
__device__ float g_wr1[27*CD*CD], g_wr2[8*CD*CD], g_wr3[CD*CD], g_wp[CD*CD];
__device__ float g_bnst[2][2][CD];

// merged weight transpose: (co,ci,tap) -> [tap][ci][co]; optionally zeroes a buffer
__global__ void wtrans_multi(WJob j0, WJob j1, WJob j2, int nj, float* zbuf, int zn) {
    int idx = blockIdx.x * 256 + threadIdx.x;
    if (zbuf && idx < zn) zbuf[idx] = 0.f;
    WJob J; int base = 0;
    if (idx < j0.n) J = j0;
    else if (nj > 1 && idx < j0.n + j1.n) { J = j1; base = j0.n; }
    else if (nj > 2 && idx < j0.n + j1.n + j2.n) { J = j2; base = j0.n + j1.n; }
    else return;
    int t = idx - base;
    int tap = t / (CD*CD); int rem = t - tap*(CD*CD);
    int ci = rem >> 7, co = rem & 127;
    J.dst[t] = J.src[(co*CD + ci)*J.KK + tap];
}

__global__ void ln_kernel(const float* __restrict__ in, float* __restrict__ out,
                          const float* __restrict__ gam, const float* __restrict__ bet,
                          float* __restrict__ xm, float eps) {
    int m = blockIdx.x, c = threadIdx.x, lane = c & 31, wid = c >> 5;
    float v = in[m*CD + c], s = v, sq = v*v;
    #pragma unroll
    for (int o = 16; o > 0; o >>= 1) { s += __shfl_xor_sync(~0u, s, o); sq += __shfl_xor_sync(~0u, sq, o); }
    __shared__ float ss[4], sqq[4], ys[4];
    if (lane == 0) { ss[wid] = s; sqq[wid] = sq; }
    __syncthreads();
    float S = ss[0]+ss[1]+ss[2]+ss[3], SQ = sqq[0]+sqq[1]+sqq[2]+sqq[3];
    float mean = S*(1.0f/CD), var = SQ*(1.0f/CD) - mean*mean, rs = rsqrtf(var + eps);
    float y = (v - mean)*rs*gam[c] + bet[c];
    out[m*CD + c] = y;
    if (xm) {
        float t = y;
        #pragma unroll
        for (int o = 16; o > 0; o >>= 1) t += __shfl_xor_sync(~0u, t, o);
        if (lane == 0) ys[wid] = t;
        __syncthreads();
        if (c == 0) xm[m] = (ys[0]+ys[1]+ys[2]+ys[3])*(1.0f/CD);
    }
}

// coalesced BN stats for q and k at once: grid (32, 2), 256 thr
__global__ void bn_stats(const float* __restrict__ q, const float* __restrict__ k) {
    int buf = blockIdx.y;
    const float* src = buf ? k : q;
    int tid = threadIdx.x;
    int base = blockIdx.x * 128;            // 128 rows per block
    float s = 0.f, sq = 0.f;
    for (int i = tid; i < 128*CD; i += 256) {
        float v = src[(base + (i >> 7))*CD + (i & 127)];
        s += v; sq += v*v;
    }
    __shared__ float sh[256];
    sh[tid] = s; __syncthreads();
    if (tid < 128) atomicAdd(&g_bnst[buf][0][tid], sh[tid] + sh[tid+128]);
    __syncthreads();
    sh[tid] = sq; __syncthreads();
    if (tid < 128) atomicAdd(&g_bnst[buf][1][tid], sh[tid] + sh[tid+128]);
}

__global__ void bn_apply(float* __restrict__ q, float* __restrict__ k,
                         const float* __restrict__ qg, const float* __restrict__ qb2,
                         const float* __restrict__ kg, const float* __restrict__ kb2) {
    int buf = blockIdx.y;
    float* dst = buf ? k : q;
    const float* gam = buf ? kg : qg;
    const float* bet = buf ? kb2 : qb2;
    int idx = blockIdx.x * 256 + threadIdx.x;
    int c = idx & 127;
    float S = g_bnst[buf][0][c], SQ = g_bnst[buf][1][c];
    float mean = S*(1.0f/MTOT), var = SQ*(1.0f/MTOT) - mean*mean;
    float sc = gam[c]*rsqrtf(var + 1e-5f), sh = bet[c] - mean*sc;
    dst[idx] = dst[idx]*sc + sh;
}

// implicit-GEMM conv, BM=64 BN=64 BK=16, 128 thr, TM=8 TN=4, 2-stage double buffer
template<int KS>
__global__ void conv_gemm_kernel(Job j0, Job j1) {
    constexpr int K = KS*KS*KS*CD;
    constexpr int NIT = K / 16;
    Job jb = (blockIdx.z == 0) ? j0 : j1;
    const int m0 = blockIdx.y << 6, n0 = blockIdx.x << 6;
    __shared__ float As[2][16][64], Bs[2][16][64];
    const int tid = threadIdx.x;                 // 128
    const int am = tid & 63, kgA = tid >> 6;     // A: this thread loads kgroups kgA, kgA+2
    const int gm = m0 + am, bb = gm >> 11, p = gm & 2047;
    const int tt = p >> 4, ii = (p >> 2) & 3, jj = p & 3;
    const int br = tid >> 4, bc = (tid & 15) << 2;  // B: rows br, br+8
    const int ty = tid >> 4, tx = tid & 15;         // compute: 8x4 tile
    float acc[8][4] = {};

    auto ldA = [&](int kgabs) -> float4 {        // kgabs = k/4 global
        int tap = kgabs >> 5;
        int ci = (kgabs << 2) & 127;
        int dt, di, dj;
        if (KS == 3) { dt = tap/9 - 1; int r9 = tap%9; di = r9/3 - 1; dj = r9%3 - 1; }
        else if (KS == 2) { dt = (tap>>2) - 1; di = ((tap>>1)&1) - 1; dj = (tap&1) - 1; }
        else { dt = di = dj = 0; }
        int t2 = tt + dt, i2 = ii + di, j2 = jj + dj;
        if ((unsigned)t2 < 128u && (unsigned)i2 < 4u && (unsigned)j2 < 4u)
            return *(const float4*)(jb.in + (((bb<<11) + (t2<<4) + (i2<<2) + j2) << 7) + ci);
        return make_float4(0.f,0.f,0.f,0.f);
    };

    // prologue: stage 0
    {
        float4 a0 = ldA(kgA), a1 = ldA(kgA + 2);
        float4 b0 = *(const float4*)(jb.wt + (size_t)br*CD + n0 + bc);
        float4 b1 = *(const float4*)(jb.wt + (size_t)(br+8)*CD + n0 + bc);
        int k4 = kgA << 2;
        As[0][k4+0][am]=a0.x; As[0][k4+1][am]=a0.y; As[0][k4+2][am]=a0.z; As[0][k4+3][am]=a0.w;
        As[0][k4+8][am]=a1.x; As[0][k4+9][am]=a1.y; As[0][k4+10][am]=a1.z; As[0][k4+11][am]=a1.w;
        *(float4*)&Bs[0][br][bc]   = b0;
        *(float4*)&Bs[0][br+8][bc] = b1;
    }
    __syncthreads();

    for (int it = 0; it < NIT; it++) {
        int s = it & 1;
        float4 na0, na1, nb0, nb1;
        bool more = (it + 1 < NIT);
        if (more) {
            int kg = (it+1)*4;
            na0 = ldA(kg + kgA); na1 = ldA(kg + kgA + 2);
            nb0 = *(const float4*)(jb.wt + (size_t)((it+1)*16 + br)*CD + n0 + bc);
            nb1 = *(const float4*)(jb.wt + (size_t)((it+1)*16 + br + 8)*CD + n0 + bc);
        }
        #pragma unroll
        for (int kk = 0; kk < 16; kk++) {
            const float* ap = &As[s][kk][ty << 3];
            float4 x0 = *(const float4*)ap;
            float4 x1 = *(const float4*)(ap + 4);
            float4 bq = *(const float4*)&Bs[s][kk][tx << 2];
            float ar[8] = {x0.x,x0.y,x0.z,x0.w,x1.x,x1.y,x1.z,x1.w};
            #pragma unroll
            for (int r = 0; r < 8; r++) {
                acc[r][0] += ar[r]*bq.x; acc[r][1] += ar[r]*bq.y;
                acc[r][2] += ar[r]*bq.z; acc[r][3] += ar[r]*bq.w;
            }
        }
        if (more) {
            int so = s ^ 1, k4 = kgA << 2;
            As[so][k4+0][am]=na0.x; As[so][k4+1][am]=na0.y; As[so][k4+2][am]=na0.z; As[so][k4+3][am]=na0.w;
            As[so][k4+8][am]=na1.x; As[so][k4+9][am]=na1.y; As[so][k4+10][am]=na1.z; As[so][k4+11][am]=na1.w;
            *(float4*)&Bs[so][br][bc]   = nb0;
            *(float4*)&Bs[so][br+8][bc] = nb1;
            __syncthreads();
        }
    }

    int c0 = n0 + (tx << 2);
    float4 bias4 = make_float4(0.f,0.f,0.f,0.f);
    if (jb.bias) bias4 = *(const float4*)(jb.bias + c0);
    #pragma unroll
    for (int r = 0; r < 8; r++) {
        int m = m0 + (ty << 3) + r;
        float4 o = make_float4(acc[r][0]+bias4.x, acc[r][1]+bias4.y, acc[r][2]+bias4.z, acc[r][3]+bias4.w);
        if (jb.res) {
            float4 rr = *(const float4*)(jb.res + (size_t)m*CD + c0);
            o.x += rr.x; o.y += rr.y; o.z += rr.z; o.w += rr.w;
        }
        *(float4*)(jb.out + (size_t)m*CD + c0) = o;
    }
}

// flash attention, head dim 16, fused conv_atten epilogue (unchanged, passing)
__global__ void flash_kernel(const float* __restrict__ q, const float* __restrict__ k,
                             const float* __restrict__ v, float* __restrict__ out) {
    int bh = blockIdx.y, b = bh >> 3, h = bh & 7;
    int qbase = blockIdx.x << 6;
    __shared__ float4 ks[128][4], vs[128][4];
    int tid = threadIdx.x, wid = tid >> 5, lane = tid & 31;
    int r = lane >> 2, g = lane & 3;
    int qrow = qbase + (wid << 3) + r;
    const float* qp = q + (((b<<11) + qrow) << 7) + (h << 4);
    float4 q0 = *(const float4*)(qp), q1 = *(const float4*)(qp+4);
    float4 q2 = *(const float4*)(qp+8), q3 = *(const float4*)(qp+12);
    float acc[16];
    #pragma unroll
    for (int d = 0; d < 16; d++) acc[d] = 0.f;
    float mrow = -1e30f, lsum = 0.f;
    const float* kbase = k + (((size_t)b << 11) << 7) + (h << 4);
    const float* vbase = v + (((size_t)b << 11) << 7) + (h << 4);
    for (int kt = 0; kt < 2048; kt += 128) {
        __syncthreads();
        #pragma unroll
        for (int u = 0; u < 2; u++) {
            int idx = tid + (u << 8);
            int row = idx >> 2, c4 = idx & 3;
            ks[row][c4] = *(const float4*)(kbase + (size_t)(kt+row)*CD + (c4<<2));
            vs[row][c4] = *(const float4*)(vbase + (size_t)(kt+row)*CD + (c4<<2));
        }
        __syncthreads();
        float s[32], tmax = -1e30f;
        #pragma unroll
        for (int i = 0; i < 32; i++) {
            int kc = (i << 2) + g;
            float4 ka = ks[kc][0], kb = ks[kc][1], kc2 = ks[kc][2], kd = ks[kc][3];
            float d = q0.x*ka.x + q0.y*ka.y + q0.z*ka.z + q0.w*ka.w
                    + q1.x*kb.x + q1.y*kb.y + q1.z*kb.z + q1.w*kb.w
                    + q2.x*kc2.x + q2.y*kc2.y + q2.z*kc2.z + q2.w*kc2.w
                    + q3.x*kd.x + q3.y*kd.y + q3.z*kd.z + q3.w*kd.w;
            s[i] = d; tmax = fmaxf(tmax, d);
        }
        tmax = fmaxf(tmax, __shfl_xor_sync(~0u, tmax, 1));
        tmax = fmaxf(tmax, __shfl_xor_sync(~0u, tmax, 2));
        float mnew = fmaxf(mrow, tmax);
        float corr = __expf(mrow - mnew);
        mrow = mnew; lsum *= corr;
        #pragma unroll
        for (int d = 0; d < 16; d++) acc[d] *= corr;
        #pragma unroll
        for (int i = 0; i < 32; i++) {
            float pv = __expf(s[i] - mnew);
            lsum += pv;
            int kc = (i << 2) + g;
            float4 va = vs[kc][0], vb = vs[kc][1], vc = vs[kc][2], vd = vs[kc][3];
            acc[0] += pv*va.x; acc[1] += pv*va.y; acc[2] += pv*va.z; acc[3] += pv*va.w;
            acc[4] += pv*vb.x; acc[5] += pv*vb.y; acc[6] += pv*vb.z; acc[7] += pv*vb.w;
            acc[8] += pv*vc.x; acc[9] += pv*vc.y; acc[10] += pv*vc.z; acc[11] += pv*vc.w;
            acc[12] += pv*vd.x; acc[13] += pv*vd.y; acc[14] += pv*vd.z; acc[15] += pv*vd.w;
        }
    }
    #pragma unroll
    for (int d = 0; d < 16; d++) {
        acc[d] += __shfl_xor_sync(~0u, acc[d], 1);
        acc[d] += __shfl_xor_sync(~0u, acc[d], 2);
    }
    lsum += __shfl_xor_sync(~0u, lsum, 1);
    lsum += __shfl_xor_sync(~0u, lsum, 2);
    float inv = 1.0f / lsum;
    float a0, a1, a2, a3;
    if (g == 0)      { a0=acc[0];  a1=acc[1];  a2=acc[2];  a3=acc[3];  }
    else if (g == 1) { a0=acc[4];  a1=acc[5];  a2=acc[6];  a3=acc[7];  }
    else if (g == 2) { a0=acc[8];  a1=acc[9];  a2=acc[10]; a3=acc[11]; }
    else             { a0=acc[12]; a1=acc[13]; a2=acc[14]; a3=acc[15]; }
    size_t base = ((size_t)((b<<11) + qrow) << 7) + (h << 4);
    float av2[4] = {a0, a1, a2, a3}, ov[4];
    #pragma unroll
    for (int u = 0; u < 4; u++) {
        int w2 = (g << 2) + u;
        float ca = 0.f;
        #pragma unroll
        for (int s2 = 0; s2 < 3; s2++) {
            int f = w2 + (s2 << 4);
            int sel = f % 3;
            const float* tp = (sel == 0) ? q : ((sel == 1) ? k : v);
            ca += tp[base + f/3];
        }
        ov[u] = av2[u]*inv + ca*(1.0f/3.0f);
    }
    *(float4*)(out + base + (g << 2)) = make_float4(ov[0], ov[1], ov[2], ov[3]);
}

// fused: x2 = msgfa-mix + h ; then LN(x2) -> y2, row-mean(y2) -> xm
__global__ void combine_ln(const float* __restrict__ a1, const float* __restrict__ a2,
                           const float* __restrict__ a3, const float* __restrict__ hh,
                           const float* __restrict__ gam, const float* __restrict__ bet,
                           float* __restrict__ x2, float* __restrict__ y2,
                           float* __restrict__ xm) {
    int m = blockIdx.x, c = threadIdx.x, lane = c & 31, wid = c >> 5;
    float sacc = 0.f;
    #pragma unroll
    for (int s2 = 0; s2 < 3; s2++) {
        int f = c*3 + s2;
        const float* ap = (f >> 7) == 0 ? a1 : ((f >> 7) == 1 ? a2 : a3);
        sacc += ap[(m << 7) + (f & 127)];
    }
    float v = sacc*(1.0f/3.0f) + hh[m*CD + c];
    x2[m*CD + c] = v;
    float s = v, sq = v*v;
    #pragma unroll
    for (int o = 16; o > 0; o >>= 1) { s += __shfl_xor_sync(~0u, s, o); sq += __shfl_xor_sync(~0u, sq, o); }
    __shared__ float ss[4], sqq[4], ys[4];
    if (lane == 0) { ss[wid] = s; sqq[wid] = sq; }
    __syncthreads();
    float S = ss[0]+ss[1]+ss[2]+ss[3], SQ = sqq[0]+sqq[1]+sqq[2]+sqq[3];
    float mean = S*(1.0f/CD), var = SQ*(1.0f/CD) - mean*mean, rs = rsqrtf(var + 1e-6f);
    float y = (v - mean)*rs*gam[c] + bet[c];
    y2[m*CD + c] = y;
    float t = y;
    #pragma unroll
    for (int o = 16; o > 0; o >>= 1) t += __shfl_xor_sync(~0u, t, o);
    if (lane == 0) ys[wid] = t;
    __syncthreads();
    if (c == 0) xm[m] = (ys[0]+ys[1]+ys[2]+ys[3])*(1.0f/CD);
}

__global__ void final_kernel(const float* __restrict__ x2, const float* __restrict__ y2,
                             const float* __restrict__ xm, const float* __restrict__ st1,
                             const float* __restrict__ st2, const float* __restrict__ st3,
                             float* __restrict__ out) {
    int m = blockIdx.x, b = m >> 11, p = m & 2047;
    int t = p >> 4, ii = (p >> 2) & 3, jj = p & 3;
    __shared__ float sg;
    if (threadIdx.x == 0) {
        float gg = st1[0] * xm[m];
        #pragma unroll
        for (int kd = 0; kd < 2; kd++)
        for (int kh = 0; kh < 2; kh++)
        for (int kw = 0; kw < 2; kw++) {
            int t2 = t + kd - 1, i2 = ii + kh - 1, j2 = jj + kw - 1;
            if ((unsigned)t2 < 128u && (unsigned)i2 < 4u && (unsigned)j2 < 4u)
                gg += st2[kd*4 + kh*2 + kw] * xm[(b<<11) + (t2<<4) + (i2<<2) + j2];
        }
        #pragma unroll
        for (int kd = 0; kd < 3; kd++)
        for (int kh = 0; kh < 3; kh++)
        for (int kw = 0; kw < 3; kw++) {
            int t2 = t + kd - 1, i2 = ii + kh - 1, j2 = jj + kw - 1;
            if ((unsigned)t2 < 128u && (unsigned)i2 < 4u && (unsigned)j2 < 4u)
                gg += st3[kd*9 + kh*3 + kw] * xm[(b<<11) + (t2<<4) + (i2<<2) + j2];
        }
        sg = 1.0f / (1.0f + __expf(-gg));
    }
    __syncthreads();
    int idx = m*CD + threadIdx.x;
    out[idx] = x2[idx] + y2[idx]*sg;
}

extern "C" void kernel_launch(void* const* d_in, const int* in_sizes, int n_in,
                              void* d_out, int out_size) {
    const float* x      = (const float*)d_in[0];
    const float* n1g    = (const float*)d_in[1];
    const float* n1b    = (const float*)d_in[2];
    const float* q_w    = (const float*)d_in[3];
    const float* qbg    = (const float*)d_in[4];
    const float* qbb    = (const float*)d_in[5];
    const float* k_w    = (const float*)d_in[6];
    const float* kbg    = (const float*)d_in[7];
    const float* kbb    = (const float*)d_in[8];
    const float* v_w    = (const float*)d_in[9];
    const float* proj_w = (const float*)d_in[10];
    const float* proj_b = (const float*)d_in[11];
    const float* r1_w   = (const float*)d_in[12];
    const float* r2_w   = (const float*)d_in[13];
    const float* r3_w   = (const float*)d_in[14];
    const float* n2g    = (const float*)d_in[15];
    const float* n2b    = (const float*)d_in[16];
    const float* st1    = (const float*)d_in[17];
    const float* st2    = (const float*)d_in[18];
    const float* st3    = (const float*)d_in[19];
    float* out = (float*)d_out;

    float *y1,*qb,*kb,*vb,*attn,*hb,*a1,*a2,*a3,*x2,*y2,*xm;
    float *wq,*wk,*wv,*wr1,*wr2,*wr3,*wp,*bnst;
    cudaGetSymbolAddress((void**)&y1, g_y1);     cudaGetSymbolAddress((void**)&qb, g_qb);
    cudaGetSymbolAddress((void**)&kb, g_kb);     cudaGetSymbolAddress((void**)&vb, g_vb);
    cudaGetSymbolAddress((void**)&attn, g_attn); cudaGetSymbolAddress((void**)&hb, g_hb);
    cudaGetSymbolAddress((void**)&a1, g_a1);     cudaGetSymbolAddress((void**)&a2, g_a2);
    cudaGetSymbolAddress((void**)&a3, g_a3);     cudaGetSymbolAddress((void**)&x2, g_x2);
    cudaGetSymbolAddress((void**)&y2, g_y2);     cudaGetSymbolAddress((void**)&xm, g_xm);
    cudaGetSymbolAddress((void**)&wq, g_wq);     cudaGetSymbolAddress((void**)&wk, g_wk);
    cudaGetSymbolAddress((void**)&wv, g_wv);     cudaGetSymbolAddress((void**)&wr1, g_wr1);
    cudaGetSymbolAddress((void**)&wr2, g_wr2);   cudaGetSymbolAddress((void**)&wr3, g_wr3);
    cudaGetSymbolAddress((void**)&wp, g_wp);     cudaGetSymbolAddress((void**)&bnst, g_bnst);

    auto cdiv = [](int a, int b){ return (a + b - 1) / b; };
    const int n27 = 27*CD*CD, n8 = 8*CD*CD, n1 = CD*CD;
    WJob jn = { nullptr, nullptr, 0, 0 };
    WJob wjq  = { q_w,  wq,  27, n27 };
    WJob wjr1 = { r1_w, wr1, 27, n27 };
    WJob wjk  = { k_w,  wk,  8,  n8  };
    WJob wjr2 = { r2_w, wr2, 8,  n8  };
    WJob wjv  = { v_w,  wv,  1,  n1  };
    WJob wjr3 = { r3_w, wr3, 1,  n1  };
    WJob wjp  = { proj_w, wp, 1, n1  };
    // launches 0-3: weight prep (+ BN accumulator zeroing)
    wtrans_multi<<<cdiv(n27,256),256>>>(wjq, jn, jn, 1, bnst, 2*2*CD);
    wtrans_multi<<<cdiv(n27,256),256>>>(wjr1, jn, jn, 1, nullptr, 0);
    wtrans_multi<<<cdiv(2*n8,256),256>>>(wjk, wjr2, jn, 2, nullptr, 0);
    wtrans_multi<<<cdiv(3*n1,256),256>>>(wjv, wjr3, wjp, 3, nullptr, 0);
    // launch 4
    ln_kernel<<<MTOT, 128>>>(x, y1, n1g, n1b, nullptr, 1e-6f);
    // launch 5: heavy conv3 pair (ncu target)
    Job jq  = { y1, wq,  nullptr, nullptr, qb };
    Job jr1 = { x,  wr1, x,       nullptr, a1 };
    conv_gemm_kernel<3><<<dim3(2,64,2), 128>>>(jq, jr1);
    // launch 6
    Job jk  = { y1, wk,  nullptr, nullptr, kb };
    Job jr2 = { a1, wr2, a1,      nullptr, a2 };
    conv_gemm_kernel<2><<<dim3(2,64,2), 128>>>(jk, jr2);
    // launches 7-8: both BNs
    bn_stats<<<dim3(32,2), 256>>>(qb, kb);
    bn_apply<<<dim3(MTOT*CD/256,2), 256>>>(qb, kb, qbg, qbb, kbg, kbb);
    // launch 9
    Job jv  = { y1, wv,  nullptr, nullptr, vb };
    Job jr3 = { a2, wr3, a2,      nullptr, a3 };
    conv_gemm_kernel<1><<<dim3(2,64,2), 128>>>(jv, jr3);
    // launch 10
    flash_kernel<<<dim3(32,16), 256>>>(qb, kb, vb, attn);
    // launch 11
    Job jp = { attn, wp, nullptr, proj_b, hb };
    conv_gemm_kernel<1><<<dim3(2,64,1), 128>>>(jp, jp);
    // launch 12
    combine_ln<<<MTOT, 128>>>(a1, a2, a3, hb, n2g, n2b, x2, y2, xm);
    // launch 13
    final_kernel<<<MTOT, 128>>>(x2, y2, xm, st1, st2, st3, out);
}

// round 4
// speedup vs baseline: 1.1045x; 1.0219x over previous
#include <cuda_runtime.h>
#include <math.h>

#define CD 128
#define MTOT 4096

typedef unsigned long long u64;

__device__ __forceinline__ u64 pack2(float lo, float hi) {
    u64 r; asm("mov.b64 %0,{%1,%2};" : "=l"(r) : "f"(lo), "f"(hi)); return r;
}
__device__ __forceinline__ void fma2(u64& d, u64 a, u64 b) {
    asm("fma.rn.f32x2 %0,%1,%2,%0;" : "+l"(d) : "l"(a), "l"(b));
}
__device__ __forceinline__ void mul2(u64& d, u64 a) {
    asm("mul.rn.f32x2 %0,%0,%1;" : "+l"(d) : "l"(a));
}
__device__ __forceinline__ float2 unpack2(u64 v) {
    float2 f; asm("mov.b64 {%0,%1},%2;" : "=f"(f.x), "=f"(f.y) : "l"(v)); return f;
}

union F4U { float4 f; u64 u[2]; };

struct Job  { const float* in; const float* wt; const float* res; const float* bias; float* out; };
struct WJobs { const float* src[5]; float* dst[5]; int KK[5]; int n[5]; int nj; };

__device__ float g_y1[MTOT*CD], g_qb[MTOT*CD], g_kb[MTOT*CD], g_vb[MTOT*CD];
__device__ float g_attn[MTOT*CD], g_hb[MTOT*CD], g_a1[MTOT*CD], g_a2[MTOT*CD], g_a3[MTOT*CD];
__device__ float g_x2[MTOT*CD], g_y2[MTOT*CD], g_xm[MTOT];
__device__ float g_wq[27*CD*CD], g_wk[8*CD*CD], g_wv[CD*CD];
__device__ float g_wr1[27*CD*CD], g_wr2[8*CD*CD], g_wr3[CD*CD], g_wp[CD*CD];
__device__ float g_bnst[2][2][CD];

__global__ void wtrans_multi(WJobs J, float* zbuf, int zn) {
    int idx = blockIdx.x * 256 + threadIdx.x;
    if (zbuf && idx < zn) zbuf[idx] = 0.f;
    int base = 0;
    #pragma unroll
    for (int j = 0; j < 5; j++) {
        if (j >= J.nj) return;
        if (idx < base + J.n[j]) {
            int t = idx - base;
            int tap = t / (CD*CD); int rem = t - tap*(CD*CD);
            int ci = rem >> 7, co = rem & 127;
            J.dst[j][t] = J.src[j][(co*CD + ci)*J.KK[j] + tap];
            return;
        }
        base += J.n[j];
    }
}

__global__ void ln_kernel(const float* __restrict__ in, float* __restrict__ out,
                          const float* __restrict__ gam, const float* __restrict__ bet,
                          float* __restrict__ xm, float eps) {
    int m = blockIdx.x, c = threadIdx.x, lane = c & 31, wid = c >> 5;
    float v = in[m*CD + c], s = v, sq = v*v;
    #pragma unroll
    for (int o = 16; o > 0; o >>= 1) { s += __shfl_xor_sync(~0u, s, o); sq += __shfl_xor_sync(~0u, sq, o); }
    __shared__ float ss[4], sqq[4], ys[4];
    if (lane == 0) { ss[wid] = s; sqq[wid] = sq; }
    __syncthreads();
    float S = ss[0]+ss[1]+ss[2]+ss[3], SQ = sqq[0]+sqq[1]+sqq[2]+sqq[3];
    float mean = S*(1.0f/CD), var = SQ*(1.0f/CD) - mean*mean, rs = rsqrtf(var + eps);
    float y = (v - mean)*rs*gam[c] + bet[c];
    out[m*CD + c] = y;
    if (xm) {
        float t = y;
        #pragma unroll
        for (int o = 16; o > 0; o >>= 1) t += __shfl_xor_sync(~0u, t, o);
        if (lane == 0) ys[wid] = t;
        __syncthreads();
        if (c == 0) xm[m] = (ys[0]+ys[1]+ys[2]+ys[3])*(1.0f/CD);
    }
}

__global__ void bn_stats(const float* __restrict__ q, const float* __restrict__ k) {
    int buf = blockIdx.y;
    const float* src = buf ? k : q;
    int tid = threadIdx.x;
    int base = blockIdx.x * 128;
    float s = 0.f, sq = 0.f;
    for (int i = tid; i < 128*CD; i += 256) {
        float v = src[(base + (i >> 7))*CD + (i & 127)];
        s += v; sq += v*v;
    }
    __shared__ float sh[256];
    sh[tid] = s; __syncthreads();
    if (tid < 128) atomicAdd(&g_bnst[buf][0][tid], sh[tid] + sh[tid+128]);
    __syncthreads();
    sh[tid] = sq; __syncthreads();
    if (tid < 128) atomicAdd(&g_bnst[buf][1][tid], sh[tid] + sh[tid+128]);
}

__global__ void bn_apply(float* __restrict__ q, float* __restrict__ k,
                         const float* __restrict__ qg, const float* __restrict__ qb2,
                         const float* __restrict__ kg, const float* __restrict__ kb2) {
    int buf = blockIdx.y;
    float* dst = buf ? k : q;
    const float* gam = buf ? kg : qg;
    const float* bet = buf ? kb2 : qb2;
    int idx = blockIdx.x * 256 + threadIdx.x;
    int c = idx & 127;
    float S = g_bnst[buf][0][c], SQ = g_bnst[buf][1][c];
    float mean = S*(1.0f/MTOT), var = SQ*(1.0f/MTOT) - mean*mean;
    float sc = gam[c]*rsqrtf(var + 1e-5f), sh = bet[c] - mean*sc;
    dst[idx] = dst[idx]*sc + sh;
}

// implicit-GEMM conv, BM=64 BN=64 BK=16, 128 thr, TM=8 TN=4, f32x2 math
template<int KS>
__global__ void conv_gemm_kernel(Job j0, Job j1) {
    constexpr int K = KS*KS*KS*CD;
    constexpr int NIT = K / 16;
    Job jb = (blockIdx.z == 0) ? j0 : j1;
    const int m0 = blockIdx.y << 6, n0 = blockIdx.x << 6;
    __shared__ float As[2][16][64], Bs[2][16][64];
    const int tid = threadIdx.x;
    const int am = tid & 63, kgA = tid >> 6;
    const int gm = m0 + am, bb = gm >> 11, p = gm & 2047;
    const int tt = p >> 4, ii = (p >> 2) & 3, jj = p & 3;
    const int br = tid >> 4, bc = (tid & 15) << 2;
    const int ty = tid >> 4, tx = tid & 15;
    u64 acc[4][4];
    #pragma unroll
    for (int r = 0; r < 4; r++)
        #pragma unroll
        for (int c = 0; c < 4; c++) acc[r][c] = 0ull;

    auto ldA = [&](int kgabs) -> float4 {
        int tap = kgabs >> 5;
        int ci = (kgabs << 2) & 127;
        int dt, di, dj;
        if (KS == 3) { dt = tap/9 - 1; int r9 = tap%9; di = r9/3 - 1; dj = r9%3 - 1; }
        else if (KS == 2) { dt = (tap>>2) - 1; di = ((tap>>1)&1) - 1; dj = (tap&1) - 1; }
        else { dt = di = dj = 0; }
        int t2 = tt + dt, i2 = ii + di, j2 = jj + dj;
        if ((unsigned)t2 < 128u && (unsigned)i2 < 4u && (unsigned)j2 < 4u)
            return *(const float4*)(jb.in + (((bb<<11) + (t2<<4) + (i2<<2) + j2) << 7) + ci);
        return make_float4(0.f,0.f,0.f,0.f);
    };

    {
        float4 a0 = ldA(kgA), a1 = ldA(kgA + 2);
        float4 b0 = *(const float4*)(jb.wt + (size_t)br*CD + n0 + bc);
        float4 b1 = *(const float4*)(jb.wt + (size_t)(br+8)*CD + n0 + bc);
        int k4 = kgA << 2;
        As[0][k4+0][am]=a0.x; As[0][k4+1][am]=a0.y; As[0][k4+2][am]=a0.z; As[0][k4+3][am]=a0.w;
        As[0][k4+8][am]=a1.x; As[0][k4+9][am]=a1.y; As[0][k4+10][am]=a1.z; As[0][k4+11][am]=a1.w;
        *(float4*)&Bs[0][br][bc]   = b0;
        *(float4*)&Bs[0][br+8][bc] = b1;
    }
    __syncthreads();

    for (int it = 0; it < NIT; it++) {
        int s = it & 1;
        float4 na0, na1, nb0, nb1;
        bool more = (it + 1 < NIT);
        if (more) {
            int kg = (it+1)*4;
            na0 = ldA(kg + kgA); na1 = ldA(kg + kgA + 2);
            nb0 = *(const float4*)(jb.wt + (size_t)((it+1)*16 + br)*CD + n0 + bc);
            nb1 = *(const float4*)(jb.wt + (size_t)((it+1)*16 + br + 8)*CD + n0 + bc);
        }
        #pragma unroll
        for (int kk = 0; kk < 16; kk++) {
            F4U u0, u1;
            u0.f = *(const float4*)&As[s][kk][ty << 3];
            u1.f = *(const float4*)(&As[s][kk][ty << 3] + 4);
            u64 ap[4] = {u0.u[0], u0.u[1], u1.u[0], u1.u[1]};
            float4 bq = *(const float4*)&Bs[s][kk][tx << 2];
            u64 b0 = pack2(bq.x, bq.x), b1 = pack2(bq.y, bq.y);
            u64 b2 = pack2(bq.z, bq.z), b3 = pack2(bq.w, bq.w);
            #pragma unroll
            for (int r = 0; r < 4; r++) {
                fma2(acc[r][0], ap[r], b0);
                fma2(acc[r][1], ap[r], b1);
                fma2(acc[r][2], ap[r], b2);
                fma2(acc[r][3], ap[r], b3);
            }
        }
        if (more) {
            int so = s ^ 1, k4 = kgA << 2;
            As[so][k4+0][am]=na0.x; As[so][k4+1][am]=na0.y; As[so][k4+2][am]=na0.z; As[so][k4+3][am]=na0.w;
            As[so][k4+8][am]=na1.x; As[so][k4+9][am]=na1.y; As[so][k4+10][am]=na1.z; As[so][k4+11][am]=na1.w;
            *(float4*)&Bs[so][br][bc]   = nb0;
            *(float4*)&Bs[so][br+8][bc] = nb1;
            __syncthreads();
        }
    }

    int c0 = n0 + (tx << 2);
    float4 bias4 = make_float4(0.f,0.f,0.f,0.f);
    if (jb.bias) bias4 = *(const float4*)(jb.bias + c0);
    #pragma unroll
    for (int rp = 0; rp < 4; rp++) {
        float2 p0 = unpack2(acc[rp][0]), p1 = unpack2(acc[rp][1]);
        float2 p2 = unpack2(acc[rp][2]), p3 = unpack2(acc[rp][3]);
        int mA = m0 + (ty << 3) + (rp << 1), mB = mA + 1;
        float4 oA = make_float4(p0.x+bias4.x, p1.x+bias4.y, p2.x+bias4.z, p3.x+bias4.w);
        float4 oB = make_float4(p0.y+bias4.x, p1.y+bias4.y, p2.y+bias4.z, p3.y+bias4.w);
        if (jb.res) {
            float4 rA = *(const float4*)(jb.res + (size_t)mA*CD + c0);
            float4 rB = *(const float4*)(jb.res + (size_t)mB*CD + c0);
            oA.x += rA.x; oA.y += rA.y; oA.z += rA.z; oA.w += rA.w;
            oB.x += rB.x; oB.y += rB.y; oB.z += rB.z; oB.w += rB.w;
        }
        *(float4*)(jb.out + (size_t)mA*CD + c0) = oA;
        *(float4*)(jb.out + (size_t)mB*CD + c0) = oB;
    }
}

// flash attention, head dim 16, f32x2 math, fused conv_atten epilogue
__global__ void flash_kernel(const float* __restrict__ q, const float* __restrict__ k,
                             const float* __restrict__ v, float* __restrict__ out) {
    int bh = blockIdx.y, b = bh >> 3, h = bh & 7;
    int qbase = blockIdx.x << 6;
    __shared__ float4 ks[128][4], vs[128][4];
    int tid = threadIdx.x, wid = tid >> 5, lane = tid & 31;
    int r = lane >> 2, g = lane & 3;
    int qrow = qbase + (wid << 3) + r;
    const float* qp = q + (((b<<11) + qrow) << 7) + (h << 4);
    u64 qpair[8];
    {
        F4U t0, t1, t2, t3;
        t0.f = *(const float4*)(qp);    t1.f = *(const float4*)(qp+4);
        t2.f = *(const float4*)(qp+8);  t3.f = *(const float4*)(qp+12);
        qpair[0]=t0.u[0]; qpair[1]=t0.u[1]; qpair[2]=t1.u[0]; qpair[3]=t1.u[1];
        qpair[4]=t2.u[0]; qpair[5]=t2.u[1]; qpair[6]=t3.u[0]; qpair[7]=t3.u[1];
    }
    u64 accp[8];
    #pragma unroll
    for (int d = 0; d < 8; d++) accp[d] = 0ull;
    float mrow = -1e30f, lsum = 0.f;
    const float* kbase = k + (((size_t)b << 11) << 7) + (h << 4);
    const float* vbase = v + (((size_t)b << 11) << 7) + (h << 4);
    for (int kt = 0; kt < 2048; kt += 128) {
        __syncthreads();
        #pragma unroll
        for (int u = 0; u < 2; u++) {
            int idx = tid + (u << 8);
            int row = idx >> 2, c4 = idx & 3;
            ks[row][c4] = *(const float4*)(kbase + (size_t)(kt+row)*CD + (c4<<2));
            vs[row][c4] = *(const float4*)(vbase + (size_t)(kt+row)*CD + (c4<<2));
        }
        __syncthreads();
        float s[32], tmax = -1e30f;
        #pragma unroll
        for (int i = 0; i < 32; i++) {
            int kc = (i << 2) + g;
            F4U k0, k1, k2, k3;
            k0.f = ks[kc][0]; k1.f = ks[kc][1]; k2.f = ks[kc][2]; k3.f = ks[kc][3];
            u64 d2 = 0ull;
            fma2(d2, qpair[0], k0.u[0]); fma2(d2, qpair[1], k0.u[1]);
            fma2(d2, qpair[2], k1.u[0]); fma2(d2, qpair[3], k1.u[1]);
            fma2(d2, qpair[4], k2.u[0]); fma2(d2, qpair[5], k2.u[1]);
            fma2(d2, qpair[6], k3.u[0]); fma2(d2, qpair[7], k3.u[1]);
            float2 dd = unpack2(d2);
            s[i] = dd.x + dd.y;
            tmax = fmaxf(tmax, s[i]);
        }
        tmax = fmaxf(tmax, __shfl_xor_sync(~0u, tmax, 1));
        tmax = fmaxf(tmax, __shfl_xor_sync(~0u, tmax, 2));
        float mnew = fmaxf(mrow, tmax);
        float corr = __expf(mrow - mnew);
        mrow = mnew; lsum *= corr;
        u64 c2 = pack2(corr, corr);
        #pragma unroll
        for (int d = 0; d < 8; d++) mul2(accp[d], c2);
        #pragma unroll
        for (int i = 0; i < 32; i++) {
            float pv = __expf(s[i] - mnew);
            lsum += pv;
            int kc = (i << 2) + g;
            u64 pv2 = pack2(pv, pv);
            F4U v0, v1, v2, v3;
            v0.f = vs[kc][0]; v1.f = vs[kc][1]; v2.f = vs[kc][2]; v3.f = vs[kc][3];
            fma2(accp[0], pv2, v0.u[0]); fma2(accp[1], pv2, v0.u[1]);
            fma2(accp[2], pv2, v1.u[0]); fma2(accp[3], pv2, v1.u[1]);
            fma2(accp[4], pv2, v2.u[0]); fma2(accp[5], pv2, v2.u[1]);
            fma2(accp[6], pv2, v3.u[0]); fma2(accp[7], pv2, v3.u[1]);
        }
    }
    float acc[16];
    #pragma unroll
    for (int d = 0; d < 8; d++) {
        float2 f = unpack2(accp[d]);
        acc[d*2] = f.x; acc[d*2+1] = f.y;
    }
    #pragma unroll
    for (int d = 0; d < 16; d++) {
        acc[d] += __shfl_xor_sync(~0u, acc[d], 1);
        acc[d] += __shfl_xor_sync(~0u, acc[d], 2);
    }
    lsum += __shfl_xor_sync(~0u, lsum, 1);
    lsum += __shfl_xor_sync(~0u, lsum, 2);
    float inv = 1.0f / lsum;
    float a0, a1, a2, a3;
    if (g == 0)      { a0=acc[0];  a1=acc[1];  a2=acc[2];  a3=acc[3];  }
    else if (g == 1) { a0=acc[4];  a1=acc[5];  a2=acc[6];  a3=acc[7];  }
    else if (g == 2) { a0=acc[8];  a1=acc[9];  a2=acc[10]; a3=acc[11]; }
    else             { a0=acc[12]; a1=acc[13]; a2=acc[14]; a3=acc[15]; }
    size_t base = ((size_t)((b<<11) + qrow) << 7) + (h << 4);
    float av2[4] = {a0, a1, a2, a3}, ov[4];
    #pragma unroll
    for (int u = 0; u < 4; u++) {
        int w2 = (g << 2) + u;
        float ca = 0.f;
        #pragma unroll
        for (int s2 = 0; s2 < 3; s2++) {
            int f = w2 + (s2 << 4);
            int sel = f % 3;
            const float* tp = (sel == 0) ? q : ((sel == 1) ? k : v);
            ca += tp[base + f/3];
        }
        ov[u] = av2[u]*inv + ca*(1.0f/3.0f);
    }
    *(float4*)(out + base + (g << 2)) = make_float4(ov[0], ov[1], ov[2], ov[3]);
}

__global__ void combine_ln(const float* __restrict__ a1, const float* __restrict__ a2,
                           const float* __restrict__ a3, const float* __restrict__ hh,
                           const float* __restrict__ gam, const float* __restrict__ bet,
                           float* __restrict__ x2, float* __restrict__ y2,
                           float* __restrict__ xm) {
    int m = blockIdx.x, c = threadIdx.x, lane = c & 31, wid = c >> 5;
    float sacc = 0.f;
    #pragma unroll
    for (int s2 = 0; s2 < 3; s2++) {
        int f = c*3 + s2;
        const float* ap = (f >> 7) == 0 ? a1 : ((f >> 7) == 1 ? a2 : a3);
        sacc += ap[(m << 7) + (f & 127)];
    }
    float v = sacc*(1.0f/3.0f) + hh[m*CD + c];
    x2[m*CD + c] = v;
    float s = v, sq = v*v;
    #pragma unroll
    for (int o = 16; o > 0; o >>= 1) { s += __shfl_xor_sync(~0u, s, o); sq += __shfl_xor_sync(~0u, sq, o); }
    __shared__ float ss[4], sqq[4], ys[4];
    if (lane == 0) { ss[wid] = s; sqq[wid] = sq; }
    __syncthreads();
    float S = ss[0]+ss[1]+ss[2]+ss[3], SQ = sqq[0]+sqq[1]+sqq[2]+sqq[3];
    float mean = S*(1.0f/CD), var = SQ*(1.0f/CD) - mean*mean, rs = rsqrtf(var + 1e-6f);
    float y = (v - mean)*rs*gam[c] + bet[c];
    y2[m*CD + c] = y;
    float t = y;
    #pragma unroll
    for (int o = 16; o > 0; o >>= 1) t += __shfl_xor_sync(~0u, t, o);
    if (lane == 0) ys[wid] = t;
    __syncthreads();
    if (c == 0) xm[m] = (ys[0]+ys[1]+ys[2]+ys[3])*(1.0f/CD);
}

__global__ void final_kernel(const float* __restrict__ x2, const float* __restrict__ y2,
                             const float* __restrict__ xm, const float* __restrict__ st1,
                             const float* __restrict__ st2, const float* __restrict__ st3,
                             float* __restrict__ out) {
    int m = blockIdx.x, b = m >> 11, p = m & 2047;
    int t = p >> 4, ii = (p >> 2) & 3, jj = p & 3;
    __shared__ float sg;
    if (threadIdx.x == 0) {
        float gg = st1[0] * xm[m];
        #pragma unroll
        for (int kd = 0; kd < 2; kd++)
        for (int kh = 0; kh < 2; kh++)
        for (int kw = 0; kw < 2; kw++) {
            int t2 = t + kd - 1, i2 = ii + kh - 1, j2 = jj + kw - 1;
            if ((unsigned)t2 < 128u && (unsigned)i2 < 4u && (unsigned)j2 < 4u)
                gg += st2[kd*4 + kh*2 + kw] * xm[(b<<11) + (t2<<4) + (i2<<2) + j2];
        }
        #pragma unroll
        for (int kd = 0; kd < 3; kd++)
        for (int kh = 0; kh < 3; kh++)
        for (int kw = 0; kw < 3; kw++) {
            int t2 = t + kd - 1, i2 = ii + kh - 1, j2 = jj + kw - 1;
            if ((unsigned)t2 < 128u && (unsigned)i2 < 4u && (unsigned)j2 < 4u)
                gg += st3[kd*9 + kh*3 + kw] * xm[(b<<11) + (t2<<4) + (i2<<2) + j2];
        }
        sg = 1.0f / (1.0f + __expf(-gg));
    }
    __syncthreads();
    int idx = m*CD + threadIdx.x;
    out[idx] = x2[idx] + y2[idx]*sg;
}

extern "C" void kernel_launch(void* const* d_in, const int* in_sizes, int n_in,
                              void* d_out, int out_size) {
    const float* x      = (const float*)d_in[0];
    const float* n1g    = (const float*)d_in[1];
    const float* n1b    = (const float*)d_in[2];
    const float* q_w    = (const float*)d_in[3];
    const float* qbg    = (const float*)d_in[4];
    const float* qbb    = (const float*)d_in[5];
    const float* k_w    = (const float*)d_in[6];
    const float* kbg    = (const float*)d_in[7];
    const float* kbb    = (const float*)d_in[8];
    const float* v_w    = (const float*)d_in[9];
    const float* proj_w = (const float*)d_in[10];
    const float* proj_b = (const float*)d_in[11];
    const float* r1_w   = (const float*)d_in[12];
    const float* r2_w   = (const float*)d_in[13];
    const float* r3_w   = (const float*)d_in[14];
    const float* n2g    = (const float*)d_in[15];
    const float* n2b    = (const float*)d_in[16];
    const float* st1    = (const float*)d_in[17];
    const float* st2    = (const float*)d_in[18];
    const float* st3    = (const float*)d_in[19];
    float* out = (float*)d_out;

    float *y1,*qb,*kb,*vb,*attn,*hb,*a1,*a2,*a3,*x2,*y2,*xm;
    float *wq,*wk,*wv,*wr1,*wr2,*wr3,*wp,*bnst;
    cudaGetSymbolAddress((void**)&y1, g_y1);     cudaGetSymbolAddress((void**)&qb, g_qb);
    cudaGetSymbolAddress((void**)&kb, g_kb);     cudaGetSymbolAddress((void**)&vb, g_vb);
    cudaGetSymbolAddress((void**)&attn, g_attn); cudaGetSymbolAddress((void**)&hb, g_hb);
    cudaGetSymbolAddress((void**)&a1, g_a1);     cudaGetSymbolAddress((void**)&a2, g_a2);
    cudaGetSymbolAddress((void**)&a3, g_a3);     cudaGetSymbolAddress((void**)&x2, g_x2);
    cudaGetSymbolAddress((void**)&y2, g_y2);     cudaGetSymbolAddress((void**)&xm, g_xm);
    cudaGetSymbolAddress((void**)&wq, g_wq);     cudaGetSymbolAddress((void**)&wk, g_wk);
    cudaGetSymbolAddress((void**)&wv, g_wv);     cudaGetSymbolAddress((void**)&wr1, g_wr1);
    cudaGetSymbolAddress((void**)&wr2, g_wr2);   cudaGetSymbolAddress((void**)&wr3, g_wr3);
    cudaGetSymbolAddress((void**)&wp, g_wp);     cudaGetSymbolAddress((void**)&bnst, g_bnst);

    auto cdiv = [](int a, int b){ return (a + b - 1) / b; };
    const int n27 = 27*CD*CD, n8 = 8*CD*CD, n1 = CD*CD;

    WJobs wa = {};
    wa.nj = 2;
    wa.src[0]=q_w;  wa.dst[0]=wq;  wa.KK[0]=27; wa.n[0]=n27;
    wa.src[1]=r1_w; wa.dst[1]=wr1; wa.KK[1]=27; wa.n[1]=n27;
    WJobs wb = {};
    wb.nj = 5;
    wb.src[0]=k_w;   wb.dst[0]=wk;  wb.KK[0]=8; wb.n[0]=n8;
    wb.src[1]=r2_w;  wb.dst[1]=wr2; wb.KK[1]=8; wb.n[1]=n8;
    wb.src[2]=v_w;   wb.dst[2]=wv;  wb.KK[2]=1; wb.n[2]=n1;
    wb.src[3]=r3_w;  wb.dst[3]=wr3; wb.KK[3]=1; wb.n[3]=n1;
    wb.src[4]=proj_w;wb.dst[4]=wp;  wb.KK[4]=1; wb.n[4]=n1;

    // 0-1: weight prep (+ BN accumulator zeroing)
    wtrans_multi<<<cdiv(2*n27,256),256>>>(wa, bnst, 2*2*CD);
    wtrans_multi<<<cdiv(2*n8+3*n1,256),256>>>(wb, nullptr, 0);
    // 2
    ln_kernel<<<MTOT, 128>>>(x, y1, n1g, n1b, nullptr, 1e-6f);
    // 3: conv3 pair (ncu target)
    Job jq  = { y1, wq,  nullptr, nullptr, qb };
    Job jr1 = { x,  wr1, x,       nullptr, a1 };
    conv_gemm_kernel<3><<<dim3(2,64,2), 128>>>(jq, jr1);
    // 4
    Job jk  = { y1, wk,  nullptr, nullptr, kb };
    Job jr2 = { a1, wr2, a1,      nullptr, a2 };
    conv_gemm_kernel<2><<<dim3(2,64,2), 128>>>(jk, jr2);
    // 5-6
    bn_stats<<<dim3(32,2), 256>>>(qb, kb);
    bn_apply<<<dim3(MTOT*CD/256,2), 256>>>(qb, kb, qbg, qbb, kbg, kbb);
    // 7
    Job jv  = { y1, wv,  nullptr, nullptr, vb };
    Job jr3 = { a2, wr3, a2,      nullptr, a3 };
    conv_gemm_kernel<1><<<dim3(2,64,2), 128>>>(jv, jr3);
    // 8
    flash_kernel<<<dim3(32,16), 256>>>(qb, kb, vb, attn);
    // 9
    Job jp = { attn, wp, nullptr, proj_b, hb };
    conv_gemm_kernel<1><<<dim3(2,64,1), 128>>>(jp, jp);
    // 10
    combine_ln<<<MTOT, 128>>>(a1, a2, a3, hb, n2g, n2b, x2, y2, xm);
    // 11
    final_kernel<<<MTOT, 128>>>(x2, y2, xm, st1, st2, st3, out);
}

// round 5
// speedup vs baseline: 1.8266x; 1.6538x over previous
#include <cuda_runtime.h>
#include <math.h>

#define CD 128
#define MTOT 4096

typedef unsigned long long u64;

__device__ __forceinline__ u64 pack2(float lo, float hi) {
    u64 r; asm("mov.b64 %0,{%1,%2};" : "=l"(r) : "f"(lo), "f"(hi)); return r;
}
__device__ __forceinline__ void fma2(u64& d, u64 a, u64 b) {
    asm("fma.rn.f32x2 %0,%1,%2,%0;" : "+l"(d) : "l"(a), "l"(b));
}
__device__ __forceinline__ void mul2(u64& d, u64 a) {
    asm("mul.rn.f32x2 %0,%0,%1;" : "+l"(d) : "l"(a));
}
__device__ __forceinline__ float2 unpack2(u64 v) {
    float2 f; asm("mov.b64 {%0,%1},%2;" : "=f"(f.x), "=f"(f.y) : "l"(v)); return f;
}

union F4U { float4 f; u64 u[2]; };

struct Job  { const float* in; const float* wt; const float* res; const float* bias; float* out; };
struct WJobs { const float* src[5]; float* dst[5]; int KK[5]; int n[5]; int nj; };

__device__ float g_y1[MTOT*CD], g_qb[MTOT*CD], g_kb[MTOT*CD], g_vb[MTOT*CD];
__device__ float g_attn[MTOT*CD], g_hb[MTOT*CD], g_a1[MTOT*CD], g_a2[MTOT*CD], g_a3[MTOT*CD];
__device__ float g_x2[MTOT*CD], g_y2[MTOT*CD], g_xm[MTOT];
__device__ float g_wq[27*CD*CD], g_wk[8*CD*CD], g_wv[CD*CD];
__device__ float g_wr1[27*CD*CD], g_wr2[8*CD*CD], g_wr3[CD*CD], g_wp[CD*CD];
__device__ float g_bnst[2][2][CD];
__device__ float g_part[8*2*MTOT*CD];   // split-K partials: [split][job][m][c]

__global__ void wtrans_multi(WJobs J, float* zbuf, int zn) {
    int idx = blockIdx.x * 256 + threadIdx.x;
    if (zbuf && idx < zn) zbuf[idx] = 0.f;
    int base = 0;
    #pragma unroll
    for (int j = 0; j < 5; j++) {
        if (j >= J.nj) return;
        if (idx < base + J.n[j]) {
            int t = idx - base;
            int tap = t / (CD*CD); int rem = t - tap*(CD*CD);
            int ci = rem >> 7, co = rem & 127;
            J.dst[j][t] = J.src[j][(co*CD + ci)*J.KK[j] + tap];
            return;
        }
        base += J.n[j];
    }
}

__global__ void ln_kernel(const float* __restrict__ in, float* __restrict__ out,
                          const float* __restrict__ gam, const float* __restrict__ bet,
                          float* __restrict__ xm, float eps) {
    int m = blockIdx.x, c = threadIdx.x, lane = c & 31, wid = c >> 5;
    float v = in[m*CD + c], s = v, sq = v*v;
    #pragma unroll
    for (int o = 16; o > 0; o >>= 1) { s += __shfl_xor_sync(~0u, s, o); sq += __shfl_xor_sync(~0u, sq, o); }
    __shared__ float ss[4], sqq[4], ys[4];
    if (lane == 0) { ss[wid] = s; sqq[wid] = sq; }
    __syncthreads();
    float S = ss[0]+ss[1]+ss[2]+ss[3], SQ = sqq[0]+sqq[1]+sqq[2]+sqq[3];
    float mean = S*(1.0f/CD), var = SQ*(1.0f/CD) - mean*mean, rs = rsqrtf(var + eps);
    float y = (v - mean)*rs*gam[c] + bet[c];
    out[m*CD + c] = y;
    if (xm) {
        float t = y;
        #pragma unroll
        for (int o = 16; o > 0; o >>= 1) t += __shfl_xor_sync(~0u, t, o);
        if (lane == 0) ys[wid] = t;
        __syncthreads();
        if (c == 0) xm[m] = (ys[0]+ys[1]+ys[2]+ys[3])*(1.0f/CD);
    }
}

__global__ void bn_stats(const float* __restrict__ q, const float* __restrict__ k) {
    int buf = blockIdx.y;
    const float* src = buf ? k : q;
    int tid = threadIdx.x;
    int base = blockIdx.x * 128;
    float s = 0.f, sq = 0.f;
    for (int i = tid; i < 128*CD; i += 256) {
        float v = src[(base + (i >> 7))*CD + (i & 127)];
        s += v; sq += v*v;
    }
    __shared__ float sh[256];
    sh[tid] = s; __syncthreads();
    if (tid < 128) atomicAdd(&g_bnst[buf][0][tid], sh[tid] + sh[tid+128]);
    __syncthreads();
    sh[tid] = sq; __syncthreads();
    if (tid < 128) atomicAdd(&g_bnst[buf][1][tid], sh[tid] + sh[tid+128]);
}

__global__ void bn_apply(float* __restrict__ q, float* __restrict__ k,
                         const float* __restrict__ qg, const float* __restrict__ qb2,
                         const float* __restrict__ kg, const float* __restrict__ kb2) {
    int buf = blockIdx.y;
    float* dst = buf ? k : q;
    const float* gam = buf ? kg : qg;
    const float* bet = buf ? kb2 : qb2;
    int idx = blockIdx.x * 256 + threadIdx.x;
    int c = idx & 127;
    float S = g_bnst[buf][0][c], SQ = g_bnst[buf][1][c];
    float mean = S*(1.0f/MTOT), var = SQ*(1.0f/MTOT) - mean*mean;
    float sc = gam[c]*rsqrtf(var + 1e-5f), sh = bet[c] - mean*sc;
    dst[idx] = dst[idx]*sc + sh;
}

// ---------- big conv: BM=128 BN=128 BK=16, 256 thr, TM=8 TN=8(scattered), split-K ----------
template<int KS, int SPLIT>
__global__ void conv_gemm_big(Job j0, Job j1) {
    constexpr int K = KS*KS*KS*CD;
    constexpr int KSP = K / SPLIT;
    constexpr int NIT = KSP / 16;
    const int job = blockIdx.z, split = blockIdx.y;
    Job jb = job ? j1 : j0;
    const int m0 = blockIdx.x << 7;
    const int kbase = split * KSP;
    __shared__ float As[2][16][128];
    __shared__ float Bs[2][16][256];   // duplicated cols: col c at [2c],[2c+1]
    const int tid = threadIdx.x;
    const int am = tid & 127, kg = tid >> 7;           // A loader: k-groups kg, kg+2
    const int gm = m0 + am, bb = gm >> 11, p = gm & 2047;
    const int tt = p >> 4, ii = (p >> 2) & 3, jj = p & 3;
    const int br = tid >> 5, bc = (tid & 31) << 2;     // B loader: rows br, br+8
    const int ty = tid >> 4, tx = tid & 15;            // compute: rows ty*8..+7, cols tx+16u
    u64 acc[4][8];
    #pragma unroll
    for (int r = 0; r < 4; r++)
        #pragma unroll
        for (int u = 0; u < 8; u++) acc[r][u] = 0ull;

    auto ldA = [&](int kgabs) -> float4 {
        int tap = kgabs >> 5;
        int ci = (kgabs << 2) & 127;
        int dt, di, dj;
        if (KS == 3) { dt = tap/9 - 1; int r9 = tap%9; di = r9/3 - 1; dj = r9%3 - 1; }
        else { dt = (tap>>2) - 1; di = ((tap>>1)&1) - 1; dj = (tap&1) - 1; }
        int t2 = tt + dt, i2 = ii + di, j2 = jj + dj;
        if ((unsigned)t2 < 128u && (unsigned)i2 < 4u && (unsigned)j2 < 4u)
            return *(const float4*)(jb.in + (((bb<<11) + (t2<<4) + (i2<<2) + j2) << 7) + ci);
        return make_float4(0.f,0.f,0.f,0.f);
    };
    auto stB = [&](int s, int row, float4 v) {
        *(u64*)&Bs[s][row][(bc+0)<<1] = pack2(v.x, v.x);
        *(u64*)&Bs[s][row][(bc+1)<<1] = pack2(v.y, v.y);
        *(u64*)&Bs[s][row][(bc+2)<<1] = pack2(v.z, v.z);
        *(u64*)&Bs[s][row][(bc+3)<<1] = pack2(v.w, v.w);
    };

    {   // prologue stage 0
        int kg4 = kbase >> 2;
        float4 a0 = ldA(kg4 + kg), a1 = ldA(kg4 + kg + 2);
        float4 b0 = *(const float4*)(jb.wt + (size_t)(kbase + br)*CD + bc);
        float4 b1 = *(const float4*)(jb.wt + (size_t)(kbase + br + 8)*CD + bc);
        int k4 = kg << 2;
        As[0][k4+0][am]=a0.x; As[0][k4+1][am]=a0.y; As[0][k4+2][am]=a0.z; As[0][k4+3][am]=a0.w;
        As[0][k4+8][am]=a1.x; As[0][k4+9][am]=a1.y; As[0][k4+10][am]=a1.z; As[0][k4+11][am]=a1.w;
        stB(0, br, b0); stB(0, br+8, b1);
    }
    __syncthreads();

    for (int it = 0; it < NIT; it++) {
        int s = it & 1;
        float4 na0, na1, nb0, nb1;
        bool more = (it + 1 < NIT);
        if (more) {
            int kofs = kbase + (it+1)*16;
            na0 = ldA((kofs>>2) + kg); na1 = ldA((kofs>>2) + kg + 2);
            nb0 = *(const float4*)(jb.wt + (size_t)(kofs + br)*CD + bc);
            nb1 = *(const float4*)(jb.wt + (size_t)(kofs + br + 8)*CD + bc);
        }
        #pragma unroll
        for (int kk = 0; kk < 16; kk++) {
            F4U u0, u1;
            u0.f = *(const float4*)&As[s][kk][ty << 3];
            u1.f = *(const float4*)(&As[s][kk][ty << 3] + 4);
            u64 ap[4] = {u0.u[0], u0.u[1], u1.u[0], u1.u[1]};
            u64 bu[8];
            #pragma unroll
            for (int u = 0; u < 8; u++)
                bu[u] = *(const u64*)&Bs[s][kk][(tx + (u<<4)) << 1];
            #pragma unroll
            for (int r = 0; r < 4; r++)
                #pragma unroll
                for (int u = 0; u < 8; u++)
                    fma2(acc[r][u], ap[r], bu[u]);
        }
        if (more) {
            int so = s ^ 1, k4 = kg << 2;
            As[so][k4+0][am]=na0.x; As[so][k4+1][am]=na0.y; As[so][k4+2][am]=na0.z; As[so][k4+3][am]=na0.w;
            As[so][k4+8][am]=na1.x; As[so][k4+9][am]=na1.y; As[so][k4+10][am]=na1.z; As[so][k4+11][am]=na1.w;
            stB(so, br, nb0); stB(so, br+8, nb1);
            __syncthreads();
        }
    }

    float* pb = g_part + ((size_t)(split*2 + job) << 19);
    #pragma unroll
    for (int r = 0; r < 4; r++) {
        int mA = m0 + (ty<<3) + (r<<1), mB = mA + 1;
        #pragma unroll
        for (int u = 0; u < 8; u++) {
            float2 f = unpack2(acc[r][u]);
            int col = tx + (u<<4);
            pb[(size_t)mA*CD + col] = f.x;
            pb[(size_t)mB*CD + col] = f.y;
        }
    }
}

template<int SPLIT>
__global__ void reduce_split(Job j0, Job j1) {
    int idx = blockIdx.x * 256 + threadIdx.x;      // over 2 * 2^19
    int job = idx >> 19, r = idx & ((1<<19) - 1);
    Job jb = job ? j1 : j0;
    float s = 0.f;
    #pragma unroll
    for (int sp = 0; sp < SPLIT; sp++)
        s += g_part[((size_t)(sp*2 + job) << 19) + r];
    if (jb.bias) s += jb.bias[r & 127];
    if (jb.res)  s += jb.res[r];
    jb.out[r] = s;
}

// ---------- small conv (KS=1 paths: v/r3 pair and proj) ----------
__global__ void conv_gemm_small(Job j0, Job j1) {
    constexpr int K = CD;
    constexpr int NIT = K / 16;
    Job jb = (blockIdx.z == 0) ? j0 : j1;
    const int m0 = blockIdx.y << 6, n0 = blockIdx.x << 6;
    __shared__ float As[2][16][64], Bs[2][16][64];
    const int tid = threadIdx.x;
    const int am = tid & 63, kgA = tid >> 6;
    const int gm = m0 + am;
    const int br = tid >> 4, bc = (tid & 15) << 2;
    const int ty = tid >> 4, tx = tid & 15;
    u64 acc[4][4];
    #pragma unroll
    for (int r = 0; r < 4; r++)
        #pragma unroll
        for (int c = 0; c < 4; c++) acc[r][c] = 0ull;

    auto ldA = [&](int kgabs) -> float4 {
        int ci = (kgabs << 2) & 127;
        return *(const float4*)(jb.in + ((size_t)gm << 7) + ci);
    };
    {
        float4 a0 = ldA(kgA), a1 = ldA(kgA + 2);
        float4 b0 = *(const float4*)(jb.wt + (size_t)br*CD + n0 + bc);
        float4 b1 = *(const float4*)(jb.wt + (size_t)(br+8)*CD + n0 + bc);
        int k4 = kgA << 2;
        As[0][k4+0][am]=a0.x; As[0][k4+1][am]=a0.y; As[0][k4+2][am]=a0.z; As[0][k4+3][am]=a0.w;
        As[0][k4+8][am]=a1.x; As[0][k4+9][am]=a1.y; As[0][k4+10][am]=a1.z; As[0][k4+11][am]=a1.w;
        *(float4*)&Bs[0][br][bc]   = b0;
        *(float4*)&Bs[0][br+8][bc] = b1;
    }
    __syncthreads();

    for (int it = 0; it < NIT; it++) {
        int s = it & 1;
        float4 na0, na1, nb0, nb1;
        bool more = (it + 1 < NIT);
        if (more) {
            int kg = (it+1)*4;
            na0 = ldA(kg + kgA); na1 = ldA(kg + kgA + 2);
            nb0 = *(const float4*)(jb.wt + (size_t)((it+1)*16 + br)*CD + n0 + bc);
            nb1 = *(const float4*)(jb.wt + (size_t)((it+1)*16 + br + 8)*CD + n0 + bc);
        }
        #pragma unroll
        for (int kk = 0; kk < 16; kk++) {
            F4U u0, u1;
            u0.f = *(const float4*)&As[s][kk][ty << 3];
            u1.f = *(const float4*)(&As[s][kk][ty << 3] + 4);
            u64 ap[4] = {u0.u[0], u0.u[1], u1.u[0], u1.u[1]};
            float4 bq = *(const float4*)&Bs[s][kk][tx << 2];
            u64 b0 = pack2(bq.x, bq.x), b1 = pack2(bq.y, bq.y);
            u64 b2 = pack2(bq.z, bq.z), b3 = pack2(bq.w, bq.w);
            #pragma unroll
            for (int r = 0; r < 4; r++) {
                fma2(acc[r][0], ap[r], b0);
                fma2(acc[r][1], ap[r], b1);
                fma2(acc[r][2], ap[r], b2);
                fma2(acc[r][3], ap[r], b3);
            }
        }
        if (more) {
            int so = s ^ 1, k4 = kgA << 2;
            As[so][k4+0][am]=na0.x; As[so][k4+1][am]=na0.y; As[so][k4+2][am]=na0.z; As[so][k4+3][am]=na0.w;
            As[so][k4+8][am]=na1.x; As[so][k4+9][am]=na1.y; As[so][k4+10][am]=na1.z; As[so][k4+11][am]=na1.w;
            *(float4*)&Bs[so][br][bc]   = nb0;
            *(float4*)&Bs[so][br+8][bc] = nb1;
            __syncthreads();
        }
    }

    int c0 = n0 + (tx << 2);
    float4 bias4 = make_float4(0.f,0.f,0.f,0.f);
    if (jb.bias) bias4 = *(const float4*)(jb.bias + c0);
    #pragma unroll
    for (int rp = 0; rp < 4; rp++) {
        float2 p0 = unpack2(acc[rp][0]), p1 = unpack2(acc[rp][1]);
        float2 p2 = unpack2(acc[rp][2]), p3 = unpack2(acc[rp][3]);
        int mA = m0 + (ty << 3) + (rp << 1), mB = mA + 1;
        float4 oA = make_float4(p0.x+bias4.x, p1.x+bias4.y, p2.x+bias4.z, p3.x+bias4.w);
        float4 oB = make_float4(p0.y+bias4.x, p1.y+bias4.y, p2.y+bias4.z, p3.y+bias4.w);
        if (jb.res) {
            float4 rA = *(const float4*)(jb.res + (size_t)mA*CD + c0);
            float4 rB = *(const float4*)(jb.res + (size_t)mB*CD + c0);
            oA.x += rA.x; oA.y += rA.y; oA.z += rA.z; oA.w += rA.w;
            oB.x += rB.x; oB.y += rB.y; oB.z += rB.z; oB.w += rB.w;
        }
        *(float4*)(jb.out + (size_t)mA*CD + c0) = oA;
        *(float4*)(jb.out + (size_t)mB*CD + c0) = oB;
    }
}

// ---------- flash v2: 128 thr, 4 warps * 16 rows = 64 rows/block; padded smem ----------
__global__ void flash_kernel(const float* __restrict__ q, const float* __restrict__ k,
                             const float* __restrict__ v, float* __restrict__ out) {
    const float LOG2E = 1.4426950408889634f;
    int bh = blockIdx.y, b = bh >> 3, h = bh & 7;
    int qbase = blockIdx.x << 6;
    __shared__ float4 ks[128][5], vs[128][5];   // 80B row stride: conflict-free
    int tid = threadIdx.x, wid = tid >> 5, lane = tid & 31;
    int r = lane >> 2, g = lane & 3;
    int rowA = qbase + (wid << 4) + r, rowB = rowA + 8;
    const float* qpA = q + (((b<<11) + rowA) << 7) + (h << 4);
    const float* qpB = q + (((b<<11) + rowB) << 7) + (h << 4);
    u64 qa[8], qb2[8];
    #pragma unroll
    for (int j = 0; j < 4; j++) {
        float4 ta = *(const float4*)(qpA + j*4);
        float4 tb = *(const float4*)(qpB + j*4);
        qa[j*2]   = pack2(ta.x*LOG2E, ta.y*LOG2E);
        qa[j*2+1] = pack2(ta.z*LOG2E, ta.w*LOG2E);
        qb2[j*2]   = pack2(tb.x*LOG2E, tb.y*LOG2E);
        qb2[j*2+1] = pack2(tb.z*LOG2E, tb.w*LOG2E);
    }
    u64 accA[8], accB[8];
    #pragma unroll
    for (int d = 0; d < 8; d++) { accA[d] = 0ull; accB[d] = 0ull; }
    float mA = -1e30f, mB = -1e30f, lsA = 0.f, lsB = 0.f;
    const float* kbase = k + (((size_t)b << 11) << 7) + (h << 4);
    const float* vbase = v + (((size_t)b << 11) << 7) + (h << 4);

    for (int kt = 0; kt < 2048; kt += 128) {
        __syncthreads();
        #pragma unroll
        for (int u = 0; u < 4; u++) {
            int li = tid + (u << 7);
            int row = li >> 2, j = li & 3;
            ks[row][j] = *(const float4*)(kbase + (size_t)(kt+row)*CD + (j<<2));
            vs[row][j] = *(const float4*)(vbase + (size_t)(kt+row)*CD + (j<<2));
        }
        __syncthreads();
        #pragma unroll
        for (int ch = 0; ch < 2; ch++) {
            float sA[16], sB[16];
            float tmA = -1e30f, tmB = -1e30f;
            #pragma unroll
            for (int i = 0; i < 16; i++) {
                int kc = (ch << 6) + (i << 2) + g;
                F4U k0, k1, k2, k3;
                k0.f = ks[kc][0]; k1.f = ks[kc][1]; k2.f = ks[kc][2]; k3.f = ks[kc][3];
                u64 dA = 0ull, dB = 0ull;
                fma2(dA, qa[0], k0.u[0]); fma2(dA, qa[1], k0.u[1]);
                fma2(dA, qa[2], k1.u[0]); fma2(dA, qa[3], k1.u[1]);
                fma2(dA, qa[4], k2.u[0]); fma2(dA, qa[5], k2.u[1]);
                fma2(dA, qa[6], k3.u[0]); fma2(dA, qa[7], k3.u[1]);
                fma2(dB, qb2[0], k0.u[0]); fma2(dB, qb2[1], k0.u[1]);
                fma2(dB, qb2[2], k1.u[0]); fma2(dB, qb2[3], k1.u[1]);
                fma2(dB, qb2[4], k2.u[0]); fma2(dB, qb2[5], k2.u[1]);
                fma2(dB, qb2[6], k3.u[0]); fma2(dB, qb2[7], k3.u[1]);
                float2 fa = unpack2(dA), fb = unpack2(dB);
                sA[i] = fa.x + fa.y; sB[i] = fb.x + fb.y;
                tmA = fmaxf(tmA, sA[i]); tmB = fmaxf(tmB, sB[i]);
            }
            tmA = fmaxf(tmA, __shfl_xor_sync(~0u, tmA, 1));
            tmA = fmaxf(tmA, __shfl_xor_sync(~0u, tmA, 2));
            tmB = fmaxf(tmB, __shfl_xor_sync(~0u, tmB, 1));
            tmB = fmaxf(tmB, __shfl_xor_sync(~0u, tmB, 2));
            float nA = fmaxf(mA, tmA), nB = fmaxf(mB, tmB);
            float cA = exp2f(mA - nA), cB = exp2f(mB - nB);
            mA = nA; mB = nB; lsA *= cA; lsB *= cB;
            u64 cA2 = pack2(cA, cA), cB2 = pack2(cB, cB);
            #pragma unroll
            for (int d = 0; d < 8; d++) { mul2(accA[d], cA2); mul2(accB[d], cB2); }
            #pragma unroll
            for (int i = 0; i < 16; i++) {
                int kc = (ch << 6) + (i << 2) + g;
                float pA = exp2f(sA[i] - mA), pB = exp2f(sB[i] - mB);
                lsA += pA; lsB += pB;
                u64 pA2 = pack2(pA, pA), pB2 = pack2(pB, pB);
                F4U v0, v1, v2, v3;
                v0.f = vs[kc][0]; v1.f = vs[kc][1]; v2.f = vs[kc][2]; v3.f = vs[kc][3];
                fma2(accA[0], pA2, v0.u[0]); fma2(accA[1], pA2, v0.u[1]);
                fma2(accA[2], pA2, v1.u[0]); fma2(accA[3], pA2, v1.u[1]);
                fma2(accA[4], pA2, v2.u[0]); fma2(accA[5], pA2, v2.u[1]);
                fma2(accA[6], pA2, v3.u[0]); fma2(accA[7], pA2, v3.u[1]);
                fma2(accB[0], pB2, v0.u[0]); fma2(accB[1], pB2, v0.u[1]);
                fma2(accB[2], pB2, v1.u[0]); fma2(accB[3], pB2, v1.u[1]);
                fma2(accB[4], pB2, v2.u[0]); fma2(accB[5], pB2, v2.u[1]);
                fma2(accB[6], pB2, v3.u[0]); fma2(accB[7], pB2, v3.u[1]);
            }
        }
    }
    // reduce over 4 g-lanes, write both rows with fused conv_atten
    float aA[16], aB[16];
    #pragma unroll
    for (int d = 0; d < 8; d++) {
        float2 fa = unpack2(accA[d]), fb = unpack2(accB[d]);
        aA[d*2] = fa.x; aA[d*2+1] = fa.y;
        aB[d*2] = fb.x; aB[d*2+1] = fb.y;
    }
    #pragma unroll
    for (int d = 0; d < 16; d++) {
        aA[d] += __shfl_xor_sync(~0u, aA[d], 1);
        aA[d] += __shfl_xor_sync(~0u, aA[d], 2);
        aB[d] += __shfl_xor_sync(~0u, aB[d], 1);
        aB[d] += __shfl_xor_sync(~0u, aB[d], 2);
    }
    lsA += __shfl_xor_sync(~0u, lsA, 1); lsA += __shfl_xor_sync(~0u, lsA, 2);
    lsB += __shfl_xor_sync(~0u, lsB, 1); lsB += __shfl_xor_sync(~0u, lsB, 2);
    float invA = 1.0f / lsA, invB = 1.0f / lsB;
    #pragma unroll
    for (int rr = 0; rr < 2; rr++) {
        int qrow = rr ? rowB : rowA;
        float inv = rr ? invB : invA;
        float* ac = rr ? aB : aA;
        size_t base = ((size_t)((b<<11) + qrow) << 7) + (h << 4);
        float ov[4];
        #pragma unroll
        for (int u = 0; u < 4; u++) {
            int w2 = (g << 2) + u;
            float ca = 0.f;
            #pragma unroll
            for (int s2 = 0; s2 < 3; s2++) {
                int f = w2 + (s2 << 4);
                int sel = f % 3;
                const float* tp = (sel == 0) ? q : ((sel == 1) ? k : v);
                ca += tp[base + f/3];
            }
            ov[u] = ac[(g<<2)+u]*inv + ca*(1.0f/3.0f);
        }
        *(float4*)(out + base + (g << 2)) = make_float4(ov[0], ov[1], ov[2], ov[3]);
    }
}

__global__ void combine_ln(const float* __restrict__ a1, const float* __restrict__ a2,
                           const float* __restrict__ a3, const float* __restrict__ hh,
                           const float* __restrict__ gam, const float* __restrict__ bet,
                           float* __restrict__ x2, float* __restrict__ y2,
                           float* __restrict__ xm) {
    int m = blockIdx.x, c = threadIdx.x, lane = c & 31, wid = c >> 5;
    float sacc = 0.f;
    #pragma unroll
    for (int s2 = 0; s2 < 3; s2++) {
        int f = c*3 + s2;
        const float* ap = (f >> 7) == 0 ? a1 : ((f >> 7) == 1 ? a2 : a3);
        sacc += ap[(m << 7) + (f & 127)];
    }
    float v = sacc*(1.0f/3.0f) + hh[m*CD + c];
    x2[m*CD + c] = v;
    float s = v, sq = v*v;
    #pragma unroll
    for (int o = 16; o > 0; o >>= 1) { s += __shfl_xor_sync(~0u, s, o); sq += __shfl_xor_sync(~0u, sq, o); }
    __shared__ float ss[4], sqq[4], ys[4];
    if (lane == 0) { ss[wid] = s; sqq[wid] = sq; }
    __syncthreads();
    float S = ss[0]+ss[1]+ss[2]+ss[3], SQ = sqq[0]+sqq[1]+sqq[2]+sqq[3];
    float mean = S*(1.0f/CD), var = SQ*(1.0f/CD) - mean*mean, rs = rsqrtf(var + 1e-6f);
    float y = (v - mean)*rs*gam[c] + bet[c];
    y2[m*CD + c] = y;
    float t = y;
    #pragma unroll
    for (int o = 16; o > 0; o >>= 1) t += __shfl_xor_sync(~0u, t, o);
    if (lane == 0) ys[wid] = t;
    __syncthreads();
    if (c == 0) xm[m] = (ys[0]+ys[1]+ys[2]+ys[3])*(1.0f/CD);
}

__global__ void final_kernel(const float* __restrict__ x2, const float* __restrict__ y2,
                             const float* __restrict__ xm, const float* __restrict__ st1,
                             const float* __restrict__ st2, const float* __restrict__ st3,
                             float* __restrict__ out) {
    int m = blockIdx.x, b = m >> 11, p = m & 2047;
    int t = p >> 4, ii = (p >> 2) & 3, jj = p & 3;
    __shared__ float sg;
    if (threadIdx.x == 0) {
        float gg = st1[0] * xm[m];
        #pragma unroll
        for (int kd = 0; kd < 2; kd++)
        for (int kh = 0; kh < 2; kh++)
        for (int kw = 0; kw < 2; kw++) {
            int t2 = t + kd - 1, i2 = ii + kh - 1, j2 = jj + kw - 1;
            if ((unsigned)t2 < 128u && (unsigned)i2 < 4u && (unsigned)j2 < 4u)
                gg += st2[kd*4 + kh*2 + kw] * xm[(b<<11) + (t2<<4) + (i2<<2) + j2];
        }
        #pragma unroll
        for (int kd = 0; kd < 3; kd++)
        for (int kh = 0; kh < 3; kh++)
        for (int kw = 0; kw < 3; kw++) {
            int t2 = t + kd - 1, i2 = ii + kh - 1, j2 = jj + kw - 1;
            if ((unsigned)t2 < 128u && (unsigned)i2 < 4u && (unsigned)j2 < 4u)
                gg += st3[kd*9 + kh*3 + kw] * xm[(b<<11) + (t2<<4) + (i2<<2) + j2];
        }
        sg = 1.0f / (1.0f + __expf(-gg));
    }
    __syncthreads();
    int idx = m*CD + threadIdx.x;
    out[idx] = x2[idx] + y2[idx]*sg;
}

extern "C" void kernel_launch(void* const* d_in, const int* in_sizes, int n_in,
                              void* d_out, int out_size) {
    const float* x      = (const float*)d_in[0];
    const float* n1g    = (const float*)d_in[1];
    const float* n1b    = (const float*)d_in[2];
    const float* q_w    = (const float*)d_in[3];
    const float* qbg    = (const float*)d_in[4];
    const float* qbb    = (const float*)d_in[5];
    const float* k_w    = (const float*)d_in[6];
    const float* kbg    = (const float*)d_in[7];
    const float* kbb    = (const float*)d_in[8];
    const float* v_w    = (const float*)d_in[9];
    const float* proj_w = (const float*)d_in[10];
    const float* proj_b = (const float*)d_in[11];
    const float* r1_w   = (const float*)d_in[12];
    const float* r2_w   = (const float*)d_in[13];
    const float* r3_w   = (const float*)d_in[14];
    const float* n2g    = (const float*)d_in[15];
    const float* n2b    = (const float*)d_in[16];
    const float* st1    = (const float*)d_in[17];
    const float* st2    = (const float*)d_in[18];
    const float* st3    = (const float*)d_in[19];
    float* out = (float*)d_out;

    float *y1,*qb,*kb,*vb,*attn,*hb,*a1,*a2,*a3,*x2,*y2,*xm;
    float *wq,*wk,*wv,*wr1,*wr2,*wr3,*wp,*bnst;
    cudaGetSymbolAddress((void**)&y1, g_y1);     cudaGetSymbolAddress((void**)&qb, g_qb);
    cudaGetSymbolAddress((void**)&kb, g_kb);     cudaGetSymbolAddress((void**)&vb, g_vb);
    cudaGetSymbolAddress((void**)&attn, g_attn); cudaGetSymbolAddress((void**)&hb, g_hb);
    cudaGetSymbolAddress((void**)&a1, g_a1);     cudaGetSymbolAddress((void**)&a2, g_a2);
    cudaGetSymbolAddress((void**)&a3, g_a3);     cudaGetSymbolAddress((void**)&x2, g_x2);
    cudaGetSymbolAddress((void**)&y2, g_y2);     cudaGetSymbolAddress((void**)&xm, g_xm);
    cudaGetSymbolAddress((void**)&wq, g_wq);     cudaGetSymbolAddress((void**)&wk, g_wk);
    cudaGetSymbolAddress((void**)&wv, g_wv);     cudaGetSymbolAddress((void**)&wr1, g_wr1);
    cudaGetSymbolAddress((void**)&wr2, g_wr2);   cudaGetSymbolAddress((void**)&wr3, g_wr3);
    cudaGetSymbolAddress((void**)&wp, g_wp);     cudaGetSymbolAddress((void**)&bnst, g_bnst);

    auto cdiv = [](int a, int b){ return (a + b - 1) / b; };
    const int n27 = 27*CD*CD, n8 = 8*CD*CD, n1 = CD*CD;

    WJobs wa = {};
    wa.nj = 2;
    wa.src[0]=q_w;  wa.dst[0]=wq;  wa.KK[0]=27; wa.n[0]=n27;
    wa.src[1]=r1_w; wa.dst[1]=wr1; wa.KK[1]=27; wa.n[1]=n27;
    WJobs wb = {};
    wb.nj = 5;
    wb.src[0]=k_w;   wb.dst[0]=wk;  wb.KK[0]=8; wb.n[0]=n8;
    wb.src[1]=r2_w;  wb.dst[1]=wr2; wb.KK[1]=8; wb.n[1]=n8;
    wb.src[2]=v_w;   wb.dst[2]=wv;  wb.KK[2]=1; wb.n[2]=n1;
    wb.src[3]=r3_w;  wb.dst[3]=wr3; wb.KK[3]=1; wb.n[3]=n1;
    wb.src[4]=proj_w;wb.dst[4]=wp;  wb.KK[4]=1; wb.n[4]=n1;

    wtrans_multi<<<cdiv(2*n27,256),256>>>(wa, bnst, 2*2*CD);
    wtrans_multi<<<cdiv(2*n8+3*n1,256),256>>>(wb, nullptr, 0);
    ln_kernel<<<MTOT, 128>>>(x, y1, n1g, n1b, nullptr, 1e-6f);

    Job jq  = { y1, wq,  nullptr, nullptr, qb };
    Job jr1 = { x,  wr1, x,       nullptr, a1 };
    conv_gemm_big<3,8><<<dim3(32,8,2), 256>>>(jq, jr1);
    reduce_split<8><<<MTOT*CD*2/256, 256>>>(jq, jr1);

    Job jk  = { y1, wk,  nullptr, nullptr, kb };
    Job jr2 = { a1, wr2, a1,      nullptr, a2 };
    conv_gemm_big<2,8><<<dim3(32,8,2), 256>>>(jk, jr2);
    reduce_split<8><<<MTOT*CD*2/256, 256>>>(jk, jr2);

    bn_stats<<<dim3(32,2), 256>>>(qb, kb);
    bn_apply<<<dim3(MTOT*CD/256,2), 256>>>(qb, kb, qbg, qbb, kbg, kbb);

    Job jv  = { y1, wv,  nullptr, nullptr, vb };
    Job jr3 = { a2, wr3, a2,      nullptr, a3 };
    conv_gemm_small<<<dim3(2,64,2), 128>>>(jv, jr3);

    flash_kernel<<<dim3(32,16), 128>>>(qb, kb, vb, attn);

    Job jp = { attn, wp, nullptr, proj_b, hb };
    conv_gemm_small<<<dim3(2,64,1), 128>>>(jp, jp);

    combine_ln<<<MTOT, 128>>>(a1, a2, a3, hb, n2g, n2b, x2, y2, xm);
    final_kernel<<<MTOT, 128>>>(x2, y2, xm, st1, st2, st3, out);
}

// round 6
// speedup vs baseline: 1.9967x; 1.0931x over previous
#include <cuda_runtime.h>
#include <math.h>

#define CD 128
#define MTOT 4096

typedef unsigned long long u64;

__device__ __forceinline__ u64 pack2(float lo, float hi) {
    u64 r; asm("mov.b64 %0,{%1,%2};" : "=l"(r) : "f"(lo), "f"(hi)); return r;
}
__device__ __forceinline__ void fma2(u64& d, u64 a, u64 b) {
    asm("fma.rn.f32x2 %0,%1,%2,%0;" : "+l"(d) : "l"(a), "l"(b));
}
__device__ __forceinline__ void mul2(u64& d, u64 a) {
    asm("mul.rn.f32x2 %0,%0,%1;" : "+l"(d) : "l"(a));
}
__device__ __forceinline__ float2 unpack2(u64 v) {
    float2 f; asm("mov.b64 {%0,%1},%2;" : "=f"(f.x), "=f"(f.y) : "l"(v)); return f;
}

union F4U { float4 f; u64 u[2]; };

struct Job  { const float* in; const float* wt; const float* res; const float* bias; float* out; };
struct WJobs { const float* src[5]; float* dst[5]; int KK[5]; int n[5]; int nj; };

__device__ float g_y1[MTOT*CD], g_qb[MTOT*CD], g_kb[MTOT*CD], g_vb[MTOT*CD];
__device__ float g_attn[MTOT*CD], g_hb[MTOT*CD], g_a1[MTOT*CD], g_a2[MTOT*CD], g_a3[MTOT*CD];
__device__ float g_x2[MTOT*CD], g_y2[MTOT*CD], g_xm[MTOT];
__device__ float g_wq[27*CD*CD], g_wk[8*CD*CD], g_wv[CD*CD];
__device__ float g_wr1[27*CD*CD], g_wr2[8*CD*CD], g_wr3[CD*CD], g_wp[CD*CD];
__device__ float g_bnst[2][2][CD];
__device__ float g_part[9*2*MTOT*CD];   // split-K partials: [split][job][m][c]

__global__ void wtrans_multi(WJobs J, float* zbuf, int zn) {
    int idx = blockIdx.x * 256 + threadIdx.x;
    if (zbuf && idx < zn) zbuf[idx] = 0.f;
    int base = 0;
    #pragma unroll
    for (int j = 0; j < 5; j++) {
        if (j >= J.nj) return;
        if (idx < base + J.n[j]) {
            int t = idx - base;
            int tap = t / (CD*CD); int rem = t - tap*(CD*CD);
            int ci = rem >> 7, co = rem & 127;
            J.dst[j][t] = J.src[j][(co*CD + ci)*J.KK[j] + tap];
            return;
        }
        base += J.n[j];
    }
}

__global__ void ln_kernel(const float* __restrict__ in, float* __restrict__ out,
                          const float* __restrict__ gam, const float* __restrict__ bet,
                          float* __restrict__ xm, float eps) {
    int m = blockIdx.x, c = threadIdx.x, lane = c & 31, wid = c >> 5;
    float v = in[m*CD + c], s = v, sq = v*v;
    #pragma unroll
    for (int o = 16; o > 0; o >>= 1) { s += __shfl_xor_sync(~0u, s, o); sq += __shfl_xor_sync(~0u, sq, o); }
    __shared__ float ss[4], sqq[4], ys[4];
    if (lane == 0) { ss[wid] = s; sqq[wid] = sq; }
    __syncthreads();
    float S = ss[0]+ss[1]+ss[2]+ss[3], SQ = sqq[0]+sqq[1]+sqq[2]+sqq[3];
    float mean = S*(1.0f/CD), var = SQ*(1.0f/CD) - mean*mean, rs = rsqrtf(var + eps);
    float y = (v - mean)*rs*gam[c] + bet[c];
    out[m*CD + c] = y;
    if (xm) {
        float t = y;
        #pragma unroll
        for (int o = 16; o > 0; o >>= 1) t += __shfl_xor_sync(~0u, t, o);
        if (lane == 0) ys[wid] = t;
        __syncthreads();
        if (c == 0) xm[m] = (ys[0]+ys[1]+ys[2]+ys[3])*(1.0f/CD);
    }
}

__global__ void bn_stats(const float* __restrict__ q, const float* __restrict__ k) {
    int buf = blockIdx.y;
    const float* src = buf ? k : q;
    int tid = threadIdx.x;
    int base = blockIdx.x * 128;
    float s = 0.f, sq = 0.f;
    for (int i = tid; i < 128*CD; i += 256) {
        float v = src[(base + (i >> 7))*CD + (i & 127)];
        s += v; sq += v*v;
    }
    __shared__ float sh[256];
    sh[tid] = s; __syncthreads();
    if (tid < 128) atomicAdd(&g_bnst[buf][0][tid], sh[tid] + sh[tid+128]);
    __syncthreads();
    sh[tid] = sq; __syncthreads();
    if (tid < 128) atomicAdd(&g_bnst[buf][1][tid], sh[tid] + sh[tid+128]);
}

__global__ void bn_apply(float* __restrict__ q, float* __restrict__ k,
                         const float* __restrict__ qg, const float* __restrict__ qb2,
                         const float* __restrict__ kg, const float* __restrict__ kb2) {
    int buf = blockIdx.y;
    float* dst = buf ? k : q;
    const float* gam = buf ? kg : qg;
    const float* bet = buf ? kb2 : qb2;
    int idx = blockIdx.x * 256 + threadIdx.x;
    int c = idx & 127;
    float S = g_bnst[buf][0][c], SQ = g_bnst[buf][1][c];
    float mean = S*(1.0f/MTOT), var = SQ*(1.0f/MTOT) - mean*mean;
    float sc = gam[c]*rsqrtf(var + 1e-5f), sh = bet[c] - mean*sc;
    dst[idx] = dst[idx]*sc + sh;
}

// ---------- big conv: BM=128 BN=128 BK=16, 256 thr, TM=8 TN=8 contiguous, split-K ----------
template<int KS, int SPLIT>
__global__ __launch_bounds__(256) void conv_gemm_big(Job j0, Job j1) {
    constexpr int K = KS*KS*KS*CD;
    constexpr int KSP = K / SPLIT;
    constexpr int NIT = KSP / 16;
    const int job = blockIdx.z, split = blockIdx.y;
    Job jb = job ? j1 : j0;
    const int m0 = blockIdx.x << 7;
    const int kbase = split * KSP;
    __shared__ float As[2][16][128];
    __shared__ float Bs[2][16][128];
    const int tid = threadIdx.x;
    const int am = tid & 127, kg = tid >> 7;           // A loader: k-groups kg, kg+2
    const int gm = m0 + am, bb = gm >> 11, p = gm & 2047;
    const int tt = p >> 4, ii = (p >> 2) & 3, jj = p & 3;
    const int br = tid >> 5, bc = (tid & 31) << 2;     // B loader: rows br, br+8
    const int ty = tid >> 4, tx = tid & 15;            // compute: rows ty*8..+7, cols tx*8..+7
    u64 acc[4][8];
    #pragma unroll
    for (int r = 0; r < 4; r++)
        #pragma unroll
        for (int u = 0; u < 8; u++) acc[r][u] = 0ull;

    auto ldA = [&](int kgabs) -> float4 {
        int tap = kgabs >> 5;
        int ci = (kgabs << 2) & 127;
        int dt, di, dj;
        if (KS == 3) { dt = tap/9 - 1; int r9 = tap%9; di = r9/3 - 1; dj = r9%3 - 1; }
        else { dt = (tap>>2) - 1; di = ((tap>>1)&1) - 1; dj = (tap&1) - 1; }
        int t2 = tt + dt, i2 = ii + di, j2 = jj + dj;
        if ((unsigned)t2 < 128u && (unsigned)i2 < 4u && (unsigned)j2 < 4u)
            return *(const float4*)(jb.in + (((bb<<11) + (t2<<4) + (i2<<2) + j2) << 7) + ci);
        return make_float4(0.f,0.f,0.f,0.f);
    };

    {   // prologue stage 0
        int kg4 = kbase >> 2;
        float4 a0 = ldA(kg4 + kg), a1 = ldA(kg4 + kg + 2);
        float4 b0 = *(const float4*)(jb.wt + (size_t)(kbase + br)*CD + bc);
        float4 b1 = *(const float4*)(jb.wt + (size_t)(kbase + br + 8)*CD + bc);
        int k4 = kg << 2;
        As[0][k4+0][am]=a0.x; As[0][k4+1][am]=a0.y; As[0][k4+2][am]=a0.z; As[0][k4+3][am]=a0.w;
        As[0][k4+8][am]=a1.x; As[0][k4+9][am]=a1.y; As[0][k4+10][am]=a1.z; As[0][k4+11][am]=a1.w;
        *(float4*)&Bs[0][br][bc]   = b0;
        *(float4*)&Bs[0][br+8][bc] = b1;
    }
    __syncthreads();

    for (int it = 0; it < NIT; it++) {
        int s = it & 1;
        float4 na0, na1, nb0, nb1;
        bool more = (it + 1 < NIT);
        if (more) {
            int kofs = kbase + (it+1)*16;
            na0 = ldA((kofs>>2) + kg); na1 = ldA((kofs>>2) + kg + 2);
            nb0 = *(const float4*)(jb.wt + (size_t)(kofs + br)*CD + bc);
            nb1 = *(const float4*)(jb.wt + (size_t)(kofs + br + 8)*CD + bc);
        }
        #pragma unroll
        for (int kk = 0; kk < 16; kk++) {
            F4U a0, a1;
            a0.f = *(const float4*)&As[s][kk][ty << 3];
            a1.f = *(const float4*)(&As[s][kk][ty << 3] + 4);
            u64 ap[4] = {a0.u[0], a0.u[1], a1.u[0], a1.u[1]};
            float4 b0 = *(const float4*)&Bs[s][kk][tx << 3];
            float4 b1 = *(const float4*)(&Bs[s][kk][tx << 3] + 4);
            u64 bp[8];
            bp[0] = pack2(b0.x, b0.x); bp[1] = pack2(b0.y, b0.y);
            bp[2] = pack2(b0.z, b0.z); bp[3] = pack2(b0.w, b0.w);
            bp[4] = pack2(b1.x, b1.x); bp[5] = pack2(b1.y, b1.y);
            bp[6] = pack2(b1.z, b1.z); bp[7] = pack2(b1.w, b1.w);
            #pragma unroll
            for (int r = 0; r < 4; r++)
                #pragma unroll
                for (int u = 0; u < 8; u++)
                    fma2(acc[r][u], ap[r], bp[u]);
        }
        if (more) {
            int so = s ^ 1, k4 = kg << 2;
            As[so][k4+0][am]=na0.x; As[so][k4+1][am]=na0.y; As[so][k4+2][am]=na0.z; As[so][k4+3][am]=na0.w;
            As[so][k4+8][am]=na1.x; As[so][k4+9][am]=na1.y; As[so][k4+10][am]=na1.z; As[so][k4+11][am]=na1.w;
            *(float4*)&Bs[so][br][bc]   = nb0;
            *(float4*)&Bs[so][br+8][bc] = nb1;
            __syncthreads();
        }
    }

    float* pb = g_part + ((size_t)(split*2 + job) << 19);
    int c0 = tx << 3;
    #pragma unroll
    for (int r = 0; r < 4; r++) {
        int mA = m0 + (ty<<3) + (r<<1), mB = mA + 1;
        float2 f0 = unpack2(acc[r][0]), f1 = unpack2(acc[r][1]);
        float2 f2 = unpack2(acc[r][2]), f3 = unpack2(acc[r][3]);
        float2 f4 = unpack2(acc[r][4]), f5 = unpack2(acc[r][5]);
        float2 f6 = unpack2(acc[r][6]), f7 = unpack2(acc[r][7]);
        *(float4*)(pb + (size_t)mA*CD + c0)     = make_float4(f0.x, f1.x, f2.x, f3.x);
        *(float4*)(pb + (size_t)mA*CD + c0 + 4) = make_float4(f4.x, f5.x, f6.x, f7.x);
        *(float4*)(pb + (size_t)mB*CD + c0)     = make_float4(f0.y, f1.y, f2.y, f3.y);
        *(float4*)(pb + (size_t)mB*CD + c0 + 4) = make_float4(f4.y, f5.y, f6.y, f7.y);
    }
}

template<int SPLIT>
__global__ void reduce_split(Job j0, Job j1) {
    int idx = blockIdx.x * 256 + threadIdx.x;      // over 2 * 2^19
    int job = idx >> 19, r = idx & ((1<<19) - 1);
    Job jb = job ? j1 : j0;
    float s = 0.f;
    #pragma unroll
    for (int sp = 0; sp < SPLIT; sp++)
        s += g_part[((size_t)(sp*2 + job) << 19) + r];
    if (jb.bias) s += jb.bias[r & 127];
    if (jb.res)  s += jb.res[r];
    jb.out[r] = s;
}

// ---------- small conv (KS=1 paths: v/r3 pair and proj) ----------
__global__ void conv_gemm_small(Job j0, Job j1) {
    constexpr int K = CD;
    constexpr int NIT = K / 16;
    Job jb = (blockIdx.z == 0) ? j0 : j1;
    const int m0 = blockIdx.y << 6, n0 = blockIdx.x << 6;
    __shared__ float As[2][16][64], Bs[2][16][64];
    const int tid = threadIdx.x;
    const int am = tid & 63, kgA = tid >> 6;
    const int gm = m0 + am;
    const int br = tid >> 4, bc = (tid & 15) << 2;
    const int ty = tid >> 4, tx = tid & 15;
    u64 acc[4][4];
    #pragma unroll
    for (int r = 0; r < 4; r++)
        #pragma unroll
        for (int c = 0; c < 4; c++) acc[r][c] = 0ull;

    auto ldA = [&](int kgabs) -> float4 {
        int ci = (kgabs << 2) & 127;
        return *(const float4*)(jb.in + ((size_t)gm << 7) + ci);
    };
    {
        float4 a0 = ldA(kgA), a1 = ldA(kgA + 2);
        float4 b0 = *(const float4*)(jb.wt + (size_t)br*CD + n0 + bc);
        float4 b1 = *(const float4*)(jb.wt + (size_t)(br+8)*CD + n0 + bc);
        int k4 = kgA << 2;
        As[0][k4+0][am]=a0.x; As[0][k4+1][am]=a0.y; As[0][k4+2][am]=a0.z; As[0][k4+3][am]=a0.w;
        As[0][k4+8][am]=a1.x; As[0][k4+9][am]=a1.y; As[0][k4+10][am]=a1.z; As[0][k4+11][am]=a1.w;
        *(float4*)&Bs[0][br][bc]   = b0;
        *(float4*)&Bs[0][br+8][bc] = b1;
    }
    __syncthreads();

    for (int it = 0; it < NIT; it++) {
        int s = it & 1;
        float4 na0, na1, nb0, nb1;
        bool more = (it + 1 < NIT);
        if (more) {
            int kg = (it+1)*4;
            na0 = ldA(kg + kgA); na1 = ldA(kg + kgA + 2);
            nb0 = *(const float4*)(jb.wt + (size_t)((it+1)*16 + br)*CD + n0 + bc);
            nb1 = *(const float4*)(jb.wt + (size_t)((it+1)*16 + br + 8)*CD + n0 + bc);
        }
        #pragma unroll
        for (int kk = 0; kk < 16; kk++) {
            F4U u0, u1;
            u0.f = *(const float4*)&As[s][kk][ty << 3];
            u1.f = *(const float4*)(&As[s][kk][ty << 3] + 4);
            u64 ap[4] = {u0.u[0], u0.u[1], u1.u[0], u1.u[1]};
            float4 bq = *(const float4*)&Bs[s][kk][tx << 2];
            u64 b0 = pack2(bq.x, bq.x), b1 = pack2(bq.y, bq.y);
            u64 b2 = pack2(bq.z, bq.z), b3 = pack2(bq.w, bq.w);
            #pragma unroll
            for (int r = 0; r < 4; r++) {
                fma2(acc[r][0], ap[r], b0);
                fma2(acc[r][1], ap[r], b1);
                fma2(acc[r][2], ap[r], b2);
                fma2(acc[r][3], ap[r], b3);
            }
        }
        if (more) {
            int so = s ^ 1, k4 = kgA << 2;
            As[so][k4+0][am]=na0.x; As[so][k4+1][am]=na0.y; As[so][k4+2][am]=na0.z; As[so][k4+3][am]=na0.w;
            As[so][k4+8][am]=na1.x; As[so][k4+9][am]=na1.y; As[so][k4+10][am]=na1.z; As[so][k4+11][am]=na1.w;
            *(float4*)&Bs[so][br][bc]   = nb0;
            *(float4*)&Bs[so][br+8][bc] = nb1;
            __syncthreads();
        }
    }

    int c0 = n0 + (tx << 2);
    float4 bias4 = make_float4(0.f,0.f,0.f,0.f);
    if (jb.bias) bias4 = *(const float4*)(jb.bias + c0);
    #pragma unroll
    for (int rp = 0; rp < 4; rp++) {
        float2 p0 = unpack2(acc[rp][0]), p1 = unpack2(acc[rp][1]);
        float2 p2 = unpack2(acc[rp][2]), p3 = unpack2(acc[rp][3]);
        int mA = m0 + (ty << 3) + (rp << 1), mB = mA + 1;
        float4 oA = make_float4(p0.x+bias4.x, p1.x+bias4.y, p2.x+bias4.z, p3.x+bias4.w);
        float4 oB = make_float4(p0.y+bias4.x, p1.y+bias4.y, p2.y+bias4.z, p3.y+bias4.w);
        if (jb.res) {
            float4 rA = *(const float4*)(jb.res + (size_t)mA*CD + c0);
            float4 rB = *(const float4*)(jb.res + (size_t)mB*CD + c0);
            oA.x += rA.x; oA.y += rA.y; oA.z += rA.z; oA.w += rA.w;
            oB.x += rB.x; oB.y += rB.y; oB.z += rB.z; oB.w += rB.w;
        }
        *(float4*)(jb.out + (size_t)mA*CD + c0) = oA;
        *(float4*)(jb.out + (size_t)mB*CD + c0) = oB;
    }
}

// ---------- flash: 128 thr, 4 warps * 16 rows; padded smem; 32-col score chunks ----------
__global__ void flash_kernel(const float* __restrict__ q, const float* __restrict__ k,
                             const float* __restrict__ v, float* __restrict__ out) {
    const float LOG2E = 1.4426950408889634f;
    int bh = blockIdx.y, b = bh >> 3, h = bh & 7;
    int qbase = blockIdx.x << 6;
    __shared__ float4 ks[128][5], vs[128][5];   // 80B row stride: conflict-free
    int tid = threadIdx.x, wid = tid >> 5, lane = tid & 31;
    int r = lane >> 2, g = lane & 3;
    int rowA = qbase + (wid << 4) + r, rowB = rowA + 8;
    const float* qpA = q + (((b<<11) + rowA) << 7) + (h << 4);
    const float* qpB = q + (((b<<11) + rowB) << 7) + (h << 4);
    u64 qa[8], qb2[8];
    #pragma unroll
    for (int j = 0; j < 4; j++) {
        float4 ta = *(const float4*)(qpA + j*4);
        float4 tb = *(const float4*)(qpB + j*4);
        qa[j*2]   = pack2(ta.x*LOG2E, ta.y*LOG2E);
        qa[j*2+1] = pack2(ta.z*LOG2E, ta.w*LOG2E);
        qb2[j*2]   = pack2(tb.x*LOG2E, tb.y*LOG2E);
        qb2[j*2+1] = pack2(tb.z*LOG2E, tb.w*LOG2E);
    }
    u64 accA[8], accB[8];
    #pragma unroll
    for (int d = 0; d < 8; d++) { accA[d] = 0ull; accB[d] = 0ull; }
    float mA = -1e30f, mB = -1e30f, lsA = 0.f, lsB = 0.f;
    const float* kbase = k + (((size_t)b << 11) << 7) + (h << 4);
    const float* vbase = v + (((size_t)b << 11) << 7) + (h << 4);

    for (int kt = 0; kt < 2048; kt += 128) {
        __syncthreads();
        #pragma unroll
        for (int u = 0; u < 4; u++) {
            int li = tid + (u << 7);
            int row = li >> 2, j = li & 3;
            ks[row][j] = *(const float4*)(kbase + (size_t)(kt+row)*CD + (j<<2));
            vs[row][j] = *(const float4*)(vbase + (size_t)(kt+row)*CD + (j<<2));
        }
        __syncthreads();
        #pragma unroll
        for (int ch = 0; ch < 4; ch++) {
            float sA[8], sB[8];
            float tmA = -1e30f, tmB = -1e30f;
            #pragma unroll
            for (int i = 0; i < 8; i++) {
                int kc = (ch << 5) + (i << 2) + g;
                F4U k0, k1, k2, k3;
                k0.f = ks[kc][0]; k1.f = ks[kc][1]; k2.f = ks[kc][2]; k3.f = ks[kc][3];
                u64 dA = 0ull, dB = 0ull;
                fma2(dA, qa[0], k0.u[0]); fma2(dA, qa[1], k0.u[1]);
                fma2(dA, qa[2], k1.u[0]); fma2(dA, qa[3], k1.u[1]);
                fma2(dA, qa[4], k2.u[0]); fma2(dA, qa[5], k2.u[1]);
                fma2(dA, qa[6], k3.u[0]); fma2(dA, qa[7], k3.u[1]);
                fma2(dB, qb2[0], k0.u[0]); fma2(dB, qb2[1], k0.u[1]);
                fma2(dB, qb2[2], k1.u[0]); fma2(dB, qb2[3], k1.u[1]);
                fma2(dB, qb2[4], k2.u[0]); fma2(dB, qb2[5], k2.u[1]);
                fma2(dB, qb2[6], k3.u[0]); fma2(dB, qb2[7], k3.u[1]);
                float2 fa = unpack2(dA), fb = unpack2(dB);
                sA[i] = fa.x + fa.y; sB[i] = fb.x + fb.y;
                tmA = fmaxf(tmA, sA[i]); tmB = fmaxf(tmB, sB[i]);
            }
            tmA = fmaxf(tmA, __shfl_xor_sync(~0u, tmA, 1));
            tmA = fmaxf(tmA, __shfl_xor_sync(~0u, tmA, 2));
            tmB = fmaxf(tmB, __shfl_xor_sync(~0u, tmB, 1));
            tmB = fmaxf(tmB, __shfl_xor_sync(~0u, tmB, 2));
            float nA = fmaxf(mA, tmA), nB = fmaxf(mB, tmB);
            float cA = exp2f(mA - nA), cB = exp2f(mB - nB);
            mA = nA; mB = nB; lsA *= cA; lsB *= cB;
            u64 cA2 = pack2(cA, cA), cB2 = pack2(cB, cB);
            #pragma unroll
            for (int d = 0; d < 8; d++) { mul2(accA[d], cA2); mul2(accB[d], cB2); }
            #pragma unroll
            for (int i = 0; i < 8; i++) {
                int kc = (ch << 5) + (i << 2) + g;
                float pA = exp2f(sA[i] - mA), pB = exp2f(sB[i] - mB);
                lsA += pA; lsB += pB;
                u64 pA2 = pack2(pA, pA), pB2 = pack2(pB, pB);
                F4U v0, v1, v2, v3;
                v0.f = vs[kc][0]; v1.f = vs[kc][1]; v2.f = vs[kc][2]; v3.f = vs[kc][3];
                fma2(accA[0], pA2, v0.u[0]); fma2(accA[1], pA2, v0.u[1]);
                fma2(accA[2], pA2, v1.u[0]); fma2(accA[3], pA2, v1.u[1]);
                fma2(accA[4], pA2, v2.u[0]); fma2(accA[5], pA2, v2.u[1]);
                fma2(accA[6], pA2, v3.u[0]); fma2(accA[7], pA2, v3.u[1]);
                fma2(accB[0], pB2, v0.u[0]); fma2(accB[1], pB2, v0.u[1]);
                fma2(accB[2], pB2, v1.u[0]); fma2(accB[3], pB2, v1.u[1]);
                fma2(accB[4], pB2, v2.u[0]); fma2(accB[5], pB2, v2.u[1]);
                fma2(accB[6], pB2, v3.u[0]); fma2(accB[7], pB2, v3.u[1]);
            }
        }
    }
    float aA[16], aB[16];
    #pragma unroll
    for (int d = 0; d < 8; d++) {
        float2 fa = unpack2(accA[d]), fb = unpack2(accB[d]);
        aA[d*2] = fa.x; aA[d*2+1] = fa.y;
        aB[d*2] = fb.x; aB[d*2+1] = fb.y;
    }
    #pragma unroll
    for (int d = 0; d < 16; d++) {
        aA[d] += __shfl_xor_sync(~0u, aA[d], 1);
        aA[d] += __shfl_xor_sync(~0u, aA[d], 2);
        aB[d] += __shfl_xor_sync(~0u, aB[d], 1);
        aB[d] += __shfl_xor_sync(~0u, aB[d], 2);
    }
    lsA += __shfl_xor_sync(~0u, lsA, 1); lsA += __shfl_xor_sync(~0u, lsA, 2);
    lsB += __shfl_xor_sync(~0u, lsB, 1); lsB += __shfl_xor_sync(~0u, lsB, 2);
    float invA = 1.0f / lsA, invB = 1.0f / lsB;
    #pragma unroll
    for (int rr = 0; rr < 2; rr++) {
        int qrow = rr ? rowB : rowA;
        float inv = rr ? invB : invA;
        float* ac = rr ? aB : aA;
        size_t base = ((size_t)((b<<11) + qrow) << 7) + (h << 4);
        float ov[4];
        #pragma unroll
        for (int u = 0; u < 4; u++) {
            int w2 = (g << 2) + u;
            float ca = 0.f;
            #pragma unroll
            for (int s2 = 0; s2 < 3; s2++) {
                int f = w2 + (s2 << 4);
                int sel = f % 3;
                const float* tp = (sel == 0) ? q : ((sel == 1) ? k : v);
                ca += tp[base + f/3];
            }
            ov[u] = ac[(g<<2)+u]*inv + ca*(1.0f/3.0f);
        }
        *(float4*)(out + base + (g << 2)) = make_float4(ov[0], ov[1], ov[2], ov[3]);
    }
}

__global__ void combine_ln(const float* __restrict__ a1, const float* __restrict__ a2,
                           const float* __restrict__ a3, const float* __restrict__ hh,
                           const float* __restrict__ gam, const float* __restrict__ bet,
                           float* __restrict__ x2, float* __restrict__ y2,
                           float* __restrict__ xm) {
    int m = blockIdx.x, c = threadIdx.x, lane = c & 31, wid = c >> 5;
    float sacc = 0.f;
    #pragma unroll
    for (int s2 = 0; s2 < 3; s2++) {
        int f = c*3 + s2;
        const float* ap = (f >> 7) == 0 ? a1 : ((f >> 7) == 1 ? a2 : a3);
        sacc += ap[(m << 7) + (f & 127)];
    }
    float v = sacc*(1.0f/3.0f) + hh[m*CD + c];
    x2[m*CD + c] = v;
    float s = v, sq = v*v;
    #pragma unroll
    for (int o = 16; o > 0; o >>= 1) { s += __shfl_xor_sync(~0u, s, o); sq += __shfl_xor_sync(~0u, sq, o); }
    __shared__ float ss[4], sqq[4], ys[4];
    if (lane == 0) { ss[wid] = s; sqq[wid] = sq; }
    __syncthreads();
    float S = ss[0]+ss[1]+ss[2]+ss[3], SQ = sqq[0]+sqq[1]+sqq[2]+sqq[3];
    float mean = S*(1.0f/CD), var = SQ*(1.0f/CD) - mean*mean, rs = rsqrtf(var + 1e-6f);
    float y = (v - mean)*rs*gam[c] + bet[c];
    y2[m*CD + c] = y;
    float t = y;
    #pragma unroll
    for (int o = 16; o > 0; o >>= 1) t += __shfl_xor_sync(~0u, t, o);
    if (lane == 0) ys[wid] = t;
    __syncthreads();
    if (c == 0) xm[m] = (ys[0]+ys[1]+ys[2]+ys[3])*(1.0f/CD);
}

__global__ void final_kernel(const float* __restrict__ x2, const float* __restrict__ y2,
                             const float* __restrict__ xm, const float* __restrict__ st1,
                             const float* __restrict__ st2, const float* __restrict__ st3,
                             float* __restrict__ out) {
    int m = blockIdx.x, b = m >> 11, p = m & 2047;
    int t = p >> 4, ii = (p >> 2) & 3, jj = p & 3;
    __shared__ float sg;
    if (threadIdx.x == 0) {
        float gg = st1[0] * xm[m];
        #pragma unroll
        for (int kd = 0; kd < 2; kd++)
        for (int kh = 0; kh < 2; kh++)
        for (int kw = 0; kw < 2; kw++) {
            int t2 = t + kd - 1, i2 = ii + kh - 1, j2 = jj + kw - 1;
            if ((unsigned)t2 < 128u && (unsigned)i2 < 4u && (unsigned)j2 < 4u)
                gg += st2[kd*4 + kh*2 + kw] * xm[(b<<11) + (t2<<4) + (i2<<2) + j2];
        }
        #pragma unroll
        for (int kd = 0; kd < 3; kd++)
        for (int kh = 0; kh < 3; kh++)
        for (int kw = 0; kw < 3; kw++) {
            int t2 = t + kd - 1, i2 = ii + kh - 1, j2 = jj + kw - 1;
            if ((unsigned)t2 < 128u && (unsigned)i2 < 4u && (unsigned)j2 < 4u)
                gg += st3[kd*9 + kh*3 + kw] * xm[(b<<11) + (t2<<4) + (i2<<2) + j2];
        }
        sg = 1.0f / (1.0f + __expf(-gg));
    }
    __syncthreads();
    int idx = m*CD + threadIdx.x;
    out[idx] = x2[idx] + y2[idx]*sg;
}

extern "C" void kernel_launch(void* const* d_in, const int* in_sizes, int n_in,
                              void* d_out, int out_size) {
    const float* x      = (const float*)d_in[0];
    const float* n1g    = (const float*)d_in[1];
    const float* n1b    = (const float*)d_in[2];
    const float* q_w    = (const float*)d_in[3];
    const float* qbg    = (const float*)d_in[4];
    const float* qbb    = (const float*)d_in[5];
    const float* k_w    = (const float*)d_in[6];
    const float* kbg    = (const float*)d_in[7];
    const float* kbb    = (const float*)d_in[8];
    const float* v_w    = (const float*)d_in[9];
    const float* proj_w = (const float*)d_in[10];
    const float* proj_b = (const float*)d_in[11];
    const float* r1_w   = (const float*)d_in[12];
    const float* r2_w   = (const float*)d_in[13];
    const float* r3_w   = (const float*)d_in[14];
    const float* n2g    = (const float*)d_in[15];
    const float* n2b    = (const float*)d_in[16];
    const float* st1    = (const float*)d_in[17];
    const float* st2    = (const float*)d_in[18];
    const float* st3    = (const float*)d_in[19];
    float* out = (float*)d_out;

    float *y1,*qb,*kb,*vb,*attn,*hb,*a1,*a2,*a3,*x2,*y2,*xm;
    float *wq,*wk,*wv,*wr1,*wr2,*wr3,*wp,*bnst;
    cudaGetSymbolAddress((void**)&y1, g_y1);     cudaGetSymbolAddress((void**)&qb, g_qb);
    cudaGetSymbolAddress((void**)&kb, g_kb);     cudaGetSymbolAddress((void**)&vb, g_vb);
    cudaGetSymbolAddress((void**)&attn, g_attn); cudaGetSymbolAddress((void**)&hb, g_hb);
    cudaGetSymbolAddress((void**)&a1, g_a1);     cudaGetSymbolAddress((void**)&a2, g_a2);
    cudaGetSymbolAddress((void**)&a3, g_a3);     cudaGetSymbolAddress((void**)&x2, g_x2);
    cudaGetSymbolAddress((void**)&y2, g_y2);     cudaGetSymbolAddress((void**)&xm, g_xm);
    cudaGetSymbolAddress((void**)&wq, g_wq);     cudaGetSymbolAddress((void**)&wk, g_wk);
    cudaGetSymbolAddress((void**)&wv, g_wv);     cudaGetSymbolAddress((void**)&wr1, g_wr1);
    cudaGetSymbolAddress((void**)&wr2, g_wr2);   cudaGetSymbolAddress((void**)&wr3, g_wr3);
    cudaGetSymbolAddress((void**)&wp, g_wp);     cudaGetSymbolAddress((void**)&bnst, g_bnst);

    auto cdiv = [](int a, int b){ return (a + b - 1) / b; };
    const int n27 = 27*CD*CD, n8 = 8*CD*CD, n1 = CD*CD;

    WJobs wa = {};
    wa.nj = 2;
    wa.src[0]=q_w;  wa.dst[0]=wq;  wa.KK[0]=27; wa.n[0]=n27;
    wa.src[1]=r1_w; wa.dst[1]=wr1; wa.KK[1]=27; wa.n[1]=n27;
    WJobs wb = {};
    wb.nj = 5;
    wb.src[0]=k_w;   wb.dst[0]=wk;  wb.KK[0]=8; wb.n[0]=n8;
    wb.src[1]=r2_w;  wb.dst[1]=wr2; wb.KK[1]=8; wb.n[1]=n8;
    wb.src[2]=v_w;   wb.dst[2]=wv;  wb.KK[2]=1; wb.n[2]=n1;
    wb.src[3]=r3_w;  wb.dst[3]=wr3; wb.KK[3]=1; wb.n[3]=n1;
    wb.src[4]=proj_w;wb.dst[4]=wp;  wb.KK[4]=1; wb.n[4]=n1;

    wtrans_multi<<<cdiv(2*n27,256),256>>>(wa, bnst, 2*2*CD);
    wtrans_multi<<<cdiv(2*n8+3*n1,256),256>>>(wb, nullptr, 0);
    ln_kernel<<<MTOT, 128>>>(x, y1, n1g, n1b, nullptr, 1e-6f);

    Job jq  = { y1, wq,  nullptr, nullptr, qb };
    Job jr1 = { x,  wr1, x,       nullptr, a1 };
    conv_gemm_big<3,9><<<dim3(32,9,2), 256>>>(jq, jr1);
    reduce_split<9><<<MTOT*CD*2/256, 256>>>(jq, jr1);

    Job jk  = { y1, wk,  nullptr, nullptr, kb };
    Job jr2 = { a1, wr2, a1,      nullptr, a2 };
    conv_gemm_big<2,4><<<dim3(32,4,2), 256>>>(jk, jr2);
    reduce_split<4><<<MTOT*CD*2/256, 256>>>(jk, jr2);

    bn_stats<<<dim3(32,2), 256>>>(qb, kb);
    bn_apply<<<dim3(MTOT*CD/256,2), 256>>>(qb, kb, qbg, qbb, kbg, kbb);

    Job jv  = { y1, wv,  nullptr, nullptr, vb };
    Job jr3 = { a2, wr3, a2,      nullptr, a3 };
    conv_gemm_small<<<dim3(2,64,2), 128>>>(jv, jr3);

    flash_kernel<<<dim3(32,16), 128>>>(qb, kb, vb, attn);

    Job jp = { attn, wp, nullptr, proj_b, hb };
    conv_gemm_small<<<dim3(2,64,1), 128>>>(jp, jp);

    combine_ln<<<MTOT, 128>>>(a1, a2, a3, hb, n2g, n2b, x2, y2, xm);
    final_kernel<<<MTOT, 128>>>(x2, y2, xm, st1, st2, st3, out);
}

// round 7
// speedup vs baseline: 2.0013x; 1.0023x over previous
#include <cuda_runtime.h>
#include <math.h>

#define CD 128
#define MTOT 4096

typedef unsigned long long u64;

__device__ __forceinline__ u64 pack2(float lo, float hi) {
    u64 r; asm("mov.b64 %0,{%1,%2};" : "=l"(r) : "f"(lo), "f"(hi)); return r;
}
__device__ __forceinline__ void fma2(u64& d, u64 a, u64 b) {
    asm("fma.rn.f32x2 %0,%1,%2,%0;" : "+l"(d) : "l"(a), "l"(b));
}
__device__ __forceinline__ void mul2(u64& d, u64 a) {
    asm("mul.rn.f32x2 %0,%0,%1;" : "+l"(d) : "l"(a));
}
__device__ __forceinline__ float2 unpack2(u64 v) {
    float2 f; asm("mov.b64 {%0,%1},%2;" : "=f"(f.x), "=f"(f.y) : "l"(v)); return f;
}

union F4U { float4 f; u64 u[2]; };

struct Job  { const float* in; const float* wt; const float* res; const float* bias; float* out; };
struct WJobs { const float* src[5]; float* dst[5]; int KK[5]; int n[5]; int nj; };

__device__ float g_y1[MTOT*CD], g_qb[MTOT*CD], g_kb[MTOT*CD], g_vb[MTOT*CD];
__device__ float g_attn[MTOT*CD], g_hb[MTOT*CD], g_a1[MTOT*CD], g_a2[MTOT*CD], g_a3[MTOT*CD];
__device__ float g_x2[MTOT*CD], g_y2[MTOT*CD], g_xm[MTOT];
__device__ float g_wq[27*CD*CD], g_wk[8*CD*CD], g_wv[CD*CD];
__device__ float g_wr1[27*CD*CD], g_wr2[8*CD*CD], g_wr3[CD*CD], g_wp[CD*CD];
__device__ float g_bnst[2][2][CD];
__device__ float g_part[9*2*MTOT*CD];   // split-K partials: [split][job][m][c]

__global__ void wtrans_multi(WJobs J, float* zbuf, int zn) {
    int idx = blockIdx.x * 256 + threadIdx.x;
    if (zbuf && idx < zn) zbuf[idx] = 0.f;
    int base = 0;
    #pragma unroll
    for (int j = 0; j < 5; j++) {
        if (j >= J.nj) return;
        if (idx < base + J.n[j]) {
            int t = idx - base;
            int tap = t / (CD*CD); int rem = t - tap*(CD*CD);
            int ci = rem >> 7, co = rem & 127;
            J.dst[j][t] = J.src[j][(co*CD + ci)*J.KK[j] + tap];
            return;
        }
        base += J.n[j];
    }
}

__global__ void ln_kernel(const float* __restrict__ in, float* __restrict__ out,
                          const float* __restrict__ gam, const float* __restrict__ bet,
                          float* __restrict__ xm, float eps) {
    int m = blockIdx.x, c = threadIdx.x, lane = c & 31, wid = c >> 5;
    float v = in[m*CD + c], s = v, sq = v*v;
    #pragma unroll
    for (int o = 16; o > 0; o >>= 1) { s += __shfl_xor_sync(~0u, s, o); sq += __shfl_xor_sync(~0u, sq, o); }
    __shared__ float ss[4], sqq[4], ys[4];
    if (lane == 0) { ss[wid] = s; sqq[wid] = sq; }
    __syncthreads();
    float S = ss[0]+ss[1]+ss[2]+ss[3], SQ = sqq[0]+sqq[1]+sqq[2]+sqq[3];
    float mean = S*(1.0f/CD), var = SQ*(1.0f/CD) - mean*mean, rs = rsqrtf(var + eps);
    float y = (v - mean)*rs*gam[c] + bet[c];
    out[m*CD + c] = y;
    if (xm) {
        float t = y;
        #pragma unroll
        for (int o = 16; o > 0; o >>= 1) t += __shfl_xor_sync(~0u, t, o);
        if (lane == 0) ys[wid] = t;
        __syncthreads();
        if (c == 0) xm[m] = (ys[0]+ys[1]+ys[2]+ys[3])*(1.0f/CD);
    }
}

__global__ void bn_stats(const float* __restrict__ q, const float* __restrict__ k) {
    int buf = blockIdx.y;
    const float* src = buf ? k : q;
    int tid = threadIdx.x;
    int base = blockIdx.x * 128;
    float s = 0.f, sq = 0.f;
    for (int i = tid; i < 128*CD; i += 256) {
        float v = src[(base + (i >> 7))*CD + (i & 127)];
        s += v; sq += v*v;
    }
    __shared__ float sh[256];
    sh[tid] = s; __syncthreads();
    if (tid < 128) atomicAdd(&g_bnst[buf][0][tid], sh[tid] + sh[tid+128]);
    __syncthreads();
    sh[tid] = sq; __syncthreads();
    if (tid < 128) atomicAdd(&g_bnst[buf][1][tid], sh[tid] + sh[tid+128]);
}

__global__ void bn_apply(float* __restrict__ q, float* __restrict__ k,
                         const float* __restrict__ qg, const float* __restrict__ qb2,
                         const float* __restrict__ kg, const float* __restrict__ kb2) {
    int buf = blockIdx.y;
    float* dst = buf ? k : q;
    const float* gam = buf ? kg : qg;
    const float* bet = buf ? kb2 : qb2;
    int idx = blockIdx.x * 256 + threadIdx.x;
    int c = idx & 127;
    float S = g_bnst[buf][0][c], SQ = g_bnst[buf][1][c];
    float mean = S*(1.0f/MTOT), var = SQ*(1.0f/MTOT) - mean*mean;
    float sc = gam[c]*rsqrtf(var + 1e-5f), sh = bet[c] - mean*sc;
    dst[idx] = dst[idx]*sc + sh;
}

// ---------- big conv: BM=128 BN=128 BK=16, 256 thr, warp-tiled 8x4, split-K ----------
template<int KS, int SPLIT>
__global__ __launch_bounds__(256) void conv_gemm_big(Job j0, Job j1) {
    constexpr int K = KS*KS*KS*CD;
    constexpr int KSP = K / SPLIT;
    constexpr int NIT = KSP / 16;
    const int job = blockIdx.z, split = blockIdx.y;
    Job jb = job ? j1 : j0;
    const int m0 = blockIdx.x << 7;
    const int kbase = split * KSP;
    __shared__ float As[2][16][128];
    __shared__ float Bs[2][16][128];
    const int tid = threadIdx.x;
    const int am = tid & 127, kg = tid >> 7;           // A loader: k-groups kg, kg+2
    const int gm = m0 + am, bb = gm >> 11, p = gm & 2047;
    const int tt = p >> 4, ii = (p >> 2) & 3, jj = p & 3;
    const int br = tid >> 5, bc = (tid & 31) << 2;     // B loader: rows br, br+8
    const int warp = tid >> 5, lane = tid & 31;
    // warp-tiled compute map: warp covers 8 ty x 4 tx -> A 8-way spread, B 8-way broadcast
    const int ty = ((warp >> 2) << 3) + (lane >> 2);   // 0..15
    const int tx = ((warp & 3) << 2) + (lane & 3);     // 0..15
    u64 acc[4][8];
    #pragma unroll
    for (int r = 0; r < 4; r++)
        #pragma unroll
        for (int u = 0; u < 8; u++) acc[r][u] = 0ull;

    auto ldA = [&](int kgabs) -> float4 {
        int tap = kgabs >> 5;
        int ci = (kgabs << 2) & 127;
        int dt, di, dj;
        if (KS == 3) { dt = tap/9 - 1; int r9 = tap%9; di = r9/3 - 1; dj = r9%3 - 1; }
        else { dt = (tap>>2) - 1; di = ((tap>>1)&1) - 1; dj = (tap&1) - 1; }
        int t2 = tt + dt, i2 = ii + di, j2 = jj + dj;
        if ((unsigned)t2 < 128u && (unsigned)i2 < 4u && (unsigned)j2 < 4u)
            return *(const float4*)(jb.in + (((bb<<11) + (t2<<4) + (i2<<2) + j2) << 7) + ci);
        return make_float4(0.f,0.f,0.f,0.f);
    };

    {   // prologue stage 0
        int kg4 = kbase >> 2;
        float4 a0 = ldA(kg4 + kg), a1 = ldA(kg4 + kg + 2);
        float4 b0 = *(const float4*)(jb.wt + (size_t)(kbase + br)*CD + bc);
        float4 b1 = *(const float4*)(jb.wt + (size_t)(kbase + br + 8)*CD + bc);
        int k4 = kg << 2;
        As[0][k4+0][am]=a0.x; As[0][k4+1][am]=a0.y; As[0][k4+2][am]=a0.z; As[0][k4+3][am]=a0.w;
        As[0][k4+8][am]=a1.x; As[0][k4+9][am]=a1.y; As[0][k4+10][am]=a1.z; As[0][k4+11][am]=a1.w;
        *(float4*)&Bs[0][br][bc]   = b0;
        *(float4*)&Bs[0][br+8][bc] = b1;
    }
    __syncthreads();

    for (int it = 0; it < NIT; it++) {
        int s = it & 1;
        float4 na0, na1, nb0, nb1;
        bool more = (it + 1 < NIT);
        if (more) {
            int kofs = kbase + (it+1)*16;
            na0 = ldA((kofs>>2) + kg); na1 = ldA((kofs>>2) + kg + 2);
            nb0 = *(const float4*)(jb.wt + (size_t)(kofs + br)*CD + bc);
            nb1 = *(const float4*)(jb.wt + (size_t)(kofs + br + 8)*CD + bc);
        }
        #pragma unroll
        for (int kk = 0; kk < 16; kk++) {
            F4U a0, a1;
            a0.f = *(const float4*)&As[s][kk][ty << 3];
            a1.f = *(const float4*)(&As[s][kk][ty << 3] + 4);
            u64 ap[4] = {a0.u[0], a0.u[1], a1.u[0], a1.u[1]};
            float4 b0 = *(const float4*)&Bs[s][kk][tx << 3];
            float4 b1 = *(const float4*)(&Bs[s][kk][tx << 3] + 4);
            u64 bp[8];
            bp[0] = pack2(b0.x, b0.x); bp[1] = pack2(b0.y, b0.y);
            bp[2] = pack2(b0.z, b0.z); bp[3] = pack2(b0.w, b0.w);
            bp[4] = pack2(b1.x, b1.x); bp[5] = pack2(b1.y, b1.y);
            bp[6] = pack2(b1.z, b1.z); bp[7] = pack2(b1.w, b1.w);
            #pragma unroll
            for (int r = 0; r < 4; r++)
                #pragma unroll
                for (int u = 0; u < 8; u++)
                    fma2(acc[r][u], ap[r], bp[u]);
        }
        if (more) {
            int so = s ^ 1, k4 = kg << 2;
            As[so][k4+0][am]=na0.x; As[so][k4+1][am]=na0.y; As[so][k4+2][am]=na0.z; As[so][k4+3][am]=na0.w;
            As[so][k4+8][am]=na1.x; As[so][k4+9][am]=na1.y; As[so][k4+10][am]=na1.z; As[so][k4+11][am]=na1.w;
            *(float4*)&Bs[so][br][bc]   = nb0;
            *(float4*)&Bs[so][br+8][bc] = nb1;
            __syncthreads();
        }
    }

    float* pb = g_part + ((size_t)(split*2 + job) << 19);
    int c0 = tx << 3;
    #pragma unroll
    for (int r = 0; r < 4; r++) {
        int mA = m0 + (ty<<3) + (r<<1), mB = mA + 1;
        float2 f0 = unpack2(acc[r][0]), f1 = unpack2(acc[r][1]);
        float2 f2 = unpack2(acc[r][2]), f3 = unpack2(acc[r][3]);
        float2 f4 = unpack2(acc[r][4]), f5 = unpack2(acc[r][5]);
        float2 f6 = unpack2(acc[r][6]), f7 = unpack2(acc[r][7]);
        *(float4*)(pb + (size_t)mA*CD + c0)     = make_float4(f0.x, f1.x, f2.x, f3.x);
        *(float4*)(pb + (size_t)mA*CD + c0 + 4) = make_float4(f4.x, f5.x, f6.x, f7.x);
        *(float4*)(pb + (size_t)mB*CD + c0)     = make_float4(f0.y, f1.y, f2.y, f3.y);
        *(float4*)(pb + (size_t)mB*CD + c0 + 4) = make_float4(f4.y, f5.y, f6.y, f7.y);
    }
}

template<int SPLIT>
__global__ void reduce_split(Job j0, Job j1) {
    int idx = blockIdx.x * 256 + threadIdx.x;      // over 2 * 2^19
    int job = idx >> 19, r = idx & ((1<<19) - 1);
    Job jb = job ? j1 : j0;
    float s = 0.f;
    #pragma unroll
    for (int sp = 0; sp < SPLIT; sp++)
        s += g_part[((size_t)(sp*2 + job) << 19) + r];
    if (jb.bias) s += jb.bias[r & 127];
    if (jb.res)  s += jb.res[r];
    jb.out[r] = s;
}

// ---------- small conv (KS=1 paths): warp-tiled 8x4 map ----------
__global__ void conv_gemm_small(Job j0, Job j1) {
    constexpr int K = CD;
    constexpr int NIT = K / 16;
    Job jb = (blockIdx.z == 0) ? j0 : j1;
    const int m0 = blockIdx.y << 6, n0 = blockIdx.x << 6;
    __shared__ float As[2][16][64], Bs[2][16][64];
    const int tid = threadIdx.x;
    const int am = tid & 63, kgA = tid >> 6;
    const int gm = m0 + am;
    const int br = tid >> 4, bc = (tid & 15) << 2;
    const int warp = tid >> 5, lane = tid & 31;
    const int ty = lane >> 2;                       // 0..7 (all within warp)
    const int tx = (warp << 2) + (lane & 3);        // 0..15
    u64 acc[4][4];
    #pragma unroll
    for (int r = 0; r < 4; r++)
        #pragma unroll
        for (int c = 0; c < 4; c++) acc[r][c] = 0ull;

    auto ldA = [&](int kgabs) -> float4 {
        int ci = (kgabs << 2) & 127;
        return *(const float4*)(jb.in + ((size_t)gm << 7) + ci);
    };
    {
        float4 a0 = ldA(kgA), a1 = ldA(kgA + 2);
        float4 b0 = *(const float4*)(jb.wt + (size_t)br*CD + n0 + bc);
        float4 b1 = *(const float4*)(jb.wt + (size_t)(br+8)*CD + n0 + bc);
        int k4 = kgA << 2;
        As[0][k4+0][am]=a0.x; As[0][k4+1][am]=a0.y; As[0][k4+2][am]=a0.z; As[0][k4+3][am]=a0.w;
        As[0][k4+8][am]=a1.x; As[0][k4+9][am]=a1.y; As[0][k4+10][am]=a1.z; As[0][k4+11][am]=a1.w;
        *(float4*)&Bs[0][br][bc]   = b0;
        *(float4*)&Bs[0][br+8][bc] = b1;
    }
    __syncthreads();

    for (int it = 0; it < NIT; it++) {
        int s = it & 1;
        float4 na0, na1, nb0, nb1;
        bool more = (it + 1 < NIT);
        if (more) {
            int kg = (it+1)*4;
            na0 = ldA(kg + kgA); na1 = ldA(kg + kgA + 2);
            nb0 = *(const float4*)(jb.wt + (size_t)((it+1)*16 + br)*CD + n0 + bc);
            nb1 = *(const float4*)(jb.wt + (size_t)((it+1)*16 + br + 8)*CD + n0 + bc);
        }
        #pragma unroll
        for (int kk = 0; kk < 16; kk++) {
            F4U u0, u1;
            u0.f = *(const float4*)&As[s][kk][ty << 3];
            u1.f = *(const float4*)(&As[s][kk][ty << 3] + 4);
            u64 ap[4] = {u0.u[0], u0.u[1], u1.u[0], u1.u[1]};
            float4 bq = *(const float4*)&Bs[s][kk][tx << 2];
            u64 b0 = pack2(bq.x, bq.x), b1 = pack2(bq.y, bq.y);
            u64 b2 = pack2(bq.z, bq.z), b3 = pack2(bq.w, bq.w);
            #pragma unroll
            for (int r = 0; r < 4; r++) {
                fma2(acc[r][0], ap[r], b0);
                fma2(acc[r][1], ap[r], b1);
                fma2(acc[r][2], ap[r], b2);
                fma2(acc[r][3], ap[r], b3);
            }
        }
        if (more) {
            int so = s ^ 1, k4 = kgA << 2;
            As[so][k4+0][am]=na0.x; As[so][k4+1][am]=na0.y; As[so][k4+2][am]=na0.z; As[so][k4+3][am]=na0.w;
            As[so][k4+8][am]=na1.x; As[so][k4+9][am]=na1.y; As[so][k4+10][am]=na1.z; As[so][k4+11][am]=na1.w;
            *(float4*)&Bs[so][br][bc]   = nb0;
            *(float4*)&Bs[so][br+8][bc] = nb1;
            __syncthreads();
        }
    }

    int c0 = n0 + (tx << 2);
    float4 bias4 = make_float4(0.f,0.f,0.f,0.f);
    if (jb.bias) bias4 = *(const float4*)(jb.bias + c0);
    #pragma unroll
    for (int rp = 0; rp < 4; rp++) {
        float2 p0 = unpack2(acc[rp][0]), p1 = unpack2(acc[rp][1]);
        float2 p2 = unpack2(acc[rp][2]), p3 = unpack2(acc[rp][3]);
        int mA = m0 + (ty << 3) + (rp << 1), mB = mA + 1;
        float4 oA = make_float4(p0.x+bias4.x, p1.x+bias4.y, p2.x+bias4.z, p3.x+bias4.w);
        float4 oB = make_float4(p0.y+bias4.x, p1.y+bias4.y, p2.y+bias4.z, p3.y+bias4.w);
        if (jb.res) {
            float4 rA = *(const float4*)(jb.res + (size_t)mA*CD + c0);
            float4 rB = *(const float4*)(jb.res + (size_t)mB*CD + c0);
            oA.x += rA.x; oA.y += rA.y; oA.z += rA.z; oA.w += rA.w;
            oB.x += rB.x; oB.y += rB.y; oB.z += rB.z; oB.w += rB.w;
        }
        *(float4*)(jb.out + (size_t)mA*CD + c0) = oA;
        *(float4*)(jb.out + (size_t)mB*CD + c0) = oB;
    }
}

// ---------- flash: 128 thr, 4 warps * 16 rows; padded smem; 32-col score chunks ----------
__global__ void flash_kernel(const float* __restrict__ q, const float* __restrict__ k,
                             const float* __restrict__ v, float* __restrict__ out) {
    const float LOG2E = 1.4426950408889634f;
    int bh = blockIdx.y, b = bh >> 3, h = bh & 7;
    int qbase = blockIdx.x << 6;
    __shared__ float4 ks[128][5], vs[128][5];   // 80B row stride: conflict-free
    int tid = threadIdx.x, wid = tid >> 5, lane = tid & 31;
    int r = lane >> 2, g = lane & 3;
    int rowA = qbase + (wid << 4) + r, rowB = rowA + 8;
    const float* qpA = q + (((b<<11) + rowA) << 7) + (h << 4);
    const float* qpB = q + (((b<<11) + rowB) << 7) + (h << 4);
    u64 qa[8], qb2[8];
    #pragma unroll
    for (int j = 0; j < 4; j++) {
        float4 ta = *(const float4*)(qpA + j*4);
        float4 tb = *(const float4*)(qpB + j*4);
        qa[j*2]   = pack2(ta.x*LOG2E, ta.y*LOG2E);
        qa[j*2+1] = pack2(ta.z*LOG2E, ta.w*LOG2E);
        qb2[j*2]   = pack2(tb.x*LOG2E, tb.y*LOG2E);
        qb2[j*2+1] = pack2(tb.z*LOG2E, tb.w*LOG2E);
    }
    u64 accA[8], accB[8];
    #pragma unroll
    for (int d = 0; d < 8; d++) { accA[d] = 0ull; accB[d] = 0ull; }
    float mA = -1e30f, mB = -1e30f, lsA = 0.f, lsB = 0.f;
    const float* kbase = k + (((size_t)b << 11) << 7) + (h << 4);
    const float* vbase = v + (((size_t)b << 11) << 7) + (h << 4);

    for (int kt = 0; kt < 2048; kt += 128) {
        __syncthreads();
        #pragma unroll
        for (int u = 0; u < 4; u++) {
            int li = tid + (u << 7);
            int row = li >> 2, j = li & 3;
            ks[row][j] = *(const float4*)(kbase + (size_t)(kt+row)*CD + (j<<2));
            vs[row][j] = *(const float4*)(vbase + (size_t)(kt+row)*CD + (j<<2));
        }
        __syncthreads();
        #pragma unroll
        for (int ch = 0; ch < 4; ch++) {
            float sA[8], sB[8];
            float tmA = -1e30f, tmB = -1e30f;
            #pragma unroll
            for (int i = 0; i < 8; i++) {
                int kc = (ch << 5) + (i << 2) + g;
                F4U k0, k1, k2, k3;
                k0.f = ks[kc][0]; k1.f = ks[kc][1]; k2.f = ks[kc][2]; k3.f = ks[kc][3];
                u64 dA = 0ull, dB = 0ull;
                fma2(dA, qa[0], k0.u[0]); fma2(dA, qa[1], k0.u[1]);
                fma2(dA, qa[2], k1.u[0]); fma2(dA, qa[3], k1.u[1]);
                fma2(dA, qa[4], k2.u[0]); fma2(dA, qa[5], k2.u[1]);
                fma2(dA, qa[6], k3.u[0]); fma2(dA, qa[7], k3.u[1]);
                fma2(dB, qb2[0], k0.u[0]); fma2(dB, qb2[1], k0.u[1]);
                fma2(dB, qb2[2], k1.u[0]); fma2(dB, qb2[3], k1.u[1]);
                fma2(dB, qb2[4], k2.u[0]); fma2(dB, qb2[5], k2.u[1]);
                fma2(dB, qb2[6], k3.u[0]); fma2(dB, qb2[7], k3.u[1]);
                float2 fa = unpack2(dA), fb = unpack2(dB);
                sA[i] = fa.x + fa.y; sB[i] = fb.x + fb.y;
                tmA = fmaxf(tmA, sA[i]); tmB = fmaxf(tmB, sB[i]);
            }
            tmA = fmaxf(tmA, __shfl_xor_sync(~0u, tmA, 1));
            tmA = fmaxf(tmA, __shfl_xor_sync(~0u, tmA, 2));
            tmB = fmaxf(tmB, __shfl_xor_sync(~0u, tmB, 1));
            tmB = fmaxf(tmB, __shfl_xor_sync(~0u, tmB, 2));
            float nA = fmaxf(mA, tmA), nB = fmaxf(mB, tmB);
            float cA = exp2f(mA - nA), cB = exp2f(mB - nB);
            mA = nA; mB = nB; lsA *= cA; lsB *= cB;
            u64 cA2 = pack2(cA, cA), cB2 = pack2(cB, cB);
            #pragma unroll
            for (int d = 0; d < 8; d++) { mul2(accA[d], cA2); mul2(accB[d], cB2); }
            #pragma unroll
            for (int i = 0; i < 8; i++) {
                int kc = (ch << 5) + (i << 2) + g;
                float pA = exp2f(sA[i] - mA), pB = exp2f(sB[i] - mB);
                lsA += pA; lsB += pB;
                u64 pA2 = pack2(pA, pA), pB2 = pack2(pB, pB);
                F4U v0, v1, v2, v3;
                v0.f = vs[kc][0]; v1.f = vs[kc][1]; v2.f = vs[kc][2]; v3.f = vs[kc][3];
                fma2(accA[0], pA2, v0.u[0]); fma2(accA[1], pA2, v0.u[1]);
                fma2(accA[2], pA2, v1.u[0]); fma2(accA[3], pA2, v1.u[1]);
                fma2(accA[4], pA2, v2.u[0]); fma2(accA[5], pA2, v2.u[1]);
                fma2(accA[6], pA2, v3.u[0]); fma2(accA[7], pA2, v3.u[1]);
                fma2(accB[0], pB2, v0.u[0]); fma2(accB[1], pB2, v0.u[1]);
                fma2(accB[2], pB2, v1.u[0]); fma2(accB[3], pB2, v1.u[1]);
                fma2(accB[4], pB2, v2.u[0]); fma2(accB[5], pB2, v2.u[1]);
                fma2(accB[6], pB2, v3.u[0]); fma2(accB[7], pB2, v3.u[1]);
            }
        }
    }
    float aA[16], aB[16];
    #pragma unroll
    for (int d = 0; d < 8; d++) {
        float2 fa = unpack2(accA[d]), fb = unpack2(accB[d]);
        aA[d*2] = fa.x; aA[d*2+1] = fa.y;
        aB[d*2] = fb.x; aB[d*2+1] = fb.y;
    }
    #pragma unroll
    for (int d = 0; d < 16; d++) {
        aA[d] += __shfl_xor_sync(~0u, aA[d], 1);
        aA[d] += __shfl_xor_sync(~0u, aA[d], 2);
        aB[d] += __shfl_xor_sync(~0u, aB[d], 1);
        aB[d] += __shfl_xor_sync(~0u, aB[d], 2);
    }
    lsA += __shfl_xor_sync(~0u, lsA, 1); lsA += __shfl_xor_sync(~0u, lsA, 2);
    lsB += __shfl_xor_sync(~0u, lsB, 1); lsB += __shfl_xor_sync(~0u, lsB, 2);
    float invA = 1.0f / lsA, invB = 1.0f / lsB;
    #pragma unroll
    for (int rr = 0; rr < 2; rr++) {
        int qrow = rr ? rowB : rowA;
        float inv = rr ? invB : invA;
        float* ac = rr ? aB : aA;
        size_t base = ((size_t)((b<<11) + qrow) << 7) + (h << 4);
        float ov[4];
        #pragma unroll
        for (int u = 0; u < 4; u++) {
            int w2 = (g << 2) + u;
            float ca = 0.f;
            #pragma unroll
            for (int s2 = 0; s2 < 3; s2++) {
                int f = w2 + (s2 << 4);
                int sel = f % 3;
                const float* tp = (sel == 0) ? q : ((sel == 1) ? k : v);
                ca += tp[base + f/3];
            }
            ov[u] = ac[(g<<2)+u]*inv + ca*(1.0f/3.0f);
        }
        *(float4*)(out + base + (g << 2)) = make_float4(ov[0], ov[1], ov[2], ov[3]);
    }
}

__global__ void combine_ln(const float* __restrict__ a1, const float* __restrict__ a2,
                           const float* __restrict__ a3, const float* __restrict__ hh,
                           const float* __restrict__ gam, const float* __restrict__ bet,
                           float* __restrict__ x2, float* __restrict__ y2,
                           float* __restrict__ xm) {
    int m = blockIdx.x, c = threadIdx.x, lane = c & 31, wid = c >> 5;
    float sacc = 0.f;
    #pragma unroll
    for (int s2 = 0; s2 < 3; s2++) {
        int f = c*3 + s2;
        const float* ap = (f >> 7) == 0 ? a1 : ((f >> 7) == 1 ? a2 : a3);
        sacc += ap[(m << 7) + (f & 127)];
    }
    float v = sacc*(1.0f/3.0f) + hh[m*CD + c];
    x2[m*CD + c] = v;
    float s = v, sq = v*v;
    #pragma unroll
    for (int o = 16; o > 0; o >>= 1) { s += __shfl_xor_sync(~0u, s, o); sq += __shfl_xor_sync(~0u, sq, o); }
    __shared__ float ss[4], sqq[4], ys[4];
    if (lane == 0) { ss[wid] = s; sqq[wid] = sq; }
    __syncthreads();
    float S = ss[0]+ss[1]+ss[2]+ss[3], SQ = sqq[0]+sqq[1]+sqq[2]+sqq[3];
    float mean = S*(1.0f/CD), var = SQ*(1.0f/CD) - mean*mean, rs = rsqrtf(var + 1e-6f);
    float y = (v - mean)*rs*gam[c] + bet[c];
    y2[m*CD + c] = y;
    float t = y;
    #pragma unroll
    for (int o = 16; o > 0; o >>= 1) t += __shfl_xor_sync(~0u, t, o);
    if (lane == 0) ys[wid] = t;
    __syncthreads();
    if (c == 0) xm[m] = (ys[0]+ys[1]+ys[2]+ys[3])*(1.0f/CD);
}

__global__ void final_kernel(const float* __restrict__ x2, const float* __restrict__ y2,
                             const float* __restrict__ xm, const float* __restrict__ st1,
                             const float* __restrict__ st2, const float* __restrict__ st3,
                             float* __restrict__ out) {
    int m = blockIdx.x, b = m >> 11, p = m & 2047;
    int t = p >> 4, ii = (p >> 2) & 3, jj = p & 3;
    __shared__ float sg;
    if (threadIdx.x == 0) {
        float gg = st1[0] * xm[m];
        #pragma unroll
        for (int kd = 0; kd < 2; kd++)
        for (int kh = 0; kh < 2; kh++)
        for (int kw = 0; kw < 2; kw++) {
            int t2 = t + kd - 1, i2 = ii + kh - 1, j2 = jj + kw - 1;
            if ((unsigned)t2 < 128u && (unsigned)i2 < 4u && (unsigned)j2 < 4u)
                gg += st2[kd*4 + kh*2 + kw] * xm[(b<<11) + (t2<<4) + (i2<<2) + j2];
        }
        #pragma unroll
        for (int kd = 0; kd < 3; kd++)
        for (int kh = 0; kh < 3; kh++)
        for (int kw = 0; kw < 3; kw++) {
            int t2 = t + kd - 1, i2 = ii + kh - 1, j2 = jj + kw - 1;
            if ((unsigned)t2 < 128u && (unsigned)i2 < 4u && (unsigned)j2 < 4u)
                gg += st3[kd*9 + kh*3 + kw] * xm[(b<<11) + (t2<<4) + (i2<<2) + j2];
        }
        sg = 1.0f / (1.0f + __expf(-gg));
    }
    __syncthreads();
    int idx = m*CD + threadIdx.x;
    out[idx] = x2[idx] + y2[idx]*sg;
}

extern "C" void kernel_launch(void* const* d_in, const int* in_sizes, int n_in,
                              void* d_out, int out_size) {
    const float* x      = (const float*)d_in[0];
    const float* n1g    = (const float*)d_in[1];
    const float* n1b    = (const float*)d_in[2];
    const float* q_w    = (const float*)d_in[3];
    const float* qbg    = (const float*)d_in[4];
    const float* qbb    = (const float*)d_in[5];
    const float* k_w    = (const float*)d_in[6];
    const float* kbg    = (const float*)d_in[7];
    const float* kbb    = (const float*)d_in[8];
    const float* v_w    = (const float*)d_in[9];
    const float* proj_w = (const float*)d_in[10];
    const float* proj_b = (const float*)d_in[11];
    const float* r1_w   = (const float*)d_in[12];
    const float* r2_w   = (const float*)d_in[13];
    const float* r3_w   = (const float*)d_in[14];
    const float* n2g    = (const float*)d_in[15];
    const float* n2b    = (const float*)d_in[16];
    const float* st1    = (const float*)d_in[17];
    const float* st2    = (const float*)d_in[18];
    const float* st3    = (const float*)d_in[19];
    float* out = (float*)d_out;

    float *y1,*qb,*kb,*vb,*attn,*hb,*a1,*a2,*a3,*x2,*y2,*xm;
    float *wq,*wk,*wv,*wr1,*wr2,*wr3,*wp,*bnst;
    cudaGetSymbolAddress((void**)&y1, g_y1);     cudaGetSymbolAddress((void**)&qb, g_qb);
    cudaGetSymbolAddress((void**)&kb, g_kb);     cudaGetSymbolAddress((void**)&vb, g_vb);
    cudaGetSymbolAddress((void**)&attn, g_attn); cudaGetSymbolAddress((void**)&hb, g_hb);
    cudaGetSymbolAddress((void**)&a1, g_a1);     cudaGetSymbolAddress((void**)&a2, g_a2);
    cudaGetSymbolAddress((void**)&a3, g_a3);     cudaGetSymbolAddress((void**)&x2, g_x2);
    cudaGetSymbolAddress((void**)&y2, g_y2);     cudaGetSymbolAddress((void**)&xm, g_xm);
    cudaGetSymbolAddress((void**)&wq, g_wq);     cudaGetSymbolAddress((void**)&wk, g_wk);
    cudaGetSymbolAddress((void**)&wv, g_wv);     cudaGetSymbolAddress((void**)&wr1, g_wr1);
    cudaGetSymbolAddress((void**)&wr2, g_wr2);   cudaGetSymbolAddress((void**)&wr3, g_wr3);
    cudaGetSymbolAddress((void**)&wp, g_wp);     cudaGetSymbolAddress((void**)&bnst, g_bnst);

    auto cdiv = [](int a, int b){ return (a + b - 1) / b; };
    const int n27 = 27*CD*CD, n8 = 8*CD*CD, n1 = CD*CD;

    WJobs wa = {};
    wa.nj = 2;
    wa.src[0]=q_w;  wa.dst[0]=wq;  wa.KK[0]=27; wa.n[0]=n27;
    wa.src[1]=r1_w; wa.dst[1]=wr1; wa.KK[1]=27; wa.n[1]=n27;
    WJobs wb = {};
    wb.nj = 5;
    wb.src[0]=k_w;   wb.dst[0]=wk;  wb.KK[0]=8; wb.n[0]=n8;
    wb.src[1]=r2_w;  wb.dst[1]=wr2; wb.KK[1]=8; wb.n[1]=n8;
    wb.src[2]=v_w;   wb.dst[2]=wv;  wb.KK[2]=1; wb.n[2]=n1;
    wb.src[3]=r3_w;  wb.dst[3]=wr3; wb.KK[3]=1; wb.n[3]=n1;
    wb.src[4]=proj_w;wb.dst[4]=wp;  wb.KK[4]=1; wb.n[4]=n1;

    wtrans_multi<<<cdiv(2*n27,256),256>>>(wa, bnst, 2*2*CD);
    wtrans_multi<<<cdiv(2*n8+3*n1,256),256>>>(wb, nullptr, 0);
    ln_kernel<<<MTOT, 128>>>(x, y1, n1g, n1b, nullptr, 1e-6f);

    Job jq  = { y1, wq,  nullptr, nullptr, qb };
    Job jr1 = { x,  wr1, x,       nullptr, a1 };
    conv_gemm_big<3,9><<<dim3(32,9,2), 256>>>(jq, jr1);
    reduce_split<9><<<MTOT*CD*2/256, 256>>>(jq, jr1);

    Job jk  = { y1, wk,  nullptr, nullptr, kb };
    Job jr2 = { a1, wr2, a1,      nullptr, a2 };
    conv_gemm_big<2,4><<<dim3(32,4,2), 256>>>(jk, jr2);
    reduce_split<4><<<MTOT*CD*2/256, 256>>>(jk, jr2);

    bn_stats<<<dim3(32,2), 256>>>(qb, kb);
    bn_apply<<<dim3(MTOT*CD/256,2), 256>>>(qb, kb, qbg, qbb, kbg, kbb);

    Job jv  = { y1, wv,  nullptr, nullptr, vb };
    Job jr3 = { a2, wr3, a2,      nullptr, a3 };
    conv_gemm_small<<<dim3(2,64,2), 128>>>(jv, jr3);

    flash_kernel<<<dim3(32,16), 128>>>(qb, kb, vb, attn);

    Job jp = { attn, wp, nullptr, proj_b, hb };
    conv_gemm_small<<<dim3(2,64,1), 128>>>(jp, jp);

    combine_ln<<<MTOT, 128>>>(a1, a2, a3, hb, n2g, n2b, x2, y2, xm);
    final_kernel<<<MTOT, 128>>>(x2, y2, xm, st1, st2, st3, out);
}

// round 8
// speedup vs baseline: 2.1173x; 1.0580x over previous
#include <cuda_runtime.h>
#include <math.h>

#define CD 128
#define MTOT 4096

typedef unsigned long long u64;

__device__ __forceinline__ u64 pack2(float lo, float hi) {
    u64 r; asm("mov.b64 %0,{%1,%2};" : "=l"(r) : "f"(lo), "f"(hi)); return r;
}
__device__ __forceinline__ void fma2(u64& d, u64 a, u64 b) {
    asm("fma.rn.f32x2 %0,%1,%2,%0;" : "+l"(d) : "l"(a), "l"(b));
}
__device__ __forceinline__ void mul2(u64& d, u64 a) {
    asm("mul.rn.f32x2 %0,%0,%1;" : "+l"(d) : "l"(a));
}
__device__ __forceinline__ float2 unpack2(u64 v) {
    float2 f; asm("mov.b64 {%0,%1},%2;" : "=f"(f.x), "=f"(f.y) : "l"(v)); return f;
}

union F4U { float4 f; u64 u[2]; };

struct Job  { const float* in; const float* wt; const float* res; const float* bias; float* out; };
struct WJobs { const float* src[5]; float* dst[5]; int KK[5]; int n[5]; int nj; };

__device__ float g_y1[MTOT*CD], g_qb[MTOT*CD], g_kb[MTOT*CD], g_vb[MTOT*CD];
__device__ float g_attn[MTOT*CD], g_hb[MTOT*CD], g_a1[MTOT*CD], g_a2[MTOT*CD], g_a3[MTOT*CD];
__device__ float g_x2[MTOT*CD], g_y2[MTOT*CD], g_xm[MTOT];
__device__ float g_wq[27*CD*CD], g_wk[8*CD*CD], g_wv[CD*CD];
__device__ float g_wr1[27*CD*CD], g_wr2[8*CD*CD], g_wr3[CD*CD], g_wp[CD*CD];
__device__ float g_bnst[2][2][CD];
__device__ float g_part[9*2*MTOT*CD];   // split-K partials: [split][job][m][c]

__global__ void wtrans_multi(WJobs J, float* zbuf, int zn) {
    int idx = blockIdx.x * 256 + threadIdx.x;
    if (zbuf && idx < zn) zbuf[idx] = 0.f;
    int base = 0;
    #pragma unroll
    for (int j = 0; j < 5; j++) {
        if (j >= J.nj) return;
        if (idx < base + J.n[j]) {
            int t = idx - base;
            int tap = t / (CD*CD); int rem = t - tap*(CD*CD);
            int ci = rem >> 7, co = rem & 127;
            J.dst[j][t] = J.src[j][(co*CD + ci)*J.KK[j] + tap];
            return;
        }
        base += J.n[j];
    }
}

__global__ void ln_kernel(const float* __restrict__ in, float* __restrict__ out,
                          const float* __restrict__ gam, const float* __restrict__ bet,
                          float* __restrict__ xm, float eps) {
    int m = blockIdx.x, c = threadIdx.x, lane = c & 31, wid = c >> 5;
    float v = in[m*CD + c], s = v, sq = v*v;
    #pragma unroll
    for (int o = 16; o > 0; o >>= 1) { s += __shfl_xor_sync(~0u, s, o); sq += __shfl_xor_sync(~0u, sq, o); }
    __shared__ float ss[4], sqq[4], ys[4];
    if (lane == 0) { ss[wid] = s; sqq[wid] = sq; }
    __syncthreads();
    float S = ss[0]+ss[1]+ss[2]+ss[3], SQ = sqq[0]+sqq[1]+sqq[2]+sqq[3];
    float mean = S*(1.0f/CD), var = SQ*(1.0f/CD) - mean*mean, rs = rsqrtf(var + eps);
    float y = (v - mean)*rs*gam[c] + bet[c];
    out[m*CD + c] = y;
    if (xm) {
        float t = y;
        #pragma unroll
        for (int o = 16; o > 0; o >>= 1) t += __shfl_xor_sync(~0u, t, o);
        if (lane == 0) ys[wid] = t;
        __syncthreads();
        if (c == 0) xm[m] = (ys[0]+ys[1]+ys[2]+ys[3])*(1.0f/CD);
    }
}

__global__ void bn_stats(const float* __restrict__ q, const float* __restrict__ k) {
    int buf = blockIdx.y;
    const float* src = buf ? k : q;
    int tid = threadIdx.x;
    int base = blockIdx.x * 128;
    float s = 0.f, sq = 0.f;
    for (int i = tid; i < 128*CD; i += 256) {
        float v = src[(base + (i >> 7))*CD + (i & 127)];
        s += v; sq += v*v;
    }
    __shared__ float sh[256];
    sh[tid] = s; __syncthreads();
    if (tid < 128) atomicAdd(&g_bnst[buf][0][tid], sh[tid] + sh[tid+128]);
    __syncthreads();
    sh[tid] = sq; __syncthreads();
    if (tid < 128) atomicAdd(&g_bnst[buf][1][tid], sh[tid] + sh[tid+128]);
}

__global__ void bn_apply(float* __restrict__ q, float* __restrict__ k,
                         const float* __restrict__ qg, const float* __restrict__ qb2,
                         const float* __restrict__ kg, const float* __restrict__ kb2) {
    int buf = blockIdx.y;
    float* dst = buf ? k : q;
    const float* gam = buf ? kg : qg;
    const float* bet = buf ? kb2 : qb2;
    int idx = blockIdx.x * 256 + threadIdx.x;
    int c = idx & 127;
    float S = g_bnst[buf][0][c], SQ = g_bnst[buf][1][c];
    float mean = S*(1.0f/MTOT), var = SQ*(1.0f/MTOT) - mean*mean;
    float sc = gam[c]*rsqrtf(var + 1e-5f), sh = bet[c] - mean*sc;
    dst[idx] = dst[idx]*sc + sh;
}

// ---------- big conv: BM=128 BN=128 BK=16, 256 thr, warp-tiled 8x4, split-K ----------
template<int KS, int SPLIT>
__global__ __launch_bounds__(256, 2) void conv_gemm_big(Job j0, Job j1) {
    constexpr int K = KS*KS*KS*CD;
    constexpr int KSP = K / SPLIT;
    constexpr int NIT = KSP / 16;
    const int job = blockIdx.z, split = blockIdx.y;
    Job jb = job ? j1 : j0;
    const int m0 = blockIdx.x << 7;
    const int kbase = split * KSP;
    __shared__ float As[2][16][128];
    __shared__ float Bs[2][16][128];
    const int tid = threadIdx.x;
    const int am = tid & 127, kg = tid >> 7;           // A loader: k-groups kg, kg+2
    const int gm = m0 + am, bb = gm >> 11, p = gm & 2047;
    const int tt = p >> 4, ii = (p >> 2) & 3, jj = p & 3;
    const int br = tid >> 5, bc = (tid & 31) << 2;     // B loader: rows br, br+8
    const int warp = tid >> 5, lane = tid & 31;
    // warp-tiled compute map: warp covers 8 ty x 4 tx -> A 1-wavefront, B 4-distinct
    const int ty = ((warp >> 2) << 3) + (lane >> 2);   // 0..15
    const int tx = ((warp & 3) << 2) + (lane & 3);     // 0..15
    u64 acc[4][8];
    #pragma unroll
    for (int r = 0; r < 4; r++)
        #pragma unroll
        for (int u = 0; u < 8; u++) acc[r][u] = 0ull;

    auto ldA = [&](int kgabs) -> float4 {
        int tap = kgabs >> 5;
        int ci = (kgabs << 2) & 127;
        int dt, di, dj;
        if (KS == 3) { dt = tap/9 - 1; int r9 = tap%9; di = r9/3 - 1; dj = r9%3 - 1; }
        else { dt = (tap>>2) - 1; di = ((tap>>1)&1) - 1; dj = (tap&1) - 1; }
        int t2 = tt + dt, i2 = ii + di, j2 = jj + dj;
        if ((unsigned)t2 < 128u && (unsigned)i2 < 4u && (unsigned)j2 < 4u)
            return *(const float4*)(jb.in + (((bb<<11) + (t2<<4) + (i2<<2) + j2) << 7) + ci);
        return make_float4(0.f,0.f,0.f,0.f);
    };

    {   // prologue stage 0
        int kg4 = kbase >> 2;
        float4 a0 = ldA(kg4 + kg), a1 = ldA(kg4 + kg + 2);
        float4 b0 = *(const float4*)(jb.wt + (size_t)(kbase + br)*CD + bc);
        float4 b1 = *(const float4*)(jb.wt + (size_t)(kbase + br + 8)*CD + bc);
        int k4 = kg << 2;
        As[0][k4+0][am]=a0.x; As[0][k4+1][am]=a0.y; As[0][k4+2][am]=a0.z; As[0][k4+3][am]=a0.w;
        As[0][k4+8][am]=a1.x; As[0][k4+9][am]=a1.y; As[0][k4+10][am]=a1.z; As[0][k4+11][am]=a1.w;
        *(float4*)&Bs[0][br][bc]   = b0;
        *(float4*)&Bs[0][br+8][bc] = b1;
    }
    __syncthreads();

    for (int it = 0; it < NIT; it++) {
        int s = it & 1;
        float4 na0, na1, nb0, nb1;
        bool more = (it + 1 < NIT);
        if (more) {
            int kofs = kbase + (it+1)*16;
            na0 = ldA((kofs>>2) + kg); na1 = ldA((kofs>>2) + kg + 2);
            nb0 = *(const float4*)(jb.wt + (size_t)(kofs + br)*CD + bc);
            nb1 = *(const float4*)(jb.wt + (size_t)(kofs + br + 8)*CD + bc);
        }
        #pragma unroll
        for (int kk = 0; kk < 16; kk++) {
            F4U a0, a1;
            a0.f = *(const float4*)&As[s][kk][ty << 3];
            a1.f = *(const float4*)(&As[s][kk][ty << 3] + 4);
            u64 ap[4] = {a0.u[0], a0.u[1], a1.u[0], a1.u[1]};
            float4 b0 = *(const float4*)&Bs[s][kk][tx << 3];
            float4 b1 = *(const float4*)(&Bs[s][kk][tx << 3] + 4);
            u64 bp[8];
            bp[0] = pack2(b0.x, b0.x); bp[1] = pack2(b0.y, b0.y);
            bp[2] = pack2(b0.z, b0.z); bp[3] = pack2(b0.w, b0.w);
            bp[4] = pack2(b1.x, b1.x); bp[5] = pack2(b1.y, b1.y);
            bp[6] = pack2(b1.z, b1.z); bp[7] = pack2(b1.w, b1.w);
            #pragma unroll
            for (int r = 0; r < 4; r++)
                #pragma unroll
                for (int u = 0; u < 8; u++)
                    fma2(acc[r][u], ap[r], bp[u]);
        }
        if (more) {
            int so = s ^ 1, k4 = kg << 2;
            As[so][k4+0][am]=na0.x; As[so][k4+1][am]=na0.y; As[so][k4+2][am]=na0.z; As[so][k4+3][am]=na0.w;
            As[so][k4+8][am]=na1.x; As[so][k4+9][am]=na1.y; As[so][k4+10][am]=na1.z; As[so][k4+11][am]=na1.w;
            *(float4*)&Bs[so][br][bc]   = nb0;
            *(float4*)&Bs[so][br+8][bc] = nb1;
            __syncthreads();
        }
    }

    float* pb = g_part + ((size_t)(split*2 + job) << 19);
    int c0 = tx << 3;
    #pragma unroll
    for (int r = 0; r < 4; r++) {
        int mA = m0 + (ty<<3) + (r<<1), mB = mA + 1;
        float2 f0 = unpack2(acc[r][0]), f1 = unpack2(acc[r][1]);
        float2 f2 = unpack2(acc[r][2]), f3 = unpack2(acc[r][3]);
        float2 f4 = unpack2(acc[r][4]), f5 = unpack2(acc[r][5]);
        float2 f6 = unpack2(acc[r][6]), f7 = unpack2(acc[r][7]);
        *(float4*)(pb + (size_t)mA*CD + c0)     = make_float4(f0.x, f1.x, f2.x, f3.x);
        *(float4*)(pb + (size_t)mA*CD + c0 + 4) = make_float4(f4.x, f5.x, f6.x, f7.x);
        *(float4*)(pb + (size_t)mB*CD + c0)     = make_float4(f0.y, f1.y, f2.y, f3.y);
        *(float4*)(pb + (size_t)mB*CD + c0 + 4) = make_float4(f4.y, f5.y, f6.y, f7.y);
    }
}

template<int SPLIT>
__global__ void reduce_split(Job j0, Job j1) {
    int idx = blockIdx.x * 256 + threadIdx.x;      // over 2 * 2^19
    int job = idx >> 19, r = idx & ((1<<19) - 1);
    Job jb = job ? j1 : j0;
    float s = 0.f;
    #pragma unroll
    for (int sp = 0; sp < SPLIT; sp++)
        s += g_part[((size_t)(sp*2 + job) << 19) + r];
    if (jb.bias) s += jb.bias[r & 127];
    if (jb.res)  s += jb.res[r];
    jb.out[r] = s;
}

// ---------- small conv (KS=1 paths): warp-tiled 8x4 map ----------
__global__ __launch_bounds__(128, 4) void conv_gemm_small(Job j0, Job j1) {
    constexpr int K = CD;
    constexpr int NIT = K / 16;
    Job jb = (blockIdx.z == 0) ? j0 : j1;
    const int m0 = blockIdx.y << 6, n0 = blockIdx.x << 6;
    __shared__ float As[2][16][64], Bs[2][16][64];
    const int tid = threadIdx.x;
    const int am = tid & 63, kgA = tid >> 6;
    const int gm = m0 + am;
    const int br = tid >> 4, bc = (tid & 15) << 2;
    const int warp = tid >> 5, lane = tid & 31;
    const int ty = lane >> 2;                       // 0..7 (all within warp)
    const int tx = (warp << 2) + (lane & 3);        // 0..15
    u64 acc[4][4];
    #pragma unroll
    for (int r = 0; r < 4; r++)
        #pragma unroll
        for (int c = 0; c < 4; c++) acc[r][c] = 0ull;

    auto ldA = [&](int kgabs) -> float4 {
        int ci = (kgabs << 2) & 127;
        return *(const float4*)(jb.in + ((size_t)gm << 7) + ci);
    };
    {
        float4 a0 = ldA(kgA), a1 = ldA(kgA + 2);
        float4 b0 = *(const float4*)(jb.wt + (size_t)br*CD + n0 + bc);
        float4 b1 = *(const float4*)(jb.wt + (size_t)(br+8)*CD + n0 + bc);
        int k4 = kgA << 2;
        As[0][k4+0][am]=a0.x; As[0][k4+1][am]=a0.y; As[0][k4+2][am]=a0.z; As[0][k4+3][am]=a0.w;
        As[0][k4+8][am]=a1.x; As[0][k4+9][am]=a1.y; As[0][k4+10][am]=a1.z; As[0][k4+11][am]=a1.w;
        *(float4*)&Bs[0][br][bc]   = b0;
        *(float4*)&Bs[0][br+8][bc] = b1;
    }
    __syncthreads();

    for (int it = 0; it < NIT; it++) {
        int s = it & 1;
        float4 na0, na1, nb0, nb1;
        bool more = (it + 1 < NIT);
        if (more) {
            int kg = (it+1)*4;
            na0 = ldA(kg + kgA); na1 = ldA(kg + kgA + 2);
            nb0 = *(const float4*)(jb.wt + (size_t)((it+1)*16 + br)*CD + n0 + bc);
            nb1 = *(const float4*)(jb.wt + (size_t)((it+1)*16 + br + 8)*CD + n0 + bc);
        }
        #pragma unroll
        for (int kk = 0; kk < 16; kk++) {
            F4U u0, u1;
            u0.f = *(const float4*)&As[s][kk][ty << 3];
            u1.f = *(const float4*)(&As[s][kk][ty << 3] + 4);
            u64 ap[4] = {u0.u[0], u0.u[1], u1.u[0], u1.u[1]};
            float4 bq = *(const float4*)&Bs[s][kk][tx << 2];
            u64 b0 = pack2(bq.x, bq.x), b1 = pack2(bq.y, bq.y);
            u64 b2 = pack2(bq.z, bq.z), b3 = pack2(bq.w, bq.w);
            #pragma unroll
            for (int r = 0; r < 4; r++) {
                fma2(acc[r][0], ap[r], b0);
                fma2(acc[r][1], ap[r], b1);
                fma2(acc[r][2], ap[r], b2);
                fma2(acc[r][3], ap[r], b3);
            }
        }
        if (more) {
            int so = s ^ 1, k4 = kgA << 2;
            As[so][k4+0][am]=na0.x; As[so][k4+1][am]=na0.y; As[so][k4+2][am]=na0.z; As[so][k4+3][am]=na0.w;
            As[so][k4+8][am]=na1.x; As[so][k4+9][am]=na1.y; As[so][k4+10][am]=na1.z; As[so][k4+11][am]=na1.w;
            *(float4*)&Bs[so][br][bc]   = nb0;
            *(float4*)&Bs[so][br+8][bc] = nb1;
            __syncthreads();
        }
    }

    int c0 = n0 + (tx << 2);
    float4 bias4 = make_float4(0.f,0.f,0.f,0.f);
    if (jb.bias) bias4 = *(const float4*)(jb.bias + c0);
    #pragma unroll
    for (int rp = 0; rp < 4; rp++) {
        float2 p0 = unpack2(acc[rp][0]), p1 = unpack2(acc[rp][1]);
        float2 p2 = unpack2(acc[rp][2]), p3 = unpack2(acc[rp][3]);
        int mA = m0 + (ty << 3) + (rp << 1), mB = mA + 1;
        float4 oA = make_float4(p0.x+bias4.x, p1.x+bias4.y, p2.x+bias4.z, p3.x+bias4.w);
        float4 oB = make_float4(p0.y+bias4.x, p1.y+bias4.y, p2.y+bias4.z, p3.y+bias4.w);
        if (jb.res) {
            float4 rA = *(const float4*)(jb.res + (size_t)mA*CD + c0);
            float4 rB = *(const float4*)(jb.res + (size_t)mB*CD + c0);
            oA.x += rA.x; oA.y += rA.y; oA.z += rA.z; oA.w += rA.w;
            oB.x += rB.x; oB.y += rB.y; oB.z += rB.z; oB.w += rB.w;
        }
        *(float4*)(jb.out + (size_t)mA*CD + c0) = oA;
        *(float4*)(jb.out + (size_t)mB*CD + c0) = oB;
    }
}

// ---------- flash: 128 thr, 4 warps * 16 rows; padded smem; 32-col score chunks ----------
__global__ void flash_kernel(const float* __restrict__ q, const float* __restrict__ k,
                             const float* __restrict__ v, float* __restrict__ out) {
    const float LOG2E = 1.4426950408889634f;
    int bh = blockIdx.y, b = bh >> 3, h = bh & 7;
    int qbase = blockIdx.x << 6;
    __shared__ float4 ks[128][5], vs[128][5];   // 80B row stride: conflict-free
    int tid = threadIdx.x, wid = tid >> 5, lane = tid & 31;
    int r = lane >> 2, g = lane & 3;
    int rowA = qbase + (wid << 4) + r, rowB = rowA + 8;
    const float* qpA = q + (((b<<11) + rowA) << 7) + (h << 4);
    const float* qpB = q + (((b<<11) + rowB) << 7) + (h << 4);
    u64 qa[8], qb2[8];
    #pragma unroll
    for (int j = 0; j < 4; j++) {
        float4 ta = *(const float4*)(qpA + j*4);
        float4 tb = *(const float4*)(qpB + j*4);
        qa[j*2]   = pack2(ta.x*LOG2E, ta.y*LOG2E);
        qa[j*2+1] = pack2(ta.z*LOG2E, ta.w*LOG2E);
        qb2[j*2]   = pack2(tb.x*LOG2E, tb.y*LOG2E);
        qb2[j*2+1] = pack2(tb.z*LOG2E, tb.w*LOG2E);
    }
    u64 accA[8], accB[8];
    #pragma unroll
    for (int d = 0; d < 8; d++) { accA[d] = 0ull; accB[d] = 0ull; }
    float mA = -1e30f, mB = -1e30f, lsA = 0.f, lsB = 0.f;
    const float* kbase = k + (((size_t)b << 11) << 7) + (h << 4);
    const float* vbase = v + (((size_t)b << 11) << 7) + (h << 4);

    for (int kt = 0; kt < 2048; kt += 128) {
        __syncthreads();
        #pragma unroll
        for (int u = 0; u < 4; u++) {
            int li = tid + (u << 7);
            int row = li >> 2, j = li & 3;
            ks[row][j] = *(const float4*)(kbase + (size_t)(kt+row)*CD + (j<<2));
            vs[row][j] = *(const float4*)(vbase + (size_t)(kt+row)*CD + (j<<2));
        }
        __syncthreads();
        #pragma unroll
        for (int ch = 0; ch < 4; ch++) {
            float sA[8], sB[8];
            float tmA = -1e30f, tmB = -1e30f;
            #pragma unroll
            for (int i = 0; i < 8; i++) {
                int kc = (ch << 5) + (i << 2) + g;
                F4U k0, k1, k2, k3;
                k0.f = ks[kc][0]; k1.f = ks[kc][1]; k2.f = ks[kc][2]; k3.f = ks[kc][3];
                u64 dA = 0ull, dB = 0ull;
                fma2(dA, qa[0], k0.u[0]); fma2(dA, qa[1], k0.u[1]);
                fma2(dA, qa[2], k1.u[0]); fma2(dA, qa[3], k1.u[1]);
                fma2(dA, qa[4], k2.u[0]); fma2(dA, qa[5], k2.u[1]);
                fma2(dA, qa[6], k3.u[0]); fma2(dA, qa[7], k3.u[1]);
                fma2(dB, qb2[0], k0.u[0]); fma2(dB, qb2[1], k0.u[1]);
                fma2(dB, qb2[2], k1.u[0]); fma2(dB, qb2[3], k1.u[1]);
                fma2(dB, qb2[4], k2.u[0]); fma2(dB, qb2[5], k2.u[1]);
                fma2(dB, qb2[6], k3.u[0]); fma2(dB, qb2[7], k3.u[1]);
                float2 fa = unpack2(dA), fb = unpack2(dB);
                sA[i] = fa.x + fa.y; sB[i] = fb.x + fb.y;
                tmA = fmaxf(tmA, sA[i]); tmB = fmaxf(tmB, sB[i]);
            }
            tmA = fmaxf(tmA, __shfl_xor_sync(~0u, tmA, 1));
            tmA = fmaxf(tmA, __shfl_xor_sync(~0u, tmA, 2));
            tmB = fmaxf(tmB, __shfl_xor_sync(~0u, tmB, 1));
            tmB = fmaxf(tmB, __shfl_xor_sync(~0u, tmB, 2));
            float nA = fmaxf(mA, tmA), nB = fmaxf(mB, tmB);
            float cA = exp2f(mA - nA), cB = exp2f(mB - nB);
            mA = nA; mB = nB; lsA *= cA; lsB *= cB;
            u64 cA2 = pack2(cA, cA), cB2 = pack2(cB, cB);
            #pragma unroll
            for (int d = 0; d < 8; d++) { mul2(accA[d], cA2); mul2(accB[d], cB2); }
            #pragma unroll
            for (int i = 0; i < 8; i++) {
                int kc = (ch << 5) + (i << 2) + g;
                float pA = exp2f(sA[i] - mA), pB = exp2f(sB[i] - mB);
                lsA += pA; lsB += pB;
                u64 pA2 = pack2(pA, pA), pB2 = pack2(pB, pB);
                F4U v0, v1, v2, v3;
                v0.f = vs[kc][0]; v1.f = vs[kc][1]; v2.f = vs[kc][2]; v3.f = vs[kc][3];
                fma2(accA[0], pA2, v0.u[0]); fma2(accA[1], pA2, v0.u[1]);
                fma2(accA[2], pA2, v1.u[0]); fma2(accA[3], pA2, v1.u[1]);
                fma2(accA[4], pA2, v2.u[0]); fma2(accA[5], pA2, v2.u[1]);
                fma2(accA[6], pA2, v3.u[0]); fma2(accA[7], pA2, v3.u[1]);
                fma2(accB[0], pB2, v0.u[0]); fma2(accB[1], pB2, v0.u[1]);
                fma2(accB[2], pB2, v1.u[0]); fma2(accB[3], pB2, v1.u[1]);
                fma2(accB[4], pB2, v2.u[0]); fma2(accB[5], pB2, v2.u[1]);
                fma2(accB[6], pB2, v3.u[0]); fma2(accB[7], pB2, v3.u[1]);
            }
        }
    }
    float aA[16], aB[16];
    #pragma unroll
    for (int d = 0; d < 8; d++) {
        float2 fa = unpack2(accA[d]), fb = unpack2(accB[d]);
        aA[d*2] = fa.x; aA[d*2+1] = fa.y;
        aB[d*2] = fb.x; aB[d*2+1] = fb.y;
    }
    #pragma unroll
    for (int d = 0; d < 16; d++) {
        aA[d] += __shfl_xor_sync(~0u, aA[d], 1);
        aA[d] += __shfl_xor_sync(~0u, aA[d], 2);
        aB[d] += __shfl_xor_sync(~0u, aB[d], 1);
        aB[d] += __shfl_xor_sync(~0u, aB[d], 2);
    }
    lsA += __shfl_xor_sync(~0u, lsA, 1); lsA += __shfl_xor_sync(~0u, lsA, 2);
    lsB += __shfl_xor_sync(~0u, lsB, 1); lsB += __shfl_xor_sync(~0u, lsB, 2);
    float invA = 1.0f / lsA, invB = 1.0f / lsB;
    #pragma unroll
    for (int rr = 0; rr < 2; rr++) {
        int qrow = rr ? rowB : rowA;
        float inv = rr ? invB : invA;
        float* ac = rr ? aB : aA;
        size_t base = ((size_t)((b<<11) + qrow) << 7) + (h << 4);
        float ov[4];
        #pragma unroll
        for (int u = 0; u < 4; u++) {
            int w2 = (g << 2) + u;
            float ca = 0.f;
            #pragma unroll
            for (int s2 = 0; s2 < 3; s2++) {
                int f = w2 + (s2 << 4);
                int sel = f % 3;
                const float* tp = (sel == 0) ? q : ((sel == 1) ? k : v);
                ca += tp[base + f/3];
            }
            ov[u] = ac[(g<<2)+u]*inv + ca*(1.0f/3.0f);
        }
        *(float4*)(out + base + (g << 2)) = make_float4(ov[0], ov[1], ov[2], ov[3]);
    }
}

__global__ void combine_ln(const float* __restrict__ a1, const float* __restrict__ a2,
                           const float* __restrict__ a3, const float* __restrict__ hh,
                           const float* __restrict__ gam, const float* __restrict__ bet,
                           float* __restrict__ x2, float* __restrict__ y2,
                           float* __restrict__ xm) {
    int m = blockIdx.x, c = threadIdx.x, lane = c & 31, wid = c >> 5;
    float sacc = 0.f;
    #pragma unroll
    for (int s2 = 0; s2 < 3; s2++) {
        int f = c*3 + s2;
        const float* ap = (f >> 7) == 0 ? a1 : ((f >> 7) == 1 ? a2 : a3);
        sacc += ap[(m << 7) + (f & 127)];
    }
    float v = sacc*(1.0f/3.0f) + hh[m*CD + c];
    x2[m*CD + c] = v;
    float s = v, sq = v*v;
    #pragma unroll
    for (int o = 16; o > 0; o >>= 1) { s += __shfl_xor_sync(~0u, s, o); sq += __shfl_xor_sync(~0u, sq, o); }
    __shared__ float ss[4], sqq[4], ys[4];
    if (lane == 0) { ss[wid] = s; sqq[wid] = sq; }
    __syncthreads();
    float S = ss[0]+ss[1]+ss[2]+ss[3], SQ = sqq[0]+sqq[1]+sqq[2]+sqq[3];
    float mean = S*(1.0f/CD), var = SQ*(1.0f/CD) - mean*mean, rs = rsqrtf(var + 1e-6f);
    float y = (v - mean)*rs*gam[c] + bet[c];
    y2[m*CD + c] = y;
    float t = y;
    #pragma unroll
    for (int o = 16; o > 0; o >>= 1) t += __shfl_xor_sync(~0u, t, o);
    if (lane == 0) ys[wid] = t;
    __syncthreads();
    if (c == 0) xm[m] = (ys[0]+ys[1]+ys[2]+ys[3])*(1.0f/CD);
}

__global__ void final_kernel(const float* __restrict__ x2, const float* __restrict__ y2,
                             const float* __restrict__ xm, const float* __restrict__ st1,
                             const float* __restrict__ st2, const float* __restrict__ st3,
                             float* __restrict__ out) {
    int m = blockIdx.x, b = m >> 11, p = m & 2047;
    int t = p >> 4, ii = (p >> 2) & 3, jj = p & 3;
    __shared__ float sg;
    if (threadIdx.x == 0) {
        float gg = st1[0] * xm[m];
        #pragma unroll
        for (int kd = 0; kd < 2; kd++)
        for (int kh = 0; kh < 2; kh++)
        for (int kw = 0; kw < 2; kw++) {
            int t2 = t + kd - 1, i2 = ii + kh - 1, j2 = jj + kw - 1;
            if ((unsigned)t2 < 128u && (unsigned)i2 < 4u && (unsigned)j2 < 4u)
                gg += st2[kd*4 + kh*2 + kw] * xm[(b<<11) + (t2<<4) + (i2<<2) + j2];
        }
        #pragma unroll
        for (int kd = 0; kd < 3; kd++)
        for (int kh = 0; kh < 3; kh++)
        for (int kw = 0; kw < 3; kw++) {
            int t2 = t + kd - 1, i2 = ii + kh - 1, j2 = jj + kw - 1;
            if ((unsigned)t2 < 128u && (unsigned)i2 < 4u && (unsigned)j2 < 4u)
                gg += st3[kd*9 + kh*3 + kw] * xm[(b<<11) + (t2<<4) + (i2<<2) + j2];
        }
        sg = 1.0f / (1.0f + __expf(-gg));
    }
    __syncthreads();
    int idx = m*CD + threadIdx.x;
    out[idx] = x2[idx] + y2[idx]*sg;
}

extern "C" void kernel_launch(void* const* d_in, const int* in_sizes, int n_in,
                              void* d_out, int out_size) {
    const float* x      = (const float*)d_in[0];
    const float* n1g    = (const float*)d_in[1];
    const float* n1b    = (const float*)d_in[2];
    const float* q_w    = (const float*)d_in[3];
    const float* qbg    = (const float*)d_in[4];
    const float* qbb    = (const float*)d_in[5];
    const float* k_w    = (const float*)d_in[6];
    const float* kbg    = (const float*)d_in[7];
    const float* kbb    = (const float*)d_in[8];
    const float* v_w    = (const float*)d_in[9];
    const float* proj_w = (const float*)d_in[10];
    const float* proj_b = (const float*)d_in[11];
    const float* r1_w   = (const float*)d_in[12];
    const float* r2_w   = (const float*)d_in[13];
    const float* r3_w   = (const float*)d_in[14];
    const float* n2g    = (const float*)d_in[15];
    const float* n2b    = (const float*)d_in[16];
    const float* st1    = (const float*)d_in[17];
    const float* st2    = (const float*)d_in[18];
    const float* st3    = (const float*)d_in[19];
    float* out = (float*)d_out;

    float *y1,*qb,*kb,*vb,*attn,*hb,*a1,*a2,*a3,*x2,*y2,*xm;
    float *wq,*wk,*wv,*wr1,*wr2,*wr3,*wp,*bnst;
    cudaGetSymbolAddress((void**)&y1, g_y1);     cudaGetSymbolAddress((void**)&qb, g_qb);
    cudaGetSymbolAddress((void**)&kb, g_kb);     cudaGetSymbolAddress((void**)&vb, g_vb);
    cudaGetSymbolAddress((void**)&attn, g_attn); cudaGetSymbolAddress((void**)&hb, g_hb);
    cudaGetSymbolAddress((void**)&a1, g_a1);     cudaGetSymbolAddress((void**)&a2, g_a2);
    cudaGetSymbolAddress((void**)&a3, g_a3);     cudaGetSymbolAddress((void**)&x2, g_x2);
    cudaGetSymbolAddress((void**)&y2, g_y2);     cudaGetSymbolAddress((void**)&xm, g_xm);
    cudaGetSymbolAddress((void**)&wq, g_wq);     cudaGetSymbolAddress((void**)&wk, g_wk);
    cudaGetSymbolAddress((void**)&wv, g_wv);     cudaGetSymbolAddress((void**)&wr1, g_wr1);
    cudaGetSymbolAddress((void**)&wr2, g_wr2);   cudaGetSymbolAddress((void**)&wr3, g_wr3);
    cudaGetSymbolAddress((void**)&wp, g_wp);     cudaGetSymbolAddress((void**)&bnst, g_bnst);

    auto cdiv = [](int a, int b){ return (a + b - 1) / b; };
    const int n27 = 27*CD*CD, n8 = 8*CD*CD, n1 = CD*CD;

    WJobs wa = {};
    wa.nj = 2;
    wa.src[0]=q_w;  wa.dst[0]=wq;  wa.KK[0]=27; wa.n[0]=n27;
    wa.src[1]=r1_w; wa.dst[1]=wr1; wa.KK[1]=27; wa.n[1]=n27;
    WJobs wb = {};
    wb.nj = 5;
    wb.src[0]=k_w;   wb.dst[0]=wk;  wb.KK[0]=8; wb.n[0]=n8;
    wb.src[1]=r2_w;  wb.dst[1]=wr2; wb.KK[1]=8; wb.n[1]=n8;
    wb.src[2]=v_w;   wb.dst[2]=wv;  wb.KK[2]=1; wb.n[2]=n1;
    wb.src[3]=r3_w;  wb.dst[3]=wr3; wb.KK[3]=1; wb.n[3]=n1;
    wb.src[4]=proj_w;wb.dst[4]=wp;  wb.KK[4]=1; wb.n[4]=n1;

    wtrans_multi<<<cdiv(2*n27,256),256>>>(wa, bnst, 2*2*CD);
    wtrans_multi<<<cdiv(2*n8+3*n1,256),256>>>(wb, nullptr, 0);
    ln_kernel<<<MTOT, 128>>>(x, y1, n1g, n1b, nullptr, 1e-6f);

    Job jq  = { y1, wq,  nullptr, nullptr, qb };
    Job jr1 = { x,  wr1, x,       nullptr, a1 };
    conv_gemm_big<3,9><<<dim3(32,9,2), 256>>>(jq, jr1);
    reduce_split<9><<<MTOT*CD*2/256, 256>>>(jq, jr1);

    Job jk  = { y1, wk,  nullptr, nullptr, kb };
    Job jr2 = { a1, wr2, a1,      nullptr, a2 };
    conv_gemm_big<2,4><<<dim3(32,4,2), 256>>>(jk, jr2);
    reduce_split<4><<<MTOT*CD*2/256, 256>>>(jk, jr2);

    bn_stats<<<dim3(32,2), 256>>>(qb, kb);
    bn_apply<<<dim3(MTOT*CD/256,2), 256>>>(qb, kb, qbg, qbb, kbg, kbb);

    Job jv  = { y1, wv,  nullptr, nullptr, vb };
    Job jr3 = { a2, wr3, a2,      nullptr, a3 };
    conv_gemm_small<<<dim3(2,64,2), 128>>>(jv, jr3);

    flash_kernel<<<dim3(32,16), 128>>>(qb, kb, vb, attn);

    Job jp = { attn, wp, nullptr, proj_b, hb };
    conv_gemm_small<<<dim3(2,64,1), 128>>>(jp, jp);

    combine_ln<<<MTOT, 128>>>(a1, a2, a3, hb, n2g, n2b, x2, y2, xm);
    final_kernel<<<MTOT, 128>>>(x2, y2, xm, st1, st2, st3, out);
}

// round 10
// speedup vs baseline: 2.1338x; 1.0078x over previous
#include <cuda_runtime.h>
#include <math.h>

#define CD 128
#define MTOT 4096

typedef unsigned long long u64;

__device__ __forceinline__ u64 pack2(float lo, float hi) {
    u64 r; asm("mov.b64 %0,{%1,%2};" : "=l"(r) : "f"(lo), "f"(hi)); return r;
}
__device__ __forceinline__ void fma2(u64& d, u64 a, u64 b) {
    asm("fma.rn.f32x2 %0,%1,%2,%0;" : "+l"(d) : "l"(a), "l"(b));
}
__device__ __forceinline__ void mul2(u64& d, u64 a) {
    asm("mul.rn.f32x2 %0,%0,%1;" : "+l"(d) : "l"(a));
}
__device__ __forceinline__ float2 unpack2(u64 v) {
    float2 f; asm("mov.b64 {%0,%1},%2;" : "=f"(f.x), "=f"(f.y) : "l"(v)); return f;
}

union F4U { float4 f; u64 u[2]; };

struct Job  { const float* in; const float* wt; const float* res; const float* bias; float* out; };
struct WJobs { const float* src[5]; float* dst[5]; int KK[5]; int n[5]; int nj; };

// tap -> (dt, di, dj) decode tables (uniform per BK-iteration)
__constant__ int4 c_tap3[27] = {
    {-1,-1,-1,0},{-1,-1,0,0},{-1,-1,1,0},{-1,0,-1,0},{-1,0,0,0},{-1,0,1,0},{-1,1,-1,0},{-1,1,0,0},{-1,1,1,0},
    { 0,-1,-1,0},{ 0,-1,0,0},{ 0,-1,1,0},{ 0,0,-1,0},{ 0,0,0,0},{ 0,0,1,0},{ 0,1,-1,0},{ 0,1,0,0},{ 0,1,1,0},
    { 1,-1,-1,0},{ 1,-1,0,0},{ 1,-1,1,0},{ 1,0,-1,0},{ 1,0,0,0},{ 1,0,1,0},{ 1,1,-1,0},{ 1,1,0,0},{ 1,1,1,0}
};
__constant__ int4 c_tap2[8] = {
    {-1,-1,-1,0},{-1,-1,0,0},{-1,0,-1,0},{-1,0,0,0},
    { 0,-1,-1,0},{ 0,-1,0,0},{ 0,0,-1,0},{ 0,0,0,0}
};

__device__ float g_y1[MTOT*CD], g_qb[MTOT*CD], g_kb[MTOT*CD], g_vb[MTOT*CD];
__device__ float g_attn[MTOT*CD], g_hb[MTOT*CD], g_a1[MTOT*CD], g_a2[MTOT*CD], g_a3[MTOT*CD];
__device__ float g_x2[MTOT*CD], g_y2[MTOT*CD], g_xm[MTOT];
__device__ float g_wq[27*CD*CD], g_wk[8*CD*CD], g_wv[CD*CD];
__device__ float g_wr1[27*CD*CD], g_wr2[8*CD*CD], g_wr3[CD*CD], g_wp[CD*CD];
__device__ float g_bnst[2][2][CD];
__device__ float g_part[9*2*MTOT*CD];   // split-K partials: [split][job][m][c]

__global__ void wtrans_multi(WJobs J, float* zbuf, int zn) {
    int idx = blockIdx.x * 256 + threadIdx.x;
    if (zbuf && idx < zn) zbuf[idx] = 0.f;
    int base = 0;
    #pragma unroll
    for (int j = 0; j < 5; j++) {
        if (j >= J.nj) return;
        if (idx < base + J.n[j]) {
            int t = idx - base;
            int tap = t / (CD*CD); int rem = t - tap*(CD*CD);
            int ci = rem >> 7, co = rem & 127;
            J.dst[j][t] = J.src[j][(co*CD + ci)*J.KK[j] + tap];
            return;
        }
        base += J.n[j];
    }
}

__global__ void ln_kernel(const float* __restrict__ in, float* __restrict__ out,
                          const float* __restrict__ gam, const float* __restrict__ bet,
                          float* __restrict__ xm, float eps) {
    int m = blockIdx.x, c = threadIdx.x, lane = c & 31, wid = c >> 5;
    float v = in[m*CD + c], s = v, sq = v*v;
    #pragma unroll
    for (int o = 16; o > 0; o >>= 1) { s += __shfl_xor_sync(~0u, s, o); sq += __shfl_xor_sync(~0u, sq, o); }
    __shared__ float ss[4], sqq[4], ys[4];
    if (lane == 0) { ss[wid] = s; sqq[wid] = sq; }
    __syncthreads();
    float S = ss[0]+ss[1]+ss[2]+ss[3], SQ = sqq[0]+sqq[1]+sqq[2]+sqq[3];
    float mean = S*(1.0f/CD), var = SQ*(1.0f/CD) - mean*mean, rs = rsqrtf(var + eps);
    float y = (v - mean)*rs*gam[c] + bet[c];
    out[m*CD + c] = y;
    if (xm) {
        float t = y;
        #pragma unroll
        for (int o = 16; o > 0; o >>= 1) t += __shfl_xor_sync(~0u, t, o);
        if (lane == 0) ys[wid] = t;
        __syncthreads();
        if (c == 0) xm[m] = (ys[0]+ys[1]+ys[2]+ys[3])*(1.0f/CD);
    }
}

__global__ void bn_stats(const float* __restrict__ q, const float* __restrict__ k) {
    int buf = blockIdx.y;
    const float* src = buf ? k : q;
    int tid = threadIdx.x;
    int base = blockIdx.x * 128;
    float s = 0.f, sq = 0.f;
    for (int i = tid; i < 128*CD; i += 256) {
        float v = src[(base + (i >> 7))*CD + (i & 127)];
        s += v; sq += v*v;
    }
    __shared__ float sh[256];
    sh[tid] = s; __syncthreads();
    if (tid < 128) atomicAdd(&g_bnst[buf][0][tid], sh[tid] + sh[tid+128]);
    __syncthreads();
    sh[tid] = sq; __syncthreads();
    if (tid < 128) atomicAdd(&g_bnst[buf][1][tid], sh[tid] + sh[tid+128]);
}

__global__ void bn_apply(float* __restrict__ q, float* __restrict__ k,
                         const float* __restrict__ qg, const float* __restrict__ qb2,
                         const float* __restrict__ kg, const float* __restrict__ kb2) {
    int buf = blockIdx.y;
    float* dst = buf ? k : q;
    const float* gam = buf ? kg : qg;
    const float* bet = buf ? kb2 : qb2;
    int idx = blockIdx.x * 256 + threadIdx.x;
    int c = idx & 127;
    float S = g_bnst[buf][0][c], SQ = g_bnst[buf][1][c];
    float mean = S*(1.0f/MTOT), var = SQ*(1.0f/MTOT) - mean*mean;
    float sc = gam[c]*rsqrtf(var + 1e-5f), sh = bet[c] - mean*sc;
    dst[idx] = dst[idx]*sc + sh;
}

// ---------- big conv: BM=128 BN=128 BK=16, 256 thr, warp-tiled 8x4, split-K ----------
template<int KS, int SPLIT>
__global__ __launch_bounds__(256, 2) void conv_gemm_big(Job j0, Job j1) {
    constexpr int K = KS*KS*KS*CD;
    constexpr int KSP = K / SPLIT;
    constexpr int NIT = KSP / 16;
    const int job = blockIdx.z, split = blockIdx.y;
    Job jb = job ? j1 : j0;
    const int m0 = blockIdx.x << 7;
    const int kbase = split * KSP;
    __shared__ float As[2][16][128];
    __shared__ float Bs[2][16][128];
    const int tid = threadIdx.x;
    const int am = tid & 127, kg = tid >> 7;           // A loader: k-groups kg, kg+2
    const int gm = m0 + am, bb = gm >> 11, p = gm & 2047;
    const int tt = p >> 4, ii = (p >> 2) & 3, jj = p & 3;
    const int br = tid >> 5, bc = (tid & 31) << 2;     // B loader: rows br, br+8
    const int warp = tid >> 5, lane = tid & 31;
    const int ty = ((warp >> 2) << 3) + (lane >> 2);   // 0..15
    const int tx = ((warp & 3) << 2) + (lane & 3);     // 0..15
    u64 acc[4][8];
    #pragma unroll
    for (int r = 0; r < 4; r++)
        #pragma unroll
        for (int u = 0; u < 8; u++) acc[r][u] = 0ull;

    // per-iteration A fetch: tap decode is uniform (one tap per BK=16 span)
    auto fetchA = [&](int kofs, float4& a0, float4& a1) {
        int tap = kofs >> 7;
        int4 d = (KS == 3) ? c_tap3[tap] : c_tap2[tap];
        int t2 = tt + d.x, i2 = ii + d.y, j2 = jj + d.z;
        bool valid = ((unsigned)t2 < 128u) & ((unsigned)i2 < 4u) & ((unsigned)j2 < 4u);
        const float* ap = jb.in + (((size_t)((bb<<11) + (t2<<4) + (i2<<2) + j2)) << 7);
        int ci0 = (kofs & 127) + (kg << 2);
        a0 = valid ? *(const float4*)(ap + ci0)     : make_float4(0.f,0.f,0.f,0.f);
        a1 = valid ? *(const float4*)(ap + ci0 + 8) : make_float4(0.f,0.f,0.f,0.f);
    };

    {   // prologue stage 0
        float4 a0, a1;
        fetchA(kbase, a0, a1);
        float4 b0 = *(const float4*)(jb.wt + (size_t)(kbase + br)*CD + bc);
        float4 b1 = *(const float4*)(jb.wt + (size_t)(kbase + br + 8)*CD + bc);
        int k4 = kg << 2;
        As[0][k4+0][am]=a0.x; As[0][k4+1][am]=a0.y; As[0][k4+2][am]=a0.z; As[0][k4+3][am]=a0.w;
        As[0][k4+8][am]=a1.x; As[0][k4+9][am]=a1.y; As[0][k4+10][am]=a1.z; As[0][k4+11][am]=a1.w;
        *(float4*)&Bs[0][br][bc]   = b0;
        *(float4*)&Bs[0][br+8][bc] = b1;
    }
    __syncthreads();

    for (int it = 0; it < NIT; it++) {
        int s = it & 1;
        float4 na0, na1, nb0, nb1;
        bool more = (it + 1 < NIT);
        if (more) {
            int kofs = kbase + (it+1)*16;
            fetchA(kofs, na0, na1);
            nb0 = *(const float4*)(jb.wt + (size_t)(kofs + br)*CD + bc);
            nb1 = *(const float4*)(jb.wt + (size_t)(kofs + br + 8)*CD + bc);
        }
        #pragma unroll
        for (int kk = 0; kk < 16; kk++) {
            F4U a0, a1;
            a0.f = *(const float4*)&As[s][kk][ty << 3];
            a1.f = *(const float4*)(&As[s][kk][ty << 3] + 4);
            u64 ap[4] = {a0.u[0], a0.u[1], a1.u[0], a1.u[1]};
            float4 b0 = *(const float4*)&Bs[s][kk][tx << 3];
            float4 b1 = *(const float4*)(&Bs[s][kk][tx << 3] + 4);
            u64 bp[8];
            bp[0] = pack2(b0.x, b0.x); bp[1] = pack2(b0.y, b0.y);
            bp[2] = pack2(b0.z, b0.z); bp[3] = pack2(b0.w, b0.w);
            bp[4] = pack2(b1.x, b1.x); bp[5] = pack2(b1.y, b1.y);
            bp[6] = pack2(b1.z, b1.z); bp[7] = pack2(b1.w, b1.w);
            #pragma unroll
            for (int r = 0; r < 4; r++)
                #pragma unroll
                for (int u = 0; u < 8; u++)
                    fma2(acc[r][u], ap[r], bp[u]);
        }
        if (more) {
            int so = s ^ 1, k4 = kg << 2;
            As[so][k4+0][am]=na0.x; As[so][k4+1][am]=na0.y; As[so][k4+2][am]=na0.z; As[so][k4+3][am]=na0.w;
            As[so][k4+8][am]=na1.x; As[so][k4+9][am]=na1.y; As[so][k4+10][am]=na1.z; As[so][k4+11][am]=na1.w;
            *(float4*)&Bs[so][br][bc]   = nb0;
            *(float4*)&Bs[so][br+8][bc] = nb1;
            __syncthreads();
        }
    }

    float* pb = g_part + ((size_t)(split*2 + job) << 19);
    int c0 = tx << 3;
    #pragma unroll
    for (int r = 0; r < 4; r++) {
        int mA = m0 + (ty<<3) + (r<<1), mB = mA + 1;
        float2 f0 = unpack2(acc[r][0]), f1 = unpack2(acc[r][1]);
        float2 f2 = unpack2(acc[r][2]), f3 = unpack2(acc[r][3]);
        float2 f4 = unpack2(acc[r][4]), f5 = unpack2(acc[r][5]);
        float2 f6 = unpack2(acc[r][6]), f7 = unpack2(acc[r][7]);
        *(float4*)(pb + (size_t)mA*CD + c0)     = make_float4(f0.x, f1.x, f2.x, f3.x);
        *(float4*)(pb + (size_t)mA*CD + c0 + 4) = make_float4(f4.x, f5.x, f6.x, f7.x);
        *(float4*)(pb + (size_t)mB*CD + c0)     = make_float4(f0.y, f1.y, f2.y, f3.y);
        *(float4*)(pb + (size_t)mB*CD + c0 + 4) = make_float4(f4.y, f5.y, f6.y, f7.y);
    }
}

template<int SPLIT>
__global__ void reduce_split(Job j0, Job j1) {
    int idx = blockIdx.x * 256 + threadIdx.x;      // over 2 * 2^19
    int job = idx >> 19, r = idx & ((1<<19) - 1);
    Job jb = job ? j1 : j0;
    float s = 0.f;
    #pragma unroll
    for (int sp = 0; sp < SPLIT; sp++)
        s += g_part[((size_t)(sp*2 + job) << 19) + r];
    if (jb.bias) s += jb.bias[r & 127];
    if (jb.res)  s += jb.res[r];
    jb.out[r] = s;
}

// ---------- small conv (KS=1 paths): warp-tiled 8x4 map ----------
__global__ __launch_bounds__(128, 4) void conv_gemm_small(Job j0, Job j1) {
    constexpr int K = CD;
    constexpr int NIT = K / 16;
    Job jb = (blockIdx.z == 0) ? j0 : j1;
    const int m0 = blockIdx.y << 6, n0 = blockIdx.x << 6;
    __shared__ float As[2][16][64], Bs[2][16][64];
    const int tid = threadIdx.x;
    const int am = tid & 63, kgA = tid >> 6;
    const int gm = m0 + am;
    const int br = tid >> 4, bc = (tid & 15) << 2;
    const int warp = tid >> 5, lane = tid & 31;
    const int ty = lane >> 2;
    const int tx = (warp << 2) + (lane & 3);
    u64 acc[4][4];
    #pragma unroll
    for (int r = 0; r < 4; r++)
        #pragma unroll
        for (int c = 0; c < 4; c++) acc[r][c] = 0ull;

    auto ldA = [&](int kgabs) -> float4 {
        int ci = (kgabs << 2) & 127;
        return *(const float4*)(jb.in + ((size_t)gm << 7) + ci);
    };
    {
        float4 a0 = ldA(kgA), a1 = ldA(kgA + 2);
        float4 b0 = *(const float4*)(jb.wt + (size_t)br*CD + n0 + bc);
        float4 b1 = *(const float4*)(jb.wt + (size_t)(br+8)*CD + n0 + bc);
        int k4 = kgA << 2;
        As[0][k4+0][am]=a0.x; As[0][k4+1][am]=a0.y; As[0][k4+2][am]=a0.z; As[0][k4+3][am]=a0.w;
        As[0][k4+8][am]=a1.x; As[0][k4+9][am]=a1.y; As[0][k4+10][am]=a1.z; As[0][k4+11][am]=a1.w;
        *(float4*)&Bs[0][br][bc]   = b0;
        *(float4*)&Bs[0][br+8][bc] = b1;
    }
    __syncthreads();

    for (int it = 0; it < NIT; it++) {
        int s = it & 1;
        float4 na0, na1, nb0, nb1;
        bool more = (it + 1 < NIT);
        if (more) {
            int kg = (it+1)*4;
            na0 = ldA(kg + kgA); na1 = ldA(kg + kgA + 2);
            nb0 = *(const float4*)(jb.wt + (size_t)((it+1)*16 + br)*CD + n0 + bc);
            nb1 = *(const float4*)(jb.wt + (size_t)((it+1)*16 + br + 8)*CD + n0 + bc);
        }
        #pragma unroll
        for (int kk = 0; kk < 16; kk++) {
            F4U u0, u1;
            u0.f = *(const float4*)&As[s][kk][ty << 3];
            u1.f = *(const float4*)(&As[s][kk][ty << 3] + 4);
            u64 ap[4] = {u0.u[0], u0.u[1], u1.u[0], u1.u[1]};
            float4 bq = *(const float4*)&Bs[s][kk][tx << 2];
            u64 b0 = pack2(bq.x, bq.x), b1 = pack2(bq.y, bq.y);
            u64 b2 = pack2(bq.z, bq.z), b3 = pack2(bq.w, bq.w);
            #pragma unroll
            for (int r = 0; r < 4; r++) {
                fma2(acc[r][0], ap[r], b0);
                fma2(acc[r][1], ap[r], b1);
                fma2(acc[r][2], ap[r], b2);
                fma2(acc[r][3], ap[r], b3);
            }
        }
        if (more) {
            int so = s ^ 1, k4 = kgA << 2;
            As[so][k4+0][am]=na0.x; As[so][k4+1][am]=na0.y; As[so][k4+2][am]=na0.z; As[so][k4+3][am]=na0.w;
            As[so][k4+8][am]=na1.x; As[so][k4+9][am]=na1.y; As[so][k4+10][am]=na1.z; As[so][k4+11][am]=na1.w;
            *(float4*)&Bs[so][br][bc]   = nb0;
            *(float4*)&Bs[so][br+8][bc] = nb1;
            __syncthreads();
        }
    }

    int c0 = n0 + (tx << 2);
    float4 bias4 = make_float4(0.f,0.f,0.f,0.f);
    if (jb.bias) bias4 = *(const float4*)(jb.bias + c0);
    #pragma unroll
    for (int rp = 0; rp < 4; rp++) {
        float2 p0 = unpack2(acc[rp][0]), p1 = unpack2(acc[rp][1]);
        float2 p2 = unpack2(acc[rp][2]), p3 = unpack2(acc[rp][3]);
        int mA = m0 + (ty << 3) + (rp << 1), mB = mA + 1;
        float4 oA = make_float4(p0.x+bias4.x, p1.x+bias4.y, p2.x+bias4.z, p3.x+bias4.w);
        float4 oB = make_float4(p0.y+bias4.x, p1.y+bias4.y, p2.y+bias4.z, p3.y+bias4.w);
        if (jb.res) {
            float4 rA = *(const float4*)(jb.res + (size_t)mA*CD + c0);
            float4 rB = *(const float4*)(jb.res + (size_t)mB*CD + c0);
            oA.x += rA.x; oA.y += rA.y; oA.z += rA.z; oA.w += rA.w;
            oB.x += rB.x; oB.y += rB.y; oB.z += rB.z; oB.w += rB.w;
        }
        *(float4*)(jb.out + (size_t)mA*CD + c0) = oA;
        *(float4*)(jb.out + (size_t)mB*CD + c0) = oB;
    }
}

// ---------- flash: 128 thr, 4 warps * 16 rows; padded smem; 32-col score chunks ----------
__global__ void flash_kernel(const float* __restrict__ q, const float* __restrict__ k,
                             const float* __restrict__ v, float* __restrict__ out) {
    const float LOG2E = 1.4426950408889634f;
    int bh = blockIdx.y, b = bh >> 3, h = bh & 7;
    int qbase = blockIdx.x << 6;
    __shared__ float4 ks[128][5], vs[128][5];   // 80B row stride: conflict-free
    int tid = threadIdx.x, wid = tid >> 5, lane = tid & 31;
    int r = lane >> 2, g = lane & 3;
    int rowA = qbase + (wid << 4) + r, rowB = rowA + 8;
    const float* qpA = q + (((b<<11) + rowA) << 7) + (h << 4);
    const float* qpB = q + (((b<<11) + rowB) << 7) + (h << 4);
    u64 qa[8], qb2[8];
    #pragma unroll
    for (int j = 0; j < 4; j++) {
        float4 ta = *(const float4*)(qpA + j*4);
        float4 tb = *(const float4*)(qpB + j*4);
        qa[j*2]   = pack2(ta.x*LOG2E, ta.y*LOG2E);
        qa[j*2+1] = pack2(ta.z*LOG2E, ta.w*LOG2E);
        qb2[j*2]   = pack2(tb.x*LOG2E, tb.y*LOG2E);
        qb2[j*2+1] = pack2(tb.z*LOG2E, tb.w*LOG2E);
    }
    u64 accA[8], accB[8];
    #pragma unroll
    for (int d = 0; d < 8; d++) { accA[d] = 0ull; accB[d] = 0ull; }
    float mA = -1e30f, mB = -1e30f, lsA = 0.f, lsB = 0.f;
    const float* kbase = k + (((size_t)b << 11) << 7) + (h << 4);
    const float* vbase = v + (((size_t)b << 11) << 7) + (h << 4);

    for (int kt = 0; kt < 2048; kt += 128) {
        __syncthreads();
        #pragma unroll
        for (int u = 0; u < 4; u++) {
            int li = tid + (u << 7);
            int row = li >> 2, j = li & 3;
            ks[row][j] = *(const float4*)(kbase + (size_t)(kt+row)*CD + (j<<2));
            vs[row][j] = *(const float4*)(vbase + (size_t)(kt+row)*CD + (j<<2));
        }
        __syncthreads();
        #pragma unroll
        for (int ch = 0; ch < 4; ch++) {
            float sA[8], sB[8];
            float tmA = -1e30f, tmB = -1e30f;
            #pragma unroll
            for (int i = 0; i < 8; i++) {
                int kc = (ch << 5) + (i << 2) + g;
                F4U k0, k1, k2, k3;
                k0.f = ks[kc][0]; k1.f = ks[kc][1]; k2.f = ks[kc][2]; k3.f = ks[kc][3];
                u64 dA = 0ull, dB = 0ull;
                fma2(dA, qa[0], k0.u[0]); fma2(dA, qa[1], k0.u[1]);
                fma2(dA, qa[2], k1.u[0]); fma2(dA, qa[3], k1.u[1]);
                fma2(dA, qa[4], k2.u[0]); fma2(dA, qa[5], k2.u[1]);
                fma2(dA, qa[6], k3.u[0]); fma2(dA, qa[7], k3.u[1]);
                fma2(dB, qb2[0], k0.u[0]); fma2(dB, qb2[1], k0.u[1]);
                fma2(dB, qb2[2], k1.u[0]); fma2(dB, qb2[3], k1.u[1]);
                fma2(dB, qb2[4], k2.u[0]); fma2(dB, qb2[5], k2.u[1]);
                fma2(dB, qb2[6], k3.u[0]); fma2(dB, qb2[7], k3.u[1]);
                float2 fa = unpack2(dA), fb = unpack2(dB);
                sA[i] = fa.x + fa.y; sB[i] = fb.x + fb.y;
                tmA = fmaxf(tmA, sA[i]); tmB = fmaxf(tmB, sB[i]);
            }
            tmA = fmaxf(tmA, __shfl_xor_sync(~0u, tmA, 1));
            tmA = fmaxf(tmA, __shfl_xor_sync(~0u, tmA, 2));
            tmB = fmaxf(tmB, __shfl_xor_sync(~0u, tmB, 1));
            tmB = fmaxf(tmB, __shfl_xor_sync(~0u, tmB, 2));
            float nA = fmaxf(mA, tmA), nB = fmaxf(mB, tmB);
            float cA = exp2f(mA - nA), cB = exp2f(mB - nB);
            mA = nA; mB = nB; lsA *= cA; lsB *= cB;
            u64 cA2 = pack2(cA, cA), cB2 = pack2(cB, cB);
            #pragma unroll
            for (int d = 0; d < 8; d++) { mul2(accA[d], cA2); mul2(accB[d], cB2); }
            #pragma unroll
            for (int i = 0; i < 8; i++) {
                int kc = (ch << 5) + (i << 2) + g;
                float pA = exp2f(sA[i] - mA), pB = exp2f(sB[i] - mB);
                lsA += pA; lsB += pB;
                u64 pA2 = pack2(pA, pA), pB2 = pack2(pB, pB);
                F4U v0, v1, v2, v3;
                v0.f = vs[kc][0]; v1.f = vs[kc][1]; v2.f = vs[kc][2]; v3.f = vs[kc][3];
                fma2(accA[0], pA2, v0.u[0]); fma2(accA[1], pA2, v0.u[1]);
                fma2(accA[2], pA2, v1.u[0]); fma2(accA[3], pA2, v1.u[1]);
                fma2(accA[4], pA2, v2.u[0]); fma2(accA[5], pA2, v2.u[1]);
                fma2(accA[6], pA2, v3.u[0]); fma2(accA[7], pA2, v3.u[1]);
                fma2(accB[0], pB2, v0.u[0]); fma2(accB[1], pB2, v0.u[1]);
                fma2(accB[2], pB2, v1.u[0]); fma2(accB[3], pB2, v1.u[1]);
                fma2(accB[4], pB2, v2.u[0]); fma2(accB[5], pB2, v2.u[1]);
                fma2(accB[6], pB2, v3.u[0]); fma2(accB[7], pB2, v3.u[1]);
            }
        }
    }
    float aA[16], aB[16];
    #pragma unroll
    for (int d = 0; d < 8; d++) {
        float2 fa = unpack2(accA[d]), fb = unpack2(accB[d]);
        aA[d*2] = fa.x; aA[d*2+1] = fa.y;
        aB[d*2] = fb.x; aB[d*2+1] = fb.y;
    }
    #pragma unroll
    for (int d = 0; d < 16; d++) {
        aA[d] += __shfl_xor_sync(~0u, aA[d], 1);
        aA[d] += __shfl_xor_sync(~0u, aA[d], 2);
        aB[d] += __shfl_xor_sync(~0u, aB[d], 1);
        aB[d] += __shfl_xor_sync(~0u, aB[d], 2);
    }
    lsA += __shfl_xor_sync(~0u, lsA, 1); lsA += __shfl_xor_sync(~0u, lsA, 2);
    lsB += __shfl_xor_sync(~0u, lsB, 1); lsB += __shfl_xor_sync(~0u, lsB, 2);
    float invA = 1.0f / lsA, invB = 1.0f / lsB;
    #pragma unroll
    for (int rr = 0; rr < 2; rr++) {
        int qrow = rr ? rowB : rowA;
        float inv = rr ? invB : invA;
        float* ac = rr ? aB : aA;
        size_t base = ((size_t)((b<<11) + qrow) << 7) + (h << 4);
        float ov[4];
        #pragma unroll
        for (int u = 0; u < 4; u++) {
            int w2 = (g << 2) + u;
            float ca = 0.f;
            #pragma unroll
            for (int s2 = 0; s2 < 3; s2++) {
                int f = w2 + (s2 << 4);
                int sel = f % 3;
                const float* tp = (sel == 0) ? q : ((sel == 1) ? k : v);
                ca += tp[base + f/3];
            }
            ov[u] = ac[(g<<2)+u]*inv + ca*(1.0f/3.0f);
        }
        *(float4*)(out + base + (g << 2)) = make_float4(ov[0], ov[1], ov[2], ov[3]);
    }
}

__global__ void combine_ln(const float* __restrict__ a1, const float* __restrict__ a2,
                           const float* __restrict__ a3, const float* __restrict__ hh,
                           const float* __restrict__ gam, const float* __restrict__ bet,
                           float* __restrict__ x2, float* __restrict__ y2,
                           float* __restrict__ xm) {
    int m = blockIdx.x, c = threadIdx.x, lane = c & 31, wid = c >> 5;
    float sacc = 0.f;
    #pragma unroll
    for (int s2 = 0; s2 < 3; s2++) {
        int f = c*3 + s2;
        const float* ap = (f >> 7) == 0 ? a1 : ((f >> 7) == 1 ? a2 : a3);
        sacc += ap[(m << 7) + (f & 127)];
    }
    float v = sacc*(1.0f/3.0f) + hh[m*CD + c];
    x2[m*CD + c] = v;
    float s = v, sq = v*v;
    #pragma unroll
    for (int o = 16; o > 0; o >>= 1) { s += __shfl_xor_sync(~0u, s, o); sq += __shfl_xor_sync(~0u, sq, o); }
    __shared__ float ss[4], sqq[4], ys[4];
    if (lane == 0) { ss[wid] = s; sqq[wid] = sq; }
    __syncthreads();
    float S = ss[0]+ss[1]+ss[2]+ss[3], SQ = sqq[0]+sqq[1]+sqq[2]+sqq[3];
    float mean = S*(1.0f/CD), var = SQ*(1.0f/CD) - mean*mean, rs = rsqrtf(var + 1e-6f);
    float y = (v - mean)*rs*gam[c] + bet[c];
    y2[m*CD + c] = y;
    float t = y;
    #pragma unroll
    for (int o = 16; o > 0; o >>= 1) t += __shfl_xor_sync(~0u, t, o);
    if (lane == 0) ys[wid] = t;
    __syncthreads();
    if (c == 0) xm[m] = (ys[0]+ys[1]+ys[2]+ys[3])*(1.0f/CD);
}

__global__ void final_kernel(const float* __restrict__ x2, const float* __restrict__ y2,
                             const float* __restrict__ xm, const float* __restrict__ st1,
                             const float* __restrict__ st2, const float* __restrict__ st3,
                             float* __restrict__ out) {
    int m = blockIdx.x, b = m >> 11, p = m & 2047;
    int t = p >> 4, ii = (p >> 2) & 3, jj = p & 3;
    __shared__ float sg;
    if (threadIdx.x == 0) {
        float gg = st1[0] * xm[m];
        #pragma unroll
        for (int kd = 0; kd < 2; kd++)
        for (int kh = 0; kh < 2; kh++)
        for (int kw = 0; kw < 2; kw++) {
            int t2 = t + kd - 1, i2 = ii + kh - 1, j2 = jj + kw - 1;
            if ((unsigned)t2 < 128u && (unsigned)i2 < 4u && (unsigned)j2 < 4u)
                gg += st2[kd*4 + kh*2 + kw] * xm[(b<<11) + (t2<<4) + (i2<<2) + j2];
        }
        #pragma unroll
        for (int kd = 0; kd < 3; kd++)
        for (int kh = 0; kh < 3; kh++)
        for (int kw = 0; kw < 3; kw++) {
            int t2 = t + kd - 1, i2 = ii + kh - 1, j2 = jj + kw - 1;
            if ((unsigned)t2 < 128u && (unsigned)i2 < 4u && (unsigned)j2 < 4u)
                gg += st3[kd*9 + kh*3 + kw] * xm[(b<<11) + (t2<<4) + (i2<<2) + j2];
        }
        sg = 1.0f / (1.0f + __expf(-gg));
    }
    __syncthreads();
    int idx = m*CD + threadIdx.x;
    out[idx] = x2[idx] + y2[idx]*sg;
}

extern "C" void kernel_launch(void* const* d_in, const int* in_sizes, int n_in,
                              void* d_out, int out_size) {
    const float* x      = (const float*)d_in[0];
    const float* n1g    = (const float*)d_in[1];
    const float* n1b    = (const float*)d_in[2];
    const float* q_w    = (const float*)d_in[3];
    const float* qbg    = (const float*)d_in[4];
    const float* qbb    = (const float*)d_in[5];
    const float* k_w    = (const float*)d_in[6];
    const float* kbg    = (const float*)d_in[7];
    const float* kbb    = (const float*)d_in[8];
    const float* v_w    = (const float*)d_in[9];
    const float* proj_w = (const float*)d_in[10];
    const float* proj_b = (const float*)d_in[11];
    const float* r1_w   = (const float*)d_in[12];
    const float* r2_w   = (const float*)d_in[13];
    const float* r3_w   = (const float*)d_in[14];
    const float* n2g    = (const float*)d_in[15];
    const float* n2b    = (const float*)d_in[16];
    const float* st1    = (const float*)d_in[17];
    const float* st2    = (const float*)d_in[18];
    const float* st3    = (const float*)d_in[19];
    float* out = (float*)d_out;

    float *y1,*qb,*kb,*vb,*attn,*hb,*a1,*a2,*a3,*x2,*y2,*xm;
    float *wq,*wk,*wv,*wr1,*wr2,*wr3,*wp,*bnst;
    cudaGetSymbolAddress((void**)&y1, g_y1);     cudaGetSymbolAddress((void**)&qb, g_qb);
    cudaGetSymbolAddress((void**)&kb, g_kb);     cudaGetSymbolAddress((void**)&vb, g_vb);
    cudaGetSymbolAddress((void**)&attn, g_attn); cudaGetSymbolAddress((void**)&hb, g_hb);
    cudaGetSymbolAddress((void**)&a1, g_a1);     cudaGetSymbolAddress((void**)&a2, g_a2);
    cudaGetSymbolAddress((void**)&a3, g_a3);     cudaGetSymbolAddress((void**)&x2, g_x2);
    cudaGetSymbolAddress((void**)&y2, g_y2);     cudaGetSymbolAddress((void**)&xm, g_xm);
    cudaGetSymbolAddress((void**)&wq, g_wq);     cudaGetSymbolAddress((void**)&wk, g_wk);
    cudaGetSymbolAddress((void**)&wv, g_wv);     cudaGetSymbolAddress((void**)&wr1, g_wr1);
    cudaGetSymbolAddress((void**)&wr2, g_wr2);   cudaGetSymbolAddress((void**)&wr3, g_wr3);
    cudaGetSymbolAddress((void**)&wp, g_wp);     cudaGetSymbolAddress((void**)&bnst, g_bnst);

    auto cdiv = [](int a, int b){ return (a + b - 1) / b; };
    const int n27 = 27*CD*CD, n8 = 8*CD*CD, n1 = CD*CD;

    WJobs wa = {};
    wa.nj = 2;
    wa.src[0]=q_w;  wa.dst[0]=wq;  wa.KK[0]=27; wa.n[0]=n27;
    wa.src[1]=r1_w; wa.dst[1]=wr1; wa.KK[1]=27; wa.n[1]=n27;
    WJobs wb = {};
    wb.nj = 5;
    wb.src[0]=k_w;   wb.dst[0]=wk;  wb.KK[0]=8; wb.n[0]=n8;
    wb.src[1]=r2_w;  wb.dst[1]=wr2; wb.KK[1]=8; wb.n[1]=n8;
    wb.src[2]=v_w;   wb.dst[2]=wv;  wb.KK[2]=1; wb.n[2]=n1;
    wb.src[3]=r3_w;  wb.dst[3]=wr3; wb.KK[3]=1; wb.n[3]=n1;
    wb.src[4]=proj_w;wb.dst[4]=wp;  wb.KK[4]=1; wb.n[4]=n1;

    wtrans_multi<<<cdiv(2*n27,256),256>>>(wa, bnst, 2*2*CD);
    wtrans_multi<<<cdiv(2*n8+3*n1,256),256>>>(wb, nullptr, 0);
    ln_kernel<<<MTOT, 128>>>(x, y1, n1g, n1b, nullptr, 1e-6f);

    Job jq  = { y1, wq,  nullptr, nullptr, qb };
    Job jr1 = { x,  wr1, x,       nullptr, a1 };
    conv_gemm_big<3,9><<<dim3(32,9,2), 256>>>(jq, jr1);
    reduce_split<9><<<MTOT*CD*2/256, 256>>>(jq, jr1);

    Job jk  = { y1, wk,  nullptr, nullptr, kb };
    Job jr2 = { a1, wr2, a1,      nullptr, a2 };
    conv_gemm_big<2,4><<<dim3(32,4,2), 256>>>(jk, jr2);
    reduce_split<4><<<MTOT*CD*2/256, 256>>>(jk, jr2);

    bn_stats<<<dim3(32,2), 256>>>(qb, kb);
    bn_apply<<<dim3(MTOT*CD/256,2), 256>>>(qb, kb, qbg, qbb, kbg, kbb);

    Job jv  = { y1, wv,  nullptr, nullptr, vb };
    Job jr3 = { a2, wr3, a2,      nullptr, a3 };
    conv_gemm_small<<<dim3(2,64,2), 128>>>(jv, jr3);

    flash_kernel<<<dim3(32,16), 128>>>(qb, kb, vb, attn);

    Job jp = { attn, wp, nullptr, proj_b, hb };
    conv_gemm_small<<<dim3(2,64,1), 128>>>(jp, jp);

    combine_ln<<<MTOT, 128>>>(a1, a2, a3, hb, n2g, n2b, x2, y2, xm);
    final_kernel<<<MTOT, 128>>>(x2, y2, xm, st1, st2, st3, out);
}

// round 14
// speedup vs baseline: 2.5426x; 1.1916x over previous
#include <cuda_runtime.h>
#include <cuda_bf16.h>
#include <cstdint>
#include <math.h>

#define CD 128
#define MTOT 4096

typedef unsigned long long u64;

__device__ __forceinline__ u64 pack2(float lo, float hi) {
    u64 r; asm("mov.b64 %0,{%1,%2};" : "=l"(r) : "f"(lo), "f"(hi)); return r;
}
__device__ __forceinline__ void fma2(u64& d, u64 a, u64 b) {
    asm("fma.rn.f32x2 %0,%1,%2,%0;" : "+l"(d) : "l"(a), "l"(b));
}
__device__ __forceinline__ void mul2(u64& d, u64 a) {
    asm("mul.rn.f32x2 %0,%0,%1;" : "+l"(d) : "l"(a));
}
__device__ __forceinline__ float2 unpack2(u64 v) {
    float2 f; asm("mov.b64 {%0,%1},%2;" : "=f"(f.x), "=f"(f.y) : "l"(v)); return f;
}

union F4U { float4 f; u64 u[2]; };

struct Job  { const float* in; const float* wt; const float* res; const float* bias; float* out; };
struct WJobs { const float* src[5]; float* dst[5]; int KK[5]; int n[5]; int nj; };
struct MJob { const __nv_bfloat16* inh; const __nv_bfloat16* inl;
              const __nv_bfloat16* wh;  const __nv_bfloat16* wl; };
struct RJob { const float* res; const float* bias; float* out;
              __nv_bfloat16* oh; __nv_bfloat16* ol; };
struct BWJob { const float* src; __nv_bfloat16* h; __nv_bfloat16* l; int KK; int n; };

__constant__ int4 c_tap3[27] = {
    {-1,-1,-1,0},{-1,-1,0,0},{-1,-1,1,0},{-1,0,-1,0},{-1,0,0,0},{-1,0,1,0},{-1,1,-1,0},{-1,1,0,0},{-1,1,1,0},
    { 0,-1,-1,0},{ 0,-1,0,0},{ 0,-1,1,0},{ 0,0,-1,0},{ 0,0,0,0},{ 0,0,1,0},{ 0,1,-1,0},{ 0,1,0,0},{ 0,1,1,0},
    { 1,-1,-1,0},{ 1,-1,0,0},{ 1,-1,1,0},{ 1,0,-1,0},{ 1,0,0,0},{ 1,0,1,0},{ 1,1,-1,0},{ 1,1,0,0},{ 1,1,1,0}
};
__constant__ int4 c_tap2[8] = {
    {-1,-1,-1,0},{-1,-1,0,0},{-1,0,-1,0},{-1,0,0,0},
    { 0,-1,-1,0},{ 0,-1,0,0},{ 0,0,-1,0},{ 0,0,0,0}
};

__device__ float g_y1[MTOT*CD], g_qb[MTOT*CD], g_kb[MTOT*CD], g_vb[MTOT*CD];
__device__ float g_attn[MTOT*CD], g_hb[MTOT*CD], g_a1[MTOT*CD], g_a2[MTOT*CD], g_a3[MTOT*CD];
__device__ float g_x2[MTOT*CD], g_y2[MTOT*CD], g_xm[MTOT];
__device__ float g_wv[CD*CD], g_wr3[CD*CD], g_wp[CD*CD];
__device__ float g_bnst[2][2][CD];
__device__ float g_part[9*2*MTOT*CD];
__device__ __nv_bfloat16 g_wqh[27*CD*CD], g_wql[27*CD*CD];
__device__ __nv_bfloat16 g_wr1h[27*CD*CD], g_wr1l[27*CD*CD];
__device__ __nv_bfloat16 g_wkh[8*CD*CD], g_wkl[8*CD*CD];
__device__ __nv_bfloat16 g_wr2h[8*CD*CD], g_wr2l[8*CD*CD];
__device__ __nv_bfloat16 g_y1h[MTOT*CD], g_y1l[MTOT*CD];
__device__ __nv_bfloat16 g_xh[MTOT*CD], g_xl[MTOT*CD];
__device__ __nv_bfloat16 g_a1h[MTOT*CD], g_a1l[MTOT*CD];

// ---------------- mma.sync helpers (sm_80+ path, legal on plain sm_100) ----------------
__device__ __forceinline__ uint32_t smem_u32(const void* p) {
    uint32_t a; asm("{ .reg .u64 t; cvta.to.shared.u64 t, %1; cvt.u32.u64 %0, t; }" : "=r"(a) : "l"(p));
    return a;
}
__device__ __forceinline__ void ldsm_x4(uint32_t* r, uint32_t a) {
    asm volatile("ldmatrix.sync.aligned.m8n8.x4.shared.b16 {%0,%1,%2,%3}, [%4];"
        : "=r"(r[0]), "=r"(r[1]), "=r"(r[2]), "=r"(r[3]) : "r"(a));
}
__device__ __forceinline__ void ldsm_x2(uint32_t* r, uint32_t a) {
    asm volatile("ldmatrix.sync.aligned.m8n8.x2.shared.b16 {%0,%1}, [%2];"
        : "=r"(r[0]), "=r"(r[1]) : "r"(a));
}
__device__ __forceinline__ void mma16816(float* d, const uint32_t* a, const uint32_t* b) {
    asm volatile("mma.sync.aligned.m16n8k16.row.col.f32.bf16.bf16.f32 "
        "{%0,%1,%2,%3},{%4,%5,%6,%7},{%8,%9},{%0,%1,%2,%3};"
        : "+f"(d[0]), "+f"(d[1]), "+f"(d[2]), "+f"(d[3])
        : "r"(a[0]), "r"(a[1]), "r"(a[2]), "r"(a[3]), "r"(b[0]), "r"(b[1]));
}

// ---------------- weight/bf16 prep ----------------
__global__ void wtrans_bf16(BWJob j0, BWJob j1, BWJob j2, BWJob j3,
                            const float* x, __nv_bfloat16* xh, __nv_bfloat16* xl, int nx,
                            float* zbuf, int zn) {
    int idx = blockIdx.x * 256 + threadIdx.x;
    if (zbuf && idx < zn) zbuf[idx] = 0.f;
    BWJob js[4] = {j0, j1, j2, j3};
    int base = 0;
    #pragma unroll
    for (int j = 0; j < 4; j++) {
        if (idx < base + js[j].n) {
            int t = idx - base;
            int K2 = js[j].KK * CD;
            int co = t / K2, k = t - co * K2;
            int tap = k >> 7, ci = k & 127;
            float v = js[j].src[(co*CD + ci) * js[j].KK + tap];
            __nv_bfloat16 h = __float2bfloat16(v);
            js[j].h[t] = h;
            js[j].l[t] = __float2bfloat16(v - __bfloat162float(h));
            return;
        }
        base += js[j].n;
    }
    int t = idx - base;
    if (t < nx) {
        float v = x[t];
        __nv_bfloat16 h = __float2bfloat16(v);
        xh[t] = h;
        xl[t] = __float2bfloat16(v - __bfloat162float(h));
    }
}

__global__ void wtrans_multi(WJobs J, float* zbuf, int zn) {
    int idx = blockIdx.x * 256 + threadIdx.x;
    if (zbuf && idx < zn) zbuf[idx] = 0.f;
    int base = 0;
    #pragma unroll
    for (int j = 0; j < 5; j++) {
        if (j >= J.nj) return;
        if (idx < base + J.n[j]) {
            int t = idx - base;
            int tap = t / (CD*CD); int rem = t - tap*(CD*CD);
            int ci = rem >> 7, co = rem & 127;
            J.dst[j][t] = J.src[j][(co*CD + ci)*J.KK[j] + tap];
            return;
        }
        base += J.n[j];
    }
}

__global__ void ln_kernel(const float* __restrict__ in, float* __restrict__ out,
                          const float* __restrict__ gam, const float* __restrict__ bet,
                          float* __restrict__ xm, float eps,
                          __nv_bfloat16* outh, __nv_bfloat16* outl) {
    int m = blockIdx.x, c = threadIdx.x, lane = c & 31, wid = c >> 5;
    float v = in[m*CD + c], s = v, sq = v*v;
    #pragma unroll
    for (int o = 16; o > 0; o >>= 1) { s += __shfl_xor_sync(~0u, s, o); sq += __shfl_xor_sync(~0u, sq, o); }
    __shared__ float ss[4], sqq[4], ys[4];
    if (lane == 0) { ss[wid] = s; sqq[wid] = sq; }
    __syncthreads();
    float S = ss[0]+ss[1]+ss[2]+ss[3], SQ = sqq[0]+sqq[1]+sqq[2]+sqq[3];
    float mean = S*(1.0f/CD), var = SQ*(1.0f/CD) - mean*mean, rs = rsqrtf(var + eps);
    float y = (v - mean)*rs*gam[c] + bet[c];
    out[m*CD + c] = y;
    if (outh) {
        __nv_bfloat16 h = __float2bfloat16(y);
        outh[m*CD + c] = h;
        outl[m*CD + c] = __float2bfloat16(y - __bfloat162float(h));
    }
    if (xm) {
        float t = y;
        #pragma unroll
        for (int o = 16; o > 0; o >>= 1) t += __shfl_xor_sync(~0u, t, o);
        if (lane == 0) ys[wid] = t;
        __syncthreads();
        if (c == 0) xm[m] = (ys[0]+ys[1]+ys[2]+ys[3])*(1.0f/CD);
    }
}

__global__ void bn_stats(const float* __restrict__ q, const float* __restrict__ k) {
    int buf = blockIdx.y;
    const float* src = buf ? k : q;
    int tid = threadIdx.x;
    int base = blockIdx.x * 128;
    float s = 0.f, sq = 0.f;
    for (int i = tid; i < 128*CD; i += 256) {
        float v = src[(base + (i >> 7))*CD + (i & 127)];
        s += v; sq += v*v;
    }
    __shared__ float sh[256];
    sh[tid] = s; __syncthreads();
    if (tid < 128) atomicAdd(&g_bnst[buf][0][tid], sh[tid] + sh[tid+128]);
    __syncthreads();
    sh[tid] = sq; __syncthreads();
    if (tid < 128) atomicAdd(&g_bnst[buf][1][tid], sh[tid] + sh[tid+128]);
}

__global__ void bn_apply(float* __restrict__ q, float* __restrict__ k,
                         const float* __restrict__ qg, const float* __restrict__ qb2,
                         const float* __restrict__ kg, const float* __restrict__ kb2) {
    int buf = blockIdx.y;
    float* dst = buf ? k : q;
    const float* gam = buf ? kg : qg;
    const float* bet = buf ? kb2 : qb2;
    int idx = blockIdx.x * 256 + threadIdx.x;
    int c = idx & 127;
    float S = g_bnst[buf][0][c], SQ = g_bnst[buf][1][c];
    float mean = S*(1.0f/MTOT), var = SQ*(1.0f/MTOT) - mean*mean;
    float sc = gam[c]*rsqrtf(var + 1e-5f), sh = bet[c] - mean*sc;
    dst[idx] = dst[idx]*sc + sh;
}

// ---------- HMMA bf16 hi/lo conv: BM=128 BN=128 BK=32, 3 K-sections, split-K ----------
template<int KS, int SPLIT>
__global__ __launch_bounds__(256, 2) void conv_mma(MJob j0, MJob j1) {
    constexpr int K = KS*KS*KS*CD;
    constexpr int KSP = K / SPLIT;
    constexpr int NIT = KSP / 32;
    constexpr int TOT = NIT * 3;
    const int job = blockIdx.z, split = blockIdx.y;
    MJob jb = job ? j1 : j0;
    const int m0 = blockIdx.x << 7;
    const int kbase = split * KSP;
    __shared__ __align__(16) __nv_bfloat16 As[128][40];   // 80B row stride: ldmatrix conflict-free
    __shared__ __align__(16) __nv_bfloat16 Bs[128][40];
    const int tid = threadIdx.x, warp = tid >> 5, lane = tid & 31;
    const int wm = warp >> 2, wn = warp & 3;              // warp tile: rows wm*64.., cols wn*32..

    const int r0 = tid >> 2, q0 = tid & 3;
    int gm0 = m0 + r0, gm1 = m0 + r0 + 64;
    int bb0 = gm0 >> 11, p0 = gm0 & 2047;
    int tt0 = p0 >> 4, ii0 = (p0 >> 2) & 3, jj0 = p0 & 3;
    int bb1 = gm1 >> 11, p1 = gm1 & 2047;
    int tt1 = p1 >> 4, ii1 = (p1 >> 2) & 3, jj1 = p1 & 3;

    float acc[4][4][4];
    #pragma unroll
    for (int mf = 0; mf < 4; mf++)
        #pragma unroll
        for (int nf = 0; nf < 4; nf++)
            #pragma unroll
            for (int r = 0; r < 4; r++) acc[mf][nf][r] = 0.f;

    uint32_t abase = smem_u32(As), bbase = smem_u32(Bs);
    uint32_t aAddr[4][2], bAddr[4][2];
    #pragma unroll
    for (int mf = 0; mf < 4; mf++) {
        int arow = wm*64 + mf*16 + (lane & 7) + ((lane >> 3) & 1) * 8;
        int acol = ((lane >> 4) << 3);
        #pragma unroll
        for (int kk = 0; kk < 2; kk++)
            aAddr[mf][kk] = abase + (arow*40 + kk*16 + acol) * 2;
    }
    #pragma unroll
    for (int nf = 0; nf < 4; nf++) {
        int l = lane & 15;
        int brow = wn*32 + nf*8 + (l & 7);
        int bcol = ((l >> 3) << 3);
        #pragma unroll
        for (int kk = 0; kk < 2; kk++)
            bAddr[nf][kk] = bbase + (brow*40 + kk*16 + bcol) * 2;
    }

    const uint4 zero4 = make_uint4(0u,0u,0u,0u);
    for (int it = 0; it < TOT; it++) {
        int sec = it / NIT, itk = it - sec*NIT;
        int kc = kbase + itk*32;
        const __nv_bfloat16* Ap = (sec == 1) ? jb.inl : jb.inh;
        const __nv_bfloat16* Bp = (sec == 2) ? jb.wl  : jb.wh;
        int tap = kc >> 7;
        int4 d = (KS == 3) ? c_tap3[tap] : c_tap2[tap];
        int ci0 = (kc & 127) + q0*8;
        uint4 a0v, a1v, b0v, b1v;
        {
            int t2 = tt0 + d.x, i2 = ii0 + d.y, j2 = jj0 + d.z;
            bool v = ((unsigned)t2 < 128u) & ((unsigned)i2 < 4u) & ((unsigned)j2 < 4u);
            size_t off = ((size_t)((bb0<<11) + (t2<<4) + (i2<<2) + j2) << 7) + ci0;
            a0v = v ? *(const uint4*)(Ap + off) : zero4;
        }
        {
            int t2 = tt1 + d.x, i2 = ii1 + d.y, j2 = jj1 + d.z;
            bool v = ((unsigned)t2 < 128u) & ((unsigned)i2 < 4u) & ((unsigned)j2 < 4u);
            size_t off = ((size_t)((bb1<<11) + (t2<<4) + (i2<<2) + j2) << 7) + ci0;
            a1v = v ? *(const uint4*)(Ap + off) : zero4;
        }
        b0v = *(const uint4*)(Bp + (size_t)r0*K + kc + q0*8);
        b1v = *(const uint4*)(Bp + (size_t)(r0+64)*K + kc + q0*8);
        __syncthreads();
        *(uint4*)&As[r0][q0*8]      = a0v;
        *(uint4*)&As[r0+64][q0*8]   = a1v;
        *(uint4*)&Bs[r0][q0*8]      = b0v;
        *(uint4*)&Bs[r0+64][q0*8]   = b1v;
        __syncthreads();
        #pragma unroll
        for (int kk = 0; kk < 2; kk++) {
            uint32_t af[4][4], bf[4][2];
            #pragma unroll
            for (int mf = 0; mf < 4; mf++) ldsm_x4(af[mf], aAddr[mf][kk]);
            #pragma unroll
            for (int nf = 0; nf < 4; nf++) ldsm_x2(bf[nf], bAddr[nf][kk]);
            #pragma unroll
            for (int mf = 0; mf < 4; mf++)
                #pragma unroll
                for (int nf = 0; nf < 4; nf++)
                    mma16816(acc[mf][nf], af[mf], bf[nf]);
        }
    }

    float* pb = g_part + ((size_t)(split*2 + job) << 19);
    #pragma unroll
    for (int mf = 0; mf < 4; mf++) {
        int row = m0 + wm*64 + mf*16 + (lane >> 2);
        #pragma unroll
        for (int nf = 0; nf < 4; nf++) {
            int col = wn*32 + nf*8 + (lane & 3)*2;
            *(float2*)(pb + (size_t)row*CD + col)     = make_float2(acc[mf][nf][0], acc[mf][nf][1]);
            *(float2*)(pb + (size_t)(row+8)*CD + col) = make_float2(acc[mf][nf][2], acc[mf][nf][3]);
        }
    }
}

template<int SPLIT>
__global__ void reduce_split(RJob j0, RJob j1) {
    int idx = blockIdx.x * 256 + threadIdx.x;
    int job = idx >> 19, r = idx & ((1 << 19) - 1);
    RJob jb = job ? j1 : j0;
    float s = 0.f;
    #pragma unroll
    for (int sp = 0; sp < SPLIT; sp++)
        s += g_part[((size_t)(sp*2 + job) << 19) + r];
    if (jb.bias) s += jb.bias[r & 127];
    if (jb.res)  s += jb.res[r];
    jb.out[r] = s;
    if (jb.oh) {
        __nv_bfloat16 h = __float2bfloat16(s);
        jb.oh[r] = h;
        jb.ol[r] = __float2bfloat16(s - __bfloat162float(h));
    }
}

// ---------------- small conv (KS=1 paths), unchanged ----------------
__global__ __launch_bounds__(128, 4) void conv_gemm_small(Job j0, Job j1) {
    constexpr int K = CD;
    constexpr int NIT = K / 16;
    Job jb = (blockIdx.z == 0) ? j0 : j1;
    const int m0 = blockIdx.y << 6, n0 = blockIdx.x << 6;
    __shared__ float As[2][16][64], Bs[2][16][64];
    const int tid = threadIdx.x;
    const int am = tid & 63, kgA = tid >> 6;
    const int gm = m0 + am;
    const int br = tid >> 4, bc = (tid & 15) << 2;
    const int warp = tid >> 5, lane = tid & 31;
    const int ty = lane >> 2;
    const int tx = (warp << 2) + (lane & 3);
    u64 acc[4][4];
    #pragma unroll
    for (int r = 0; r < 4; r++)
        #pragma unroll
        for (int c = 0; c < 4; c++) acc[r][c] = 0ull;

    auto ldA = [&](int kgabs) -> float4 {
        int ci = (kgabs << 2) & 127;
        return *(const float4*)(jb.in + ((size_t)gm << 7) + ci);
    };
    {
        float4 a0 = ldA(kgA), a1 = ldA(kgA + 2);
        float4 b0 = *(const float4*)(jb.wt + (size_t)br*CD + n0 + bc);
        float4 b1 = *(const float4*)(jb.wt + (size_t)(br+8)*CD + n0 + bc);
        int k4 = kgA << 2;
        As[0][k4+0][am]=a0.x; As[0][k4+1][am]=a0.y; As[0][k4+2][am]=a0.z; As[0][k4+3][am]=a0.w;
        As[0][k4+8][am]=a1.x; As[0][k4+9][am]=a1.y; As[0][k4+10][am]=a1.z; As[0][k4+11][am]=a1.w;
        *(float4*)&Bs[0][br][bc]   = b0;
        *(float4*)&Bs[0][br+8][bc] = b1;
    }
    __syncthreads();

    for (int it = 0; it < NIT; it++) {
        int s = it & 1;
        float4 na0, na1, nb0, nb1;
        bool more = (it + 1 < NIT);
        if (more) {
            int kg = (it+1)*4;
            na0 = ldA(kg + kgA); na1 = ldA(kg + kgA + 2);
            nb0 = *(const float4*)(jb.wt + (size_t)((it+1)*16 + br)*CD + n0 + bc);
            nb1 = *(const float4*)(jb.wt + (size_t)((it+1)*16 + br + 8)*CD + n0 + bc);
        }
        #pragma unroll
        for (int kk = 0; kk < 16; kk++) {
            F4U u0, u1;
            u0.f = *(const float4*)&As[s][kk][ty << 3];
            u1.f = *(const float4*)(&As[s][kk][ty << 3] + 4);
            u64 ap[4] = {u0.u[0], u0.u[1], u1.u[0], u1.u[1]};
            float4 bq = *(const float4*)&Bs[s][kk][tx << 2];
            u64 b0 = pack2(bq.x, bq.x), b1 = pack2(bq.y, bq.y);
            u64 b2 = pack2(bq.z, bq.z), b3 = pack2(bq.w, bq.w);
            #pragma unroll
            for (int r = 0; r < 4; r++) {
                fma2(acc[r][0], ap[r], b0);
                fma2(acc[r][1], ap[r], b1);
                fma2(acc[r][2], ap[r], b2);
                fma2(acc[r][3], ap[r], b3);
            }
        }
        if (more) {
            int so = s ^ 1, k4 = kgA << 2;
            As[so][k4+0][am]=na0.x; As[so][k4+1][am]=na0.y; As[so][k4+2][am]=na0.z; As[so][k4+3][am]=na0.w;
            As[so][k4+8][am]=na1.x; As[so][k4+9][am]=na1.y; As[so][k4+10][am]=na1.z; As[so][k4+11][am]=na1.w;
            *(float4*)&Bs[so][br][bc]   = nb0;
            *(float4*)&Bs[so][br+8][bc] = nb1;
            __syncthreads();
        }
    }

    int c0 = n0 + (tx << 2);
    float4 bias4 = make_float4(0.f,0.f,0.f,0.f);
    if (jb.bias) bias4 = *(const float4*)(jb.bias + c0);
    #pragma unroll
    for (int rp = 0; rp < 4; rp++) {
        float2 p0 = unpack2(acc[rp][0]), p1 = unpack2(acc[rp][1]);
        float2 p2 = unpack2(acc[rp][2]), p3 = unpack2(acc[rp][3]);
        int mA = m0 + (ty << 3) + (rp << 1), mB = mA + 1;
        float4 oA = make_float4(p0.x+bias4.x, p1.x+bias4.y, p2.x+bias4.z, p3.x+bias4.w);
        float4 oB = make_float4(p0.y+bias4.x, p1.y+bias4.y, p2.y+bias4.z, p3.y+bias4.w);
        if (jb.res) {
            float4 rA = *(const float4*)(jb.res + (size_t)mA*CD + c0);
            float4 rB = *(const float4*)(jb.res + (size_t)mB*CD + c0);
            oA.x += rA.x; oA.y += rA.y; oA.z += rA.z; oA.w += rA.w;
            oB.x += rB.x; oB.y += rB.y; oB.z += rB.z; oB.w += rB.w;
        }
        *(float4*)(jb.out + (size_t)mA*CD + c0) = oA;
        *(float4*)(jb.out + (size_t)mB*CD + c0) = oB;
    }
}

// ---------------- flash (unchanged, passing) ----------------
__global__ void flash_kernel(const float* __restrict__ q, const float* __restrict__ k,
                             const float* __restrict__ v, float* __restrict__ out) {
    const float LOG2E = 1.4426950408889634f;
    int bh = blockIdx.y, b = bh >> 3, h = bh & 7;
    int qbase = blockIdx.x << 6;
    __shared__ float4 ks[128][5], vs[128][5];
    int tid = threadIdx.x, wid = tid >> 5, lane = tid & 31;
    int r = lane >> 2, g = lane & 3;
    int rowA = qbase + (wid << 4) + r, rowB = rowA + 8;
    const float* qpA = q + (((b<<11) + rowA) << 7) + (h << 4);
    const float* qpB = q + (((b<<11) + rowB) << 7) + (h << 4);
    u64 qa[8], qb2[8];
    #pragma unroll
    for (int j = 0; j < 4; j++) {
        float4 ta = *(const float4*)(qpA + j*4);
        float4 tb = *(const float4*)(qpB + j*4);
        qa[j*2]   = pack2(ta.x*LOG2E, ta.y*LOG2E);
        qa[j*2+1] = pack2(ta.z*LOG2E, ta.w*LOG2E);
        qb2[j*2]   = pack2(tb.x*LOG2E, tb.y*LOG2E);
        qb2[j*2+1] = pack2(tb.z*LOG2E, tb.w*LOG2E);
    }
    u64 accA[8], accB[8];
    #pragma unroll
    for (int d = 0; d < 8; d++) { accA[d] = 0ull; accB[d] = 0ull; }
    float mA = -1e30f, mB = -1e30f, lsA = 0.f, lsB = 0.f;
    const float* kbase = k + (((size_t)b << 11) << 7) + (h << 4);
    const float* vbase = v + (((size_t)b << 11) << 7) + (h << 4);

    for (int kt = 0; kt < 2048; kt += 128) {
        __syncthreads();
        #pragma unroll
        for (int u = 0; u < 4; u++) {
            int li = tid + (u << 7);
            int row = li >> 2, j = li & 3;
            ks[row][j] = *(const float4*)(kbase + (size_t)(kt+row)*CD + (j<<2));
            vs[row][j] = *(const float4*)(vbase + (size_t)(kt+row)*CD + (j<<2));
        }
        __syncthreads();
        #pragma unroll
        for (int ch = 0; ch < 4; ch++) {
            float sA[8], sB[8];
            float tmA = -1e30f, tmB = -1e30f;
            #pragma unroll
            for (int i = 0; i < 8; i++) {
                int kc = (ch << 5) + (i << 2) + g;
                F4U k0, k1, k2, k3;
                k0.f = ks[kc][0]; k1.f = ks[kc][1]; k2.f = ks[kc][2]; k3.f = ks[kc][3];
                u64 dA = 0ull, dB = 0ull;
                fma2(dA, qa[0], k0.u[0]); fma2(dA, qa[1], k0.u[1]);
                fma2(dA, qa[2], k1.u[0]); fma2(dA, qa[3], k1.u[1]);
                fma2(dA, qa[4], k2.u[0]); fma2(dA, qa[5], k2.u[1]);
                fma2(dA, qa[6], k3.u[0]); fma2(dA, qa[7], k3.u[1]);
                fma2(dB, qb2[0], k0.u[0]); fma2(dB, qb2[1], k0.u[1]);
                fma2(dB, qb2[2], k1.u[0]); fma2(dB, qb2[3], k1.u[1]);
                fma2(dB, qb2[4], k2.u[0]); fma2(dB, qb2[5], k2.u[1]);
                fma2(dB, qb2[6], k3.u[0]); fma2(dB, qb2[7], k3.u[1]);
                float2 fa = unpack2(dA), fb = unpack2(dB);
                sA[i] = fa.x + fa.y; sB[i] = fb.x + fb.y;
                tmA = fmaxf(tmA, sA[i]); tmB = fmaxf(tmB, sB[i]);
            }
            tmA = fmaxf(tmA, __shfl_xor_sync(~0u, tmA, 1));
            tmA = fmaxf(tmA, __shfl_xor_sync(~0u, tmA, 2));
            tmB = fmaxf(tmB, __shfl_xor_sync(~0u, tmB, 1));
            tmB = fmaxf(tmB, __shfl_xor_sync(~0u, tmB, 2));
            float nA = fmaxf(mA, tmA), nB = fmaxf(mB, tmB);
            float cA = exp2f(mA - nA), cB = exp2f(mB - nB);
            mA = nA; mB = nB; lsA *= cA; lsB *= cB;
            u64 cA2 = pack2(cA, cA), cB2 = pack2(cB, cB);
            #pragma unroll
            for (int d = 0; d < 8; d++) { mul2(accA[d], cA2); mul2(accB[d], cB2); }
            #pragma unroll
            for (int i = 0; i < 8; i++) {
                int kc = (ch << 5) + (i << 2) + g;
                float pA = exp2f(sA[i] - mA), pB = exp2f(sB[i] - mB);
                lsA += pA; lsB += pB;
                u64 pA2 = pack2(pA, pA), pB2 = pack2(pB, pB);
                F4U v0, v1, v2, v3;
                v0.f = vs[kc][0]; v1.f = vs[kc][1]; v2.f = vs[kc][2]; v3.f = vs[kc][3];
                fma2(accA[0], pA2, v0.u[0]); fma2(accA[1], pA2, v0.u[1]);
                fma2(accA[2], pA2, v1.u[0]); fma2(accA[3], pA2, v1.u[1]);
                fma2(accA[4], pA2, v2.u[0]); fma2(accA[5], pA2, v2.u[1]);
                fma2(accA[6], pA2, v3.u[0]); fma2(accA[7], pA2, v3.u[1]);
                fma2(accB[0], pB2, v0.u[0]); fma2(accB[1], pB2, v0.u[1]);
                fma2(accB[2], pB2, v1.u[0]); fma2(accB[3], pB2, v1.u[1]);
                fma2(accB[4], pB2, v2.u[0]); fma2(accB[5], pB2, v2.u[1]);
                fma2(accB[6], pB2, v3.u[0]); fma2(accB[7], pB2, v3.u[1]);
            }
        }
    }
    float aA[16], aB[16];
    #pragma unroll
    for (int d = 0; d < 8; d++) {
        float2 fa = unpack2(accA[d]), fb = unpack2(accB[d]);
        aA[d*2] = fa.x; aA[d*2+1] = fa.y;
        aB[d*2] = fb.x; aB[d*2+1] = fb.y;
    }
    #pragma unroll
    for (int d = 0; d < 16; d++) {
        aA[d] += __shfl_xor_sync(~0u, aA[d], 1);
        aA[d] += __shfl_xor_sync(~0u, aA[d], 2);
        aB[d] += __shfl_xor_sync(~0u, aB[d], 1);
        aB[d] += __shfl_xor_sync(~0u, aB[d], 2);
    }
    lsA += __shfl_xor_sync(~0u, lsA, 1); lsA += __shfl_xor_sync(~0u, lsA, 2);
    lsB += __shfl_xor_sync(~0u, lsB, 1); lsB += __shfl_xor_sync(~0u, lsB, 2);
    float invA = 1.0f / lsA, invB = 1.0f / lsB;
    #pragma unroll
    for (int rr = 0; rr < 2; rr++) {
        int qrow = rr ? rowB : rowA;
        float inv = rr ? invB : invA;
        float* ac = rr ? aB : aA;
        size_t base = ((size_t)((b<<11) + qrow) << 7) + (h << 4);
        float ov[4];
        #pragma unroll
        for (int u = 0; u < 4; u++) {
            int w2 = (g << 2) + u;
            float ca = 0.f;
            #pragma unroll
            for (int s2 = 0; s2 < 3; s2++) {
                int f = w2 + (s2 << 4);
                int sel = f % 3;
                const float* tp = (sel == 0) ? q : ((sel == 1) ? k : v);
                ca += tp[base + f/3];
            }
            ov[u] = ac[(g<<2)+u]*inv + ca*(1.0f/3.0f);
        }
        *(float4*)(out + base + (g << 2)) = make_float4(ov[0], ov[1], ov[2], ov[3]);
    }
}

__global__ void combine_ln(const float* __restrict__ a1, const float* __restrict__ a2,
                           const float* __restrict__ a3, const float* __restrict__ hh,
                           const float* __restrict__ gam, const float* __restrict__ bet,
                           float* __restrict__ x2, float* __restrict__ y2,
                           float* __restrict__ xm) {
    int m = blockIdx.x, c = threadIdx.x, lane = c & 31, wid = c >> 5;
    float sacc = 0.f;
    #pragma unroll
    for (int s2 = 0; s2 < 3; s2++) {
        int f = c*3 + s2;
        const float* ap = (f >> 7) == 0 ? a1 : ((f >> 7) == 1 ? a2 : a3);
        sacc += ap[(m << 7) + (f & 127)];
    }
    float v = sacc*(1.0f/3.0f) + hh[m*CD + c];
    x2[m*CD + c] = v;
    float s = v, sq = v*v;
    #pragma unroll
    for (int o = 16; o > 0; o >>= 1) { s += __shfl_xor_sync(~0u, s, o); sq += __shfl_xor_sync(~0u, sq, o); }
    __shared__ float ss[4], sqq[4], ys[4];
    if (lane == 0) { ss[wid] = s; sqq[wid] = sq; }
    __syncthreads();
    float S = ss[0]+ss[1]+ss[2]+ss[3], SQ = sqq[0]+sqq[1]+sqq[2]+sqq[3];
    float mean = S*(1.0f/CD), var = SQ*(1.0f/CD) - mean*mean, rs = rsqrtf(var + 1e-6f);
    float y = (v - mean)*rs*gam[c] + bet[c];
    y2[m*CD + c] = y;
    float t = y;
    #pragma unroll
    for (int o = 16; o > 0; o >>= 1) t += __shfl_xor_sync(~0u, t, o);
    if (lane == 0) ys[wid] = t;
    __syncthreads();
    if (c == 0) xm[m] = (ys[0]+ys[1]+ys[2]+ys[3])*(1.0f/CD);
}

__global__ void final_kernel(const float* __restrict__ x2, const float* __restrict__ y2,
                             const float* __restrict__ xm, const float* __restrict__ st1,
                             const float* __restrict__ st2, const float* __restrict__ st3,
                             float* __restrict__ out) {
    int m = blockIdx.x, b = m >> 11, p = m & 2047;
    int t = p >> 4, ii = (p >> 2) & 3, jj = p & 3;
    __shared__ float sg;
    if (threadIdx.x == 0) {
        float gg = st1[0] * xm[m];
        #pragma unroll
        for (int kd = 0; kd < 2; kd++)
        for (int kh = 0; kh < 2; kh++)
        for (int kw = 0; kw < 2; kw++) {
            int t2 = t + kd - 1, i2 = ii + kh - 1, j2 = jj + kw - 1;
            if ((unsigned)t2 < 128u && (unsigned)i2 < 4u && (unsigned)j2 < 4u)
                gg += st2[kd*4 + kh*2 + kw] * xm[(b<<11) + (t2<<4) + (i2<<2) + j2];
        }
        #pragma unroll
        for (int kd = 0; kd < 3; kd++)
        for (int kh = 0; kh < 3; kh++)
        for (int kw = 0; kw < 3; kw++) {
            int t2 = t + kd - 1, i2 = ii + kh - 1, j2 = jj + kw - 1;
            if ((unsigned)t2 < 128u && (unsigned)i2 < 4u && (unsigned)j2 < 4u)
                gg += st3[kd*9 + kh*3 + kw] * xm[(b<<11) + (t2<<4) + (i2<<2) + j2];
        }
        sg = 1.0f / (1.0f + __expf(-gg));
    }
    __syncthreads();
    int idx = m*CD + threadIdx.x;
    out[idx] = x2[idx] + y2[idx]*sg;
}

extern "C" void kernel_launch(void* const* d_in, const int* in_sizes, int n_in,
                              void* d_out, int out_size) {
    const float* x      = (const float*)d_in[0];
    const float* n1g    = (const float*)d_in[1];
    const float* n1b    = (const float*)d_in[2];
    const float* q_w    = (const float*)d_in[3];
    const float* qbg    = (const float*)d_in[4];
    const float* qbb    = (const float*)d_in[5];
    const float* k_w    = (const float*)d_in[6];
    const float* kbg    = (const float*)d_in[7];
    const float* kbb    = (const float*)d_in[8];
    const float* v_w    = (const float*)d_in[9];
    const float* proj_w = (const float*)d_in[10];
    const float* proj_b = (const float*)d_in[11];
    const float* r1_w   = (const float*)d_in[12];
    const float* r2_w   = (const float*)d_in[13];
    const float* r3_w   = (const float*)d_in[14];
    const float* n2g    = (const float*)d_in[15];
    const float* n2b    = (const float*)d_in[16];
    const float* st1    = (const float*)d_in[17];
    const float* st2    = (const float*)d_in[18];
    const float* st3    = (const float*)d_in[19];
    float* out = (float*)d_out;

    float *y1,*qb,*kb,*vb,*attn,*hb,*a1,*a2,*a3,*x2,*y2,*xm;
    float *wv,*wr3,*wp,*bnst;
    __nv_bfloat16 *wqh,*wql,*wr1h,*wr1l,*wkh,*wkl,*wr2h,*wr2l;
    __nv_bfloat16 *y1h,*y1l,*xh,*xl,*a1h,*a1l;
    cudaGetSymbolAddress((void**)&y1, g_y1);     cudaGetSymbolAddress((void**)&qb, g_qb);
    cudaGetSymbolAddress((void**)&kb, g_kb);     cudaGetSymbolAddress((void**)&vb, g_vb);
    cudaGetSymbolAddress((void**)&attn, g_attn); cudaGetSymbolAddress((void**)&hb, g_hb);
    cudaGetSymbolAddress((void**)&a1, g_a1);     cudaGetSymbolAddress((void**)&a2, g_a2);
    cudaGetSymbolAddress((void**)&a3, g_a3);     cudaGetSymbolAddress((void**)&x2, g_x2);
    cudaGetSymbolAddress((void**)&y2, g_y2);     cudaGetSymbolAddress((void**)&xm, g_xm);
    cudaGetSymbolAddress((void**)&wv, g_wv);     cudaGetSymbolAddress((void**)&wr3, g_wr3);
    cudaGetSymbolAddress((void**)&wp, g_wp);     cudaGetSymbolAddress((void**)&bnst, g_bnst);
    cudaGetSymbolAddress((void**)&wqh, g_wqh);   cudaGetSymbolAddress((void**)&wql, g_wql);
    cudaGetSymbolAddress((void**)&wr1h, g_wr1h); cudaGetSymbolAddress((void**)&wr1l, g_wr1l);
    cudaGetSymbolAddress((void**)&wkh, g_wkh);   cudaGetSymbolAddress((void**)&wkl, g_wkl);
    cudaGetSymbolAddress((void**)&wr2h, g_wr2h); cudaGetSymbolAddress((void**)&wr2l, g_wr2l);
    cudaGetSymbolAddress((void**)&y1h, g_y1h);   cudaGetSymbolAddress((void**)&y1l, g_y1l);
    cudaGetSymbolAddress((void**)&xh, g_xh);     cudaGetSymbolAddress((void**)&xl, g_xl);
    cudaGetSymbolAddress((void**)&a1h, g_a1h);   cudaGetSymbolAddress((void**)&a1l, g_a1l);

    auto cdiv = [](int a, int b){ return (a + b - 1) / b; };
    const int n27 = 27*CD*CD, n8 = 8*CD*CD, n1 = CD*CD, nx = MTOT*CD;

    BWJob bq  = { q_w,  wqh,  wql,  27, n27 };
    BWJob br1 = { r1_w, wr1h, wr1l, 27, n27 };
    BWJob bk  = { k_w,  wkh,  wkl,  8,  n8  };
    BWJob br2 = { r2_w, wr2h, wr2l, 8,  n8  };
    WJobs ws = {};
    ws.nj = 3;
    ws.src[0]=v_w;   ws.dst[0]=wv;  ws.KK[0]=1; ws.n[0]=n1;
    ws.src[1]=r3_w;  ws.dst[1]=wr3; ws.KK[1]=1; ws.n[1]=n1;
    ws.src[2]=proj_w;ws.dst[2]=wp;  ws.KK[2]=1; ws.n[2]=n1;

    wtrans_bf16<<<cdiv(2*n27 + 2*n8 + nx, 256), 256>>>(bq, br1, bk, br2, x, xh, xl, nx, bnst, 2*2*CD);
    wtrans_multi<<<cdiv(3*n1, 256), 256>>>(ws, nullptr, 0);
    ln_kernel<<<MTOT, 128>>>(x, y1, n1g, n1b, nullptr, 1e-6f, y1h, y1l);

    MJob mq  = { y1h, y1l, wqh,  wql  };
    MJob mr1 = { xh,  xl,  wr1h, wr1l };
    conv_mma<3,4><<<dim3(32,4,2), 256>>>(mq, mr1);
    RJob rq  = { nullptr, nullptr, qb, nullptr, nullptr };
    RJob rr1 = { x,       nullptr, a1, a1h,     a1l     };
    reduce_split<4><<<MTOT*CD*2/256, 256>>>(rq, rr1);

    MJob mk  = { y1h, y1l, wkh,  wkl  };
    MJob mr2 = { a1h, a1l, wr2h, wr2l };
    conv_mma<2,4><<<dim3(32,4,2), 256>>>(mk, mr2);
    RJob rk  = { nullptr, nullptr, kb, nullptr, nullptr };
    RJob rr2 = { a1,      nullptr, a2, nullptr, nullptr };
    reduce_split<4><<<MTOT*CD*2/256, 256>>>(rk, rr2);

    bn_stats<<<dim3(32,2), 256>>>(qb, kb);
    bn_apply<<<dim3(MTOT*CD/256,2), 256>>>(qb, kb, qbg, qbb, kbg, kbb);

    Job jv  = { y1, wv,  nullptr, nullptr, vb };
    Job jr3 = { a2, wr3, a2,      nullptr, a3 };
    conv_gemm_small<<<dim3(2,64,2), 128>>>(jv, jr3);

    flash_kernel<<<dim3(32,16), 128>>>(qb, kb, vb, attn);

    Job jp = { attn, wp, nullptr, proj_b, hb };
    conv_gemm_small<<<dim3(2,64,1), 128>>>(jp, jp);

    combine_ln<<<MTOT, 128>>>(a1, a2, a3, hb, n2g, n2b, x2, y2, xm);
    final_kernel<<<MTOT, 128>>>(x2, y2, xm, st1, st2, st3, out);
}

// round 15
// speedup vs baseline: 2.6471x; 1.0411x over previous
#include <cuda_runtime.h>
#include <cuda_bf16.h>
#include <cstdint>
#include <math.h>

#define CD 128
#define MTOT 4096

typedef unsigned long long u64;

__device__ __forceinline__ u64 pack2(float lo, float hi) {
    u64 r; asm("mov.b64 %0,{%1,%2};" : "=l"(r) : "f"(lo), "f"(hi)); return r;
}
__device__ __forceinline__ void fma2(u64& d, u64 a, u64 b) {
    asm("fma.rn.f32x2 %0,%1,%2,%0;" : "+l"(d) : "l"(a), "l"(b));
}
__device__ __forceinline__ void mul2(u64& d, u64 a) {
    asm("mul.rn.f32x2 %0,%0,%1;" : "+l"(d) : "l"(a));
}
__device__ __forceinline__ float2 unpack2(u64 v) {
    float2 f; asm("mov.b64 {%0,%1},%2;" : "=f"(f.x), "=f"(f.y) : "l"(v)); return f;
}

union F4U { float4 f; u64 u[2]; };

struct Job  { const float* in; const float* wt; const float* res; const float* bias; float* out; };
struct WJobs { const float* src[5]; float* dst[5]; int KK[5]; int n[5]; int nj; };
struct MJob { const __nv_bfloat16* inh; const __nv_bfloat16* inl;
              const __nv_bfloat16* wh;  const __nv_bfloat16* wl; };
struct RJob { const float* res; const float* bias; float* out;
              __nv_bfloat16* oh; __nv_bfloat16* ol; };
struct BWJob { const float* src; __nv_bfloat16* h; __nv_bfloat16* l; int KK; int n; };

__constant__ int4 c_tap3[27] = {
    {-1,-1,-1,0},{-1,-1,0,0},{-1,-1,1,0},{-1,0,-1,0},{-1,0,0,0},{-1,0,1,0},{-1,1,-1,0},{-1,1,0,0},{-1,1,1,0},
    { 0,-1,-1,0},{ 0,-1,0,0},{ 0,-1,1,0},{ 0,0,-1,0},{ 0,0,0,0},{ 0,0,1,0},{ 0,1,-1,0},{ 0,1,0,0},{ 0,1,1,0},
    { 1,-1,-1,0},{ 1,-1,0,0},{ 1,-1,1,0},{ 1,0,-1,0},{ 1,0,0,0},{ 1,0,1,0},{ 1,1,-1,0},{ 1,1,0,0},{ 1,1,1,0}
};
__constant__ int4 c_tap2[8] = {
    {-1,-1,-1,0},{-1,-1,0,0},{-1,0,-1,0},{-1,0,0,0},
    { 0,-1,-1,0},{ 0,-1,0,0},{ 0,0,-1,0},{ 0,0,0,0}
};

__device__ float g_y1[MTOT*CD], g_qb[MTOT*CD], g_kb[MTOT*CD], g_vb[MTOT*CD];
__device__ float g_attn[MTOT*CD], g_hb[MTOT*CD], g_a1[MTOT*CD], g_a2[MTOT*CD], g_a3[MTOT*CD];
__device__ float g_x2[MTOT*CD], g_y2[MTOT*CD], g_xm[MTOT];
__device__ float g_wv[CD*CD], g_wr3[CD*CD], g_wp[CD*CD];
__device__ float g_bnst[2][2][CD];
__device__ float g_part[9*2*MTOT*CD];
__device__ __nv_bfloat16 g_wqh[27*CD*CD], g_wql[27*CD*CD];
__device__ __nv_bfloat16 g_wr1h[27*CD*CD], g_wr1l[27*CD*CD];
__device__ __nv_bfloat16 g_wkh[8*CD*CD], g_wkl[8*CD*CD];
__device__ __nv_bfloat16 g_wr2h[8*CD*CD], g_wr2l[8*CD*CD];
__device__ __nv_bfloat16 g_y1h[MTOT*CD], g_y1l[MTOT*CD];
__device__ __nv_bfloat16 g_xh[MTOT*CD], g_xl[MTOT*CD];
__device__ __nv_bfloat16 g_a1h[MTOT*CD], g_a1l[MTOT*CD];

// ---------------- mma.sync helpers (sm_80+ path, legal on plain sm_100) ----------------
__device__ __forceinline__ uint32_t smem_u32(const void* p) {
    uint32_t a; asm("{ .reg .u64 t; cvta.to.shared.u64 t, %1; cvt.u32.u64 %0, t; }" : "=r"(a) : "l"(p));
    return a;
}
__device__ __forceinline__ void ldsm_x4(uint32_t* r, uint32_t a) {
    asm volatile("ldmatrix.sync.aligned.m8n8.x4.shared.b16 {%0,%1,%2,%3}, [%4];"
        : "=r"(r[0]), "=r"(r[1]), "=r"(r[2]), "=r"(r[3]) : "r"(a));
}
__device__ __forceinline__ void ldsm_x2(uint32_t* r, uint32_t a) {
    asm volatile("ldmatrix.sync.aligned.m8n8.x2.shared.b16 {%0,%1}, [%2];"
        : "=r"(r[0]), "=r"(r[1]) : "r"(a));
}
__device__ __forceinline__ void mma16816(float* d, const uint32_t* a, const uint32_t* b) {
    asm volatile("mma.sync.aligned.m16n8k16.row.col.f32.bf16.bf16.f32 "
        "{%0,%1,%2,%3},{%4,%5,%6,%7},{%8,%9},{%0,%1,%2,%3};"
        : "+f"(d[0]), "+f"(d[1]), "+f"(d[2]), "+f"(d[3])
        : "r"(a[0]), "r"(a[1]), "r"(a[2]), "r"(a[3]), "r"(b[0]), "r"(b[1]));
}
__device__ __forceinline__ void cpa16(uint32_t dst, const void* src, int sz) {
    asm volatile("cp.async.ca.shared.global [%0], [%1], 16, %2;"
        :: "r"(dst), "l"(src), "r"(sz) : "memory");
}
__device__ __forceinline__ void cpa_commit() {
    asm volatile("cp.async.commit_group;" ::: "memory");
}
__device__ __forceinline__ void cpa_wait1() {
    asm volatile("cp.async.wait_group 1;" ::: "memory");
}
__device__ __forceinline__ void cpa_wait0() {
    asm volatile("cp.async.wait_group 0;" ::: "memory");
}

// ---------------- weight/bf16 prep ----------------
__global__ void wtrans_bf16(BWJob j0, BWJob j1, BWJob j2, BWJob j3,
                            const float* x, __nv_bfloat16* xh, __nv_bfloat16* xl, int nx,
                            float* zbuf, int zn) {
    int idx = blockIdx.x * 256 + threadIdx.x;
    if (zbuf && idx < zn) zbuf[idx] = 0.f;
    BWJob js[4] = {j0, j1, j2, j3};
    int base = 0;
    #pragma unroll
    for (int j = 0; j < 4; j++) {
        if (idx < base + js[j].n) {
            int t = idx - base;
            int K2 = js[j].KK * CD;
            int co = t / K2, k = t - co * K2;
            int tap = k >> 7, ci = k & 127;
            float v = js[j].src[(co*CD + ci) * js[j].KK + tap];
            __nv_bfloat16 h = __float2bfloat16(v);
            js[j].h[t] = h;
            js[j].l[t] = __float2bfloat16(v - __bfloat162float(h));
            return;
        }
        base += js[j].n;
    }
    int t = idx - base;
    if (t < nx) {
        float v = x[t];
        __nv_bfloat16 h = __float2bfloat16(v);
        xh[t] = h;
        xl[t] = __float2bfloat16(v - __bfloat162float(h));
    }
}

__global__ void wtrans_multi(WJobs J, float* zbuf, int zn) {
    int idx = blockIdx.x * 256 + threadIdx.x;
    if (zbuf && idx < zn) zbuf[idx] = 0.f;
    int base = 0;
    #pragma unroll
    for (int j = 0; j < 5; j++) {
        if (j >= J.nj) return;
        if (idx < base + J.n[j]) {
            int t = idx - base;
            int tap = t / (CD*CD); int rem = t - tap*(CD*CD);
            int ci = rem >> 7, co = rem & 127;
            J.dst[j][t] = J.src[j][(co*CD + ci)*J.KK[j] + tap];
            return;
        }
        base += J.n[j];
    }
}

__global__ void ln_kernel(const float* __restrict__ in, float* __restrict__ out,
                          const float* __restrict__ gam, const float* __restrict__ bet,
                          float* __restrict__ xm, float eps,
                          __nv_bfloat16* outh, __nv_bfloat16* outl) {
    int m = blockIdx.x, c = threadIdx.x, lane = c & 31, wid = c >> 5;
    float v = in[m*CD + c], s = v, sq = v*v;
    #pragma unroll
    for (int o = 16; o > 0; o >>= 1) { s += __shfl_xor_sync(~0u, s, o); sq += __shfl_xor_sync(~0u, sq, o); }
    __shared__ float ss[4], sqq[4], ys[4];
    if (lane == 0) { ss[wid] = s; sqq[wid] = sq; }
    __syncthreads();
    float S = ss[0]+ss[1]+ss[2]+ss[3], SQ = sqq[0]+sqq[1]+sqq[2]+sqq[3];
    float mean = S*(1.0f/CD), var = SQ*(1.0f/CD) - mean*mean, rs = rsqrtf(var + eps);
    float y = (v - mean)*rs*gam[c] + bet[c];
    out[m*CD + c] = y;
    if (outh) {
        __nv_bfloat16 h = __float2bfloat16(y);
        outh[m*CD + c] = h;
        outl[m*CD + c] = __float2bfloat16(y - __bfloat162float(h));
    }
    if (xm) {
        float t = y;
        #pragma unroll
        for (int o = 16; o > 0; o >>= 1) t += __shfl_xor_sync(~0u, t, o);
        if (lane == 0) ys[wid] = t;
        __syncthreads();
        if (c == 0) xm[m] = (ys[0]+ys[1]+ys[2]+ys[3])*(1.0f/CD);
    }
}

__global__ void bn_stats(const float* __restrict__ q, const float* __restrict__ k) {
    int buf = blockIdx.y;
    const float* src = buf ? k : q;
    int tid = threadIdx.x;
    int base = blockIdx.x * 128;
    float s = 0.f, sq = 0.f;
    for (int i = tid; i < 128*CD; i += 256) {
        float v = src[(base + (i >> 7))*CD + (i & 127)];
        s += v; sq += v*v;
    }
    __shared__ float sh[256];
    sh[tid] = s; __syncthreads();
    if (tid < 128) atomicAdd(&g_bnst[buf][0][tid], sh[tid] + sh[tid+128]);
    __syncthreads();
    sh[tid] = sq; __syncthreads();
    if (tid < 128) atomicAdd(&g_bnst[buf][1][tid], sh[tid] + sh[tid+128]);
}

__global__ void bn_apply(float* __restrict__ q, float* __restrict__ k,
                         const float* __restrict__ qg, const float* __restrict__ qb2,
                         const float* __restrict__ kg, const float* __restrict__ kb2) {
    int buf = blockIdx.y;
    float* dst = buf ? k : q;
    const float* gam = buf ? kg : qg;
    const float* bet = buf ? kb2 : qb2;
    int idx = blockIdx.x * 256 + threadIdx.x;
    int c = idx & 127;
    float S = g_bnst[buf][0][c], SQ = g_bnst[buf][1][c];
    float mean = S*(1.0f/MTOT), var = SQ*(1.0f/MTOT) - mean*mean;
    float sc = gam[c]*rsqrtf(var + 1e-5f), sh = bet[c] - mean*sc;
    dst[idx] = dst[idx]*sc + sh;
}

// ---------- HMMA bf16 hi/lo conv: BM=128 BN=128 BK=32, cp.async double buffer ----------
template<int KS, int SPLIT>
__global__ __launch_bounds__(256, 2) void conv_mma(MJob j0, MJob j1) {
    constexpr int K = KS*KS*KS*CD;
    constexpr int KSP = K / SPLIT;
    constexpr int NIT = KSP / 32;
    constexpr int TOT = NIT * 3;
    constexpr int STG = 128*40;            // elements per tile stage
    const int job = blockIdx.z, split = blockIdx.y;
    MJob jb = job ? j1 : j0;
    const int m0 = blockIdx.x << 7;
    const int kbase = split * KSP;
    __shared__ __align__(16) __nv_bfloat16 As[2][128][40];   // 80B row stride: ldmatrix conflict-free
    __shared__ __align__(16) __nv_bfloat16 Bs[2][128][40];
    const int tid = threadIdx.x, warp = tid >> 5, lane = tid & 31;
    const int wm = warp >> 2, wn = warp & 3;

    const int r0 = tid >> 2, q0 = tid & 3;
    int gm0 = m0 + r0, gm1 = m0 + r0 + 64;
    int bb0 = gm0 >> 11, p0 = gm0 & 2047;
    int tt0 = p0 >> 4, ii0 = (p0 >> 2) & 3, jj0 = p0 & 3;
    int bb1 = gm1 >> 11, p1 = gm1 & 2047;
    int tt1 = p1 >> 4, ii1 = (p1 >> 2) & 3, jj1 = p1 & 3;

    float acc[4][4][4];
    #pragma unroll
    for (int mf = 0; mf < 4; mf++)
        #pragma unroll
        for (int nf = 0; nf < 4; nf++)
            #pragma unroll
            for (int r = 0; r < 4; r++) acc[mf][nf][r] = 0.f;

    uint32_t abase = smem_u32(As), bbase = smem_u32(Bs);
    uint32_t aAddr[4][2], bAddr[4][2];
    #pragma unroll
    for (int mf = 0; mf < 4; mf++) {
        int arow = wm*64 + mf*16 + (lane & 7) + ((lane >> 3) & 1) * 8;
        int acol = ((lane >> 4) << 3);
        #pragma unroll
        for (int kk = 0; kk < 2; kk++)
            aAddr[mf][kk] = abase + (arow*40 + kk*16 + acol) * 2;
    }
    #pragma unroll
    for (int nf = 0; nf < 4; nf++) {
        int l = lane & 15;
        int brow = wn*32 + nf*8 + (l & 7);
        int bcol = ((l >> 3) << 3);
        #pragma unroll
        for (int kk = 0; kk < 2; kk++)
            bAddr[nf][kk] = bbase + (brow*40 + kk*16 + bcol) * 2;
    }
    // per-thread destination addresses within a stage
    uint32_t adst0 = smem_u32(&As[0][r0][q0*8]),    adst1 = smem_u32(&As[0][r0+64][q0*8]);
    uint32_t bdst0 = smem_u32(&Bs[0][r0][q0*8]),    bdst1 = smem_u32(&Bs[0][r0+64][q0*8]);

    auto load_tiles = [&](int it, int st) {
        int sec = it / NIT, itk = it - sec*NIT;
        int kc = kbase + itk*32;
        const __nv_bfloat16* Ap = (sec == 1) ? jb.inl : jb.inh;
        const __nv_bfloat16* Bp = (sec == 2) ? jb.wl  : jb.wh;
        int tap = kc >> 7;
        int4 d = (KS == 3) ? c_tap3[tap] : c_tap2[tap];
        int ci0 = (kc & 127) + q0*8;
        uint32_t so = st * STG * 2;  // byte offset of stage
        {
            int t2 = tt0 + d.x, i2 = ii0 + d.y, j2 = jj0 + d.z;
            bool v = ((unsigned)t2 < 128u) & ((unsigned)i2 < 4u) & ((unsigned)j2 < 4u);
            size_t off = ((size_t)((bb0<<11) + (t2<<4) + (i2<<2) + j2) << 7) + ci0;
            cpa16(adst0 + so, v ? (const void*)(Ap + off) : (const void*)Ap, v ? 16 : 0);
        }
        {
            int t2 = tt1 + d.x, i2 = ii1 + d.y, j2 = jj1 + d.z;
            bool v = ((unsigned)t2 < 128u) & ((unsigned)i2 < 4u) & ((unsigned)j2 < 4u);
            size_t off = ((size_t)((bb1<<11) + (t2<<4) + (i2<<2) + j2) << 7) + ci0;
            cpa16(adst1 + so, v ? (const void*)(Ap + off) : (const void*)Ap, v ? 16 : 0);
        }
        cpa16(bdst0 + so, Bp + (size_t)r0*K + kc + q0*8, 16);
        cpa16(bdst1 + so, Bp + (size_t)(r0+64)*K + kc + q0*8, 16);
    };

    load_tiles(0, 0);
    cpa_commit();

    for (int it = 0; it < TOT; it++) {
        int s = it & 1;
        bool more = (it + 1 < TOT);
        if (more) { load_tiles(it + 1, s ^ 1); cpa_commit(); }
        if (more) cpa_wait1(); else cpa_wait0();
        __syncthreads();
        uint32_t so = s * STG * 2;
        #pragma unroll
        for (int kk = 0; kk < 2; kk++) {
            uint32_t af[4][4], bf[4][2];
            #pragma unroll
            for (int mf = 0; mf < 4; mf++) ldsm_x4(af[mf], aAddr[mf][kk] + so);
            #pragma unroll
            for (int nf = 0; nf < 4; nf++) ldsm_x2(bf[nf], bAddr[nf][kk] + so);
            #pragma unroll
            for (int mf = 0; mf < 4; mf++)
                #pragma unroll
                for (int nf = 0; nf < 4; nf++)
                    mma16816(acc[mf][nf], af[mf], bf[nf]);
        }
        __syncthreads();
    }

    float* pb = g_part + ((size_t)(split*2 + job) << 19);
    #pragma unroll
    for (int mf = 0; mf < 4; mf++) {
        int row = m0 + wm*64 + mf*16 + (lane >> 2);
        #pragma unroll
        for (int nf = 0; nf < 4; nf++) {
            int col = wn*32 + nf*8 + (lane & 3)*2;
            *(float2*)(pb + (size_t)row*CD + col)     = make_float2(acc[mf][nf][0], acc[mf][nf][1]);
            *(float2*)(pb + (size_t)(row+8)*CD + col) = make_float2(acc[mf][nf][2], acc[mf][nf][3]);
        }
    }
}

template<int SPLIT>
__global__ void reduce_split(RJob j0, RJob j1) {
    int idx = blockIdx.x * 256 + threadIdx.x;
    int job = idx >> 19, r = idx & ((1 << 19) - 1);
    RJob jb = job ? j1 : j0;
    float s = 0.f;
    #pragma unroll
    for (int sp = 0; sp < SPLIT; sp++)
        s += g_part[((size_t)(sp*2 + job) << 19) + r];
    if (jb.bias) s += jb.bias[r & 127];
    if (jb.res)  s += jb.res[r];
    jb.out[r] = s;
    if (jb.oh) {
        __nv_bfloat16 h = __float2bfloat16(s);
        jb.oh[r] = h;
        jb.ol[r] = __float2bfloat16(s - __bfloat162float(h));
    }
}

// ---------------- small conv (KS=1 paths), unchanged ----------------
__global__ __launch_bounds__(128, 4) void conv_gemm_small(Job j0, Job j1) {
    constexpr int K = CD;
    constexpr int NIT = K / 16;
    Job jb = (blockIdx.z == 0) ? j0 : j1;
    const int m0 = blockIdx.y << 6, n0 = blockIdx.x << 6;
    __shared__ float As[2][16][64], Bs[2][16][64];
    const int tid = threadIdx.x;
    const int am = tid & 63, kgA = tid >> 6;
    const int gm = m0 + am;
    const int br = tid >> 4, bc = (tid & 15) << 2;
    const int warp = tid >> 5, lane = tid & 31;
    const int ty = lane >> 2;
    const int tx = (warp << 2) + (lane & 3);
    u64 acc[4][4];
    #pragma unroll
    for (int r = 0; r < 4; r++)
        #pragma unroll
        for (int c = 0; c < 4; c++) acc[r][c] = 0ull;

    auto ldA = [&](int kgabs) -> float4 {
        int ci = (kgabs << 2) & 127;
        return *(const float4*)(jb.in + ((size_t)gm << 7) + ci);
    };
    {
        float4 a0 = ldA(kgA), a1 = ldA(kgA + 2);
        float4 b0 = *(const float4*)(jb.wt + (size_t)br*CD + n0 + bc);
        float4 b1 = *(const float4*)(jb.wt + (size_t)(br+8)*CD + n0 + bc);
        int k4 = kgA << 2;
        As[0][k4+0][am]=a0.x; As[0][k4+1][am]=a0.y; As[0][k4+2][am]=a0.z; As[0][k4+3][am]=a0.w;
        As[0][k4+8][am]=a1.x; As[0][k4+9][am]=a1.y; As[0][k4+10][am]=a1.z; As[0][k4+11][am]=a1.w;
        *(float4*)&Bs[0][br][bc]   = b0;
        *(float4*)&Bs[0][br+8][bc] = b1;
    }
    __syncthreads();

    for (int it = 0; it < NIT; it++) {
        int s = it & 1;
        float4 na0, na1, nb0, nb1;
        bool more = (it + 1 < NIT);
        if (more) {
            int kg = (it+1)*4;
            na0 = ldA(kg + kgA); na1 = ldA(kg + kgA + 2);
            nb0 = *(const float4*)(jb.wt + (size_t)((it+1)*16 + br)*CD + n0 + bc);
            nb1 = *(const float4*)(jb.wt + (size_t)((it+1)*16 + br + 8)*CD + n0 + bc);
        }
        #pragma unroll
        for (int kk = 0; kk < 16; kk++) {
            F4U u0, u1;
            u0.f = *(const float4*)&As[s][kk][ty << 3];
            u1.f = *(const float4*)(&As[s][kk][ty << 3] + 4);
            u64 ap[4] = {u0.u[0], u0.u[1], u1.u[0], u1.u[1]};
            float4 bq = *(const float4*)&Bs[s][kk][tx << 2];
            u64 b0 = pack2(bq.x, bq.x), b1 = pack2(bq.y, bq.y);
            u64 b2 = pack2(bq.z, bq.z), b3 = pack2(bq.w, bq.w);
            #pragma unroll
            for (int r = 0; r < 4; r++) {
                fma2(acc[r][0], ap[r], b0);
                fma2(acc[r][1], ap[r], b1);
                fma2(acc[r][2], ap[r], b2);
                fma2(acc[r][3], ap[r], b3);
            }
        }
        if (more) {
            int so = s ^ 1, k4 = kgA << 2;
            As[so][k4+0][am]=na0.x; As[so][k4+1][am]=na0.y; As[so][k4+2][am]=na0.z; As[so][k4+3][am]=na0.w;
            As[so][k4+8][am]=na1.x; As[so][k4+9][am]=na1.y; As[so][k4+10][am]=na1.z; As[so][k4+11][am]=na1.w;
            *(float4*)&Bs[so][br][bc]   = nb0;
            *(float4*)&Bs[so][br+8][bc] = nb1;
            __syncthreads();
        }
    }

    int c0 = n0 + (tx << 2);
    float4 bias4 = make_float4(0.f,0.f,0.f,0.f);
    if (jb.bias) bias4 = *(const float4*)(jb.bias + c0);
    #pragma unroll
    for (int rp = 0; rp < 4; rp++) {
        float2 p0 = unpack2(acc[rp][0]), p1 = unpack2(acc[rp][1]);
        float2 p2 = unpack2(acc[rp][2]), p3 = unpack2(acc[rp][3]);
        int mA = m0 + (ty << 3) + (rp << 1), mB = mA + 1;
        float4 oA = make_float4(p0.x+bias4.x, p1.x+bias4.y, p2.x+bias4.z, p3.x+bias4.w);
        float4 oB = make_float4(p0.y+bias4.x, p1.y+bias4.y, p2.y+bias4.z, p3.y+bias4.w);
        if (jb.res) {
            float4 rA = *(const float4*)(jb.res + (size_t)mA*CD + c0);
            float4 rB = *(const float4*)(jb.res + (size_t)mB*CD + c0);
            oA.x += rA.x; oA.y += rA.y; oA.z += rA.z; oA.w += rA.w;
            oB.x += rB.x; oB.y += rB.y; oB.z += rB.z; oB.w += rB.w;
        }
        *(float4*)(jb.out + (size_t)mA*CD + c0) = oA;
        *(float4*)(jb.out + (size_t)mB*CD + c0) = oB;
    }
}

// ---------------- flash (unchanged, passing) ----------------
__global__ void flash_kernel(const float* __restrict__ q, const float* __restrict__ k,
                             const float* __restrict__ v, float* __restrict__ out) {
    const float LOG2E = 1.4426950408889634f;
    int bh = blockIdx.y, b = bh >> 3, h = bh & 7;
    int qbase = blockIdx.x << 6;
    __shared__ float4 ks[128][5], vs[128][5];
    int tid = threadIdx.x, wid = tid >> 5, lane = tid & 31;
    int r = lane >> 2, g = lane & 3;
    int rowA = qbase + (wid << 4) + r, rowB = rowA + 8;
    const float* qpA = q + (((b<<11) + rowA) << 7) + (h << 4);
    const float* qpB = q + (((b<<11) + rowB) << 7) + (h << 4);
    u64 qa[8], qb2[8];
    #pragma unroll
    for (int j = 0; j < 4; j++) {
        float4 ta = *(const float4*)(qpA + j*4);
        float4 tb = *(const float4*)(qpB + j*4);
        qa[j*2]   = pack2(ta.x*LOG2E, ta.y*LOG2E);
        qa[j*2+1] = pack2(ta.z*LOG2E, ta.w*LOG2E);
        qb2[j*2]   = pack2(tb.x*LOG2E, tb.y*LOG2E);
        qb2[j*2+1] = pack2(tb.z*LOG2E, tb.w*LOG2E);
    }
    u64 accA[8], accB[8];
    #pragma unroll
    for (int d = 0; d < 8; d++) { accA[d] = 0ull; accB[d] = 0ull; }
    float mA = -1e30f, mB = -1e30f, lsA = 0.f, lsB = 0.f;
    const float* kbase = k + (((size_t)b << 11) << 7) + (h << 4);
    const float* vbase = v + (((size_t)b << 11) << 7) + (h << 4);

    for (int kt = 0; kt < 2048; kt += 128) {
        __syncthreads();
        #pragma unroll
        for (int u = 0; u < 4; u++) {
            int li = tid + (u << 7);
            int row = li >> 2, j = li & 3;
            ks[row][j] = *(const float4*)(kbase + (size_t)(kt+row)*CD + (j<<2));
            vs[row][j] = *(const float4*)(vbase + (size_t)(kt+row)*CD + (j<<2));
        }
        __syncthreads();
        #pragma unroll
        for (int ch = 0; ch < 4; ch++) {
            float sA[8], sB[8];
            float tmA = -1e30f, tmB = -1e30f;
            #pragma unroll
            for (int i = 0; i < 8; i++) {
                int kc = (ch << 5) + (i << 2) + g;
                F4U k0, k1, k2, k3;
                k0.f = ks[kc][0]; k1.f = ks[kc][1]; k2.f = ks[kc][2]; k3.f = ks[kc][3];
                u64 dA = 0ull, dB = 0ull;
                fma2(dA, qa[0], k0.u[0]); fma2(dA, qa[1], k0.u[1]);
                fma2(dA, qa[2], k1.u[0]); fma2(dA, qa[3], k1.u[1]);
                fma2(dA, qa[4], k2.u[0]); fma2(dA, qa[5], k2.u[1]);
                fma2(dA, qa[6], k3.u[0]); fma2(dA, qa[7], k3.u[1]);
                fma2(dB, qb2[0], k0.u[0]); fma2(dB, qb2[1], k0.u[1]);
                fma2(dB, qb2[2], k1.u[0]); fma2(dB, qb2[3], k1.u[1]);
                fma2(dB, qb2[4], k2.u[0]); fma2(dB, qb2[5], k2.u[1]);
                fma2(dB, qb2[6], k3.u[0]); fma2(dB, qb2[7], k3.u[1]);
                float2 fa = unpack2(dA), fb = unpack2(dB);
                sA[i] = fa.x + fa.y; sB[i] = fb.x + fb.y;
                tmA = fmaxf(tmA, sA[i]); tmB = fmaxf(tmB, sB[i]);
            }
            tmA = fmaxf(tmA, __shfl_xor_sync(~0u, tmA, 1));
            tmA = fmaxf(tmA, __shfl_xor_sync(~0u, tmA, 2));
            tmB = fmaxf(tmB, __shfl_xor_sync(~0u, tmB, 1));
            tmB = fmaxf(tmB, __shfl_xor_sync(~0u, tmB, 2));
            float nA = fmaxf(mA, tmA), nB = fmaxf(mB, tmB);
            float cA = exp2f(mA - nA), cB = exp2f(mB - nB);
            mA = nA; mB = nB; lsA *= cA; lsB *= cB;
            u64 cA2 = pack2(cA, cA), cB2 = pack2(cB, cB);
            #pragma unroll
            for (int d = 0; d < 8; d++) { mul2(accA[d], cA2); mul2(accB[d], cB2); }
            #pragma unroll
            for (int i = 0; i < 8; i++) {
                int kc = (ch << 5) + (i << 2) + g;
                float pA = exp2f(sA[i] - mA), pB = exp2f(sB[i] - mB);
                lsA += pA; lsB += pB;
                u64 pA2 = pack2(pA, pA), pB2 = pack2(pB, pB);
                F4U v0, v1, v2, v3;
                v0.f = vs[kc][0]; v1.f = vs[kc][1]; v2.f = vs[kc][2]; v3.f = vs[kc][3];
                fma2(accA[0], pA2, v0.u[0]); fma2(accA[1], pA2, v0.u[1]);
                fma2(accA[2], pA2, v1.u[0]); fma2(accA[3], pA2, v1.u[1]);
                fma2(accA[4], pA2, v2.u[0]); fma2(accA[5], pA2, v2.u[1]);
                fma2(accA[6], pA2, v3.u[0]); fma2(accA[7], pA2, v3.u[1]);
                fma2(accB[0], pB2, v0.u[0]); fma2(accB[1], pB2, v0.u[1]);
                fma2(accB[2], pB2, v1.u[0]); fma2(accB[3], pB2, v1.u[1]);
                fma2(accB[4], pB2, v2.u[0]); fma2(accB[5], pB2, v2.u[1]);
                fma2(accB[6], pB2, v3.u[0]); fma2(accB[7], pB2, v3.u[1]);
            }
        }
    }
    float aA[16], aB[16];
    #pragma unroll
    for (int d = 0; d < 8; d++) {
        float2 fa = unpack2(accA[d]), fb = unpack2(accB[d]);
        aA[d*2] = fa.x; aA[d*2+1] = fa.y;
        aB[d*2] = fb.x; aB[d*2+1] = fb.y;
    }
    #pragma unroll
    for (int d = 0; d < 16; d++) {
        aA[d] += __shfl_xor_sync(~0u, aA[d], 1);
        aA[d] += __shfl_xor_sync(~0u, aA[d], 2);
        aB[d] += __shfl_xor_sync(~0u, aB[d], 1);
        aB[d] += __shfl_xor_sync(~0u, aB[d], 2);
    }
    lsA += __shfl_xor_sync(~0u, lsA, 1); lsA += __shfl_xor_sync(~0u, lsA, 2);
    lsB += __shfl_xor_sync(~0u, lsB, 1); lsB += __shfl_xor_sync(~0u, lsB, 2);
    float invA = 1.0f / lsA, invB = 1.0f / lsB;
    #pragma unroll
    for (int rr = 0; rr < 2; rr++) {
        int qrow = rr ? rowB : rowA;
        float inv = rr ? invB : invA;
        float* ac = rr ? aB : aA;
        size_t base = ((size_t)((b<<11) + qrow) << 7) + (h << 4);
        float ov[4];
        #pragma unroll
        for (int u = 0; u < 4; u++) {
            int w2 = (g << 2) + u;
            float ca = 0.f;
            #pragma unroll
            for (int s2 = 0; s2 < 3; s2++) {
                int f = w2 + (s2 << 4);
                int sel = f % 3;
                const float* tp = (sel == 0) ? q : ((sel == 1) ? k : v);
                ca += tp[base + f/3];
            }
            ov[u] = ac[(g<<2)+u]*inv + ca*(1.0f/3.0f);
        }
        *(float4*)(out + base + (g << 2)) = make_float4(ov[0], ov[1], ov[2], ov[3]);
    }
}

__global__ void combine_ln(const float* __restrict__ a1, const float* __restrict__ a2,
                           const float* __restrict__ a3, const float* __restrict__ hh,
                           const float* __restrict__ gam, const float* __restrict__ bet,
                           float* __restrict__ x2, float* __restrict__ y2,
                           float* __restrict__ xm) {
    int m = blockIdx.x, c = threadIdx.x, lane = c & 31, wid = c >> 5;
    float sacc = 0.f;
    #pragma unroll
    for (int s2 = 0; s2 < 3; s2++) {
        int f = c*3 + s2;
        const float* ap = (f >> 7) == 0 ? a1 : ((f >> 7) == 1 ? a2 : a3);
        sacc += ap[(m << 7) + (f & 127)];
    }
    float v = sacc*(1.0f/3.0f) + hh[m*CD + c];
    x2[m*CD + c] = v;
    float s = v, sq = v*v;
    #pragma unroll
    for (int o = 16; o > 0; o >>= 1) { s += __shfl_xor_sync(~0u, s, o); sq += __shfl_xor_sync(~0u, sq, o); }
    __shared__ float ss[4], sqq[4], ys[4];
    if (lane == 0) { ss[wid] = s; sqq[wid] = sq; }
    __syncthreads();
    float S = ss[0]+ss[1]+ss[2]+ss[3], SQ = sqq[0]+sqq[1]+sqq[2]+sqq[3];
    float mean = S*(1.0f/CD), var = SQ*(1.0f/CD) - mean*mean, rs = rsqrtf(var + 1e-6f);
    float y = (v - mean)*rs*gam[c] + bet[c];
    y2[m*CD + c] = y;
    float t = y;
    #pragma unroll
    for (int o = 16; o > 0; o >>= 1) t += __shfl_xor_sync(~0u, t, o);
    if (lane == 0) ys[wid] = t;
    __syncthreads();
    if (c == 0) xm[m] = (ys[0]+ys[1]+ys[2]+ys[3])*(1.0f/CD);
}

__global__ void final_kernel(const float* __restrict__ x2, const float* __restrict__ y2,
                             const float* __restrict__ xm, const float* __restrict__ st1,
                             const float* __restrict__ st2, const float* __restrict__ st3,
                             float* __restrict__ out) {
    int m = blockIdx.x, b = m >> 11, p = m & 2047;
    int t = p >> 4, ii = (p >> 2) & 3, jj = p & 3;
    __shared__ float sg;
    if (threadIdx.x == 0) {
        float gg = st1[0] * xm[m];
        #pragma unroll
        for (int kd = 0; kd < 2; kd++)
        for (int kh = 0; kh < 2; kh++)
        for (int kw = 0; kw < 2; kw++) {
            int t2 = t + kd - 1, i2 = ii + kh - 1, j2 = jj + kw - 1;
            if ((unsigned)t2 < 128u && (unsigned)i2 < 4u && (unsigned)j2 < 4u)
                gg += st2[kd*4 + kh*2 + kw] * xm[(b<<11) + (t2<<4) + (i2<<2) + j2];
        }
        #pragma unroll
        for (int kd = 0; kd < 3; kd++)
        for (int kh = 0; kh < 3; kh++)
        for (int kw = 0; kw < 3; kw++) {
            int t2 = t + kd - 1, i2 = ii + kh - 1, j2 = jj + kw - 1;
            if ((unsigned)t2 < 128u && (unsigned)i2 < 4u && (unsigned)j2 < 4u)
                gg += st3[kd*9 + kh*3 + kw] * xm[(b<<11) + (t2<<4) + (i2<<2) + j2];
        }
        sg = 1.0f / (1.0f + __expf(-gg));
    }
    __syncthreads();
    int idx = m*CD + threadIdx.x;
    out[idx] = x2[idx] + y2[idx]*sg;
}

extern "C" void kernel_launch(void* const* d_in, const int* in_sizes, int n_in,
                              void* d_out, int out_size) {
    const float* x      = (const float*)d_in[0];
    const float* n1g    = (const float*)d_in[1];
    const float* n1b    = (const float*)d_in[2];
    const float* q_w    = (const float*)d_in[3];
    const float* qbg    = (const float*)d_in[4];
    const float* qbb    = (const float*)d_in[5];
    const float* k_w    = (const float*)d_in[6];
    const float* kbg    = (const float*)d_in[7];
    const float* kbb    = (const float*)d_in[8];
    const float* v_w    = (const float*)d_in[9];
    const float* proj_w = (const float*)d_in[10];
    const float* proj_b = (const float*)d_in[11];
    const float* r1_w   = (const float*)d_in[12];
    const float* r2_w   = (const float*)d_in[13];
    const float* r3_w   = (const float*)d_in[14];
    const float* n2g    = (const float*)d_in[15];
    const float* n2b    = (const float*)d_in[16];
    const float* st1    = (const float*)d_in[17];
    const float* st2    = (const float*)d_in[18];
    const float* st3    = (const float*)d_in[19];
    float* out = (float*)d_out;

    float *y1,*qb,*kb,*vb,*attn,*hb,*a1,*a2,*a3,*x2,*y2,*xm;
    float *wv,*wr3,*wp,*bnst;
    __nv_bfloat16 *wqh,*wql,*wr1h,*wr1l,*wkh,*wkl,*wr2h,*wr2l;
    __nv_bfloat16 *y1h,*y1l,*xh,*xl,*a1h,*a1l;
    cudaGetSymbolAddress((void**)&y1, g_y1);     cudaGetSymbolAddress((void**)&qb, g_qb);
    cudaGetSymbolAddress((void**)&kb, g_kb);     cudaGetSymbolAddress((void**)&vb, g_vb);
    cudaGetSymbolAddress((void**)&attn, g_attn); cudaGetSymbolAddress((void**)&hb, g_hb);
    cudaGetSymbolAddress((void**)&a1, g_a1);     cudaGetSymbolAddress((void**)&a2, g_a2);
    cudaGetSymbolAddress((void**)&a3, g_a3);     cudaGetSymbolAddress((void**)&x2, g_x2);
    cudaGetSymbolAddress((void**)&y2, g_y2);     cudaGetSymbolAddress((void**)&xm, g_xm);
    cudaGetSymbolAddress((void**)&wv, g_wv);     cudaGetSymbolAddress((void**)&wr3, g_wr3);
    cudaGetSymbolAddress((void**)&wp, g_wp);     cudaGetSymbolAddress((void**)&bnst, g_bnst);
    cudaGetSymbolAddress((void**)&wqh, g_wqh);   cudaGetSymbolAddress((void**)&wql, g_wql);
    cudaGetSymbolAddress((void**)&wr1h, g_wr1h); cudaGetSymbolAddress((void**)&wr1l, g_wr1l);
    cudaGetSymbolAddress((void**)&wkh, g_wkh);   cudaGetSymbolAddress((void**)&wkl, g_wkl);
    cudaGetSymbolAddress((void**)&wr2h, g_wr2h); cudaGetSymbolAddress((void**)&wr2l, g_wr2l);
    cudaGetSymbolAddress((void**)&y1h, g_y1h);   cudaGetSymbolAddress((void**)&y1l, g_y1l);
    cudaGetSymbolAddress((void**)&xh, g_xh);     cudaGetSymbolAddress((void**)&xl, g_xl);
    cudaGetSymbolAddress((void**)&a1h, g_a1h);   cudaGetSymbolAddress((void**)&a1l, g_a1l);

    auto cdiv = [](int a, int b){ return (a + b - 1) / b; };
    const int n27 = 27*CD*CD, n8 = 8*CD*CD, n1 = CD*CD, nx = MTOT*CD;

    BWJob bq  = { q_w,  wqh,  wql,  27, n27 };
    BWJob br1 = { r1_w, wr1h, wr1l, 27, n27 };
    BWJob bk  = { k_w,  wkh,  wkl,  8,  n8  };
    BWJob br2 = { r2_w, wr2h, wr2l, 8,  n8  };
    WJobs ws = {};
    ws.nj = 3;
    ws.src[0]=v_w;   ws.dst[0]=wv;  ws.KK[0]=1; ws.n[0]=n1;
    ws.src[1]=r3_w;  ws.dst[1]=wr3; ws.KK[1]=1; ws.n[1]=n1;
    ws.src[2]=proj_w;ws.dst[2]=wp;  ws.KK[2]=1; ws.n[2]=n1;

    wtrans_bf16<<<cdiv(2*n27 + 2*n8 + nx, 256), 256>>>(bq, br1, bk, br2, x, xh, xl, nx, bnst, 2*2*CD);
    wtrans_multi<<<cdiv(3*n1, 256), 256>>>(ws, nullptr, 0);
    ln_kernel<<<MTOT, 128>>>(x, y1, n1g, n1b, nullptr, 1e-6f, y1h, y1l);

    MJob mq  = { y1h, y1l, wqh,  wql  };
    MJob mr1 = { xh,  xl,  wr1h, wr1l };
    conv_mma<3,4><<<dim3(32,4,2), 256>>>(mq, mr1);
    RJob rq  = { nullptr, nullptr, qb, nullptr, nullptr };
    RJob rr1 = { x,       nullptr, a1, a1h,     a1l     };
    reduce_split<4><<<MTOT*CD*2/256, 256>>>(rq, rr1);

    MJob mk  = { y1h, y1l, wkh,  wkl  };
    MJob mr2 = { a1h, a1l, wr2h, wr2l };
    conv_mma<2,4><<<dim3(32,4,2), 256>>>(mk, mr2);
    RJob rk  = { nullptr, nullptr, kb, nullptr, nullptr };
    RJob rr2 = { a1,      nullptr, a2, nullptr, nullptr };
    reduce_split<4><<<MTOT*CD*2/256, 256>>>(rk, rr2);

    bn_stats<<<dim3(32,2), 256>>>(qb, kb);
    bn_apply<<<dim3(MTOT*CD/256,2), 256>>>(qb, kb, qbg, qbb, kbg, kbb);

    Job jv  = { y1, wv,  nullptr, nullptr, vb };
    Job jr3 = { a2, wr3, a2,      nullptr, a3 };
    conv_gemm_small<<<dim3(2,64,2), 128>>>(jv, jr3);

    flash_kernel<<<dim3(32,16), 128>>>(qb, kb, vb, attn);

    Job jp = { attn, wp, nullptr, proj_b, hb };
    conv_gemm_small<<<dim3(2,64,1), 128>>>(jp, jp);

    combine_ln<<<MTOT, 128>>>(a1, a2, a3, hb, n2g, n2b, x2, y2, xm);
    final_kernel<<<MTOT, 128>>>(x2, y2, xm, st1, st2, st3, out);
}

// round 16
// speedup vs baseline: 3.5770x; 1.3513x over previous
#include <cuda_runtime.h>
#include <cuda_bf16.h>
#include <cstdint>
#include <math.h>

#define CD 128
#define MTOT 4096

typedef unsigned long long u64;

__device__ __forceinline__ u64 pack2(float lo, float hi) {
    u64 r; asm("mov.b64 %0,{%1,%2};" : "=l"(r) : "f"(lo), "f"(hi)); return r;
}
__device__ __forceinline__ void fma2(u64& d, u64 a, u64 b) {
    asm("fma.rn.f32x2 %0,%1,%2,%0;" : "+l"(d) : "l"(a), "l"(b));
}
__device__ __forceinline__ float2 unpack2(u64 v) {
    float2 f; asm("mov.b64 {%0,%1},%2;" : "=f"(f.x), "=f"(f.y) : "l"(v)); return f;
}

union F4U { float4 f; u64 u[2]; };

struct Job  { const float* in; const float* wt; const float* res; const float* bias; float* out;
              __nv_bfloat16* oh; __nv_bfloat16* ol; };
struct WJobs { const float* src[5]; float* dst[5]; int KK[5]; int n[5]; int nj; };
struct MJob { const __nv_bfloat16* inh; const __nv_bfloat16* inl;
              const __nv_bfloat16* wh;  const __nv_bfloat16* wl; };
struct RJob { const float* res; const float* bias; float* out;
              __nv_bfloat16* oh; __nv_bfloat16* ol; };
struct BWJob { const float* src; __nv_bfloat16* h; __nv_bfloat16* l; int KK; int n; };

__constant__ int4 c_tap3[27] = {
    {-1,-1,-1,0},{-1,-1,0,0},{-1,-1,1,0},{-1,0,-1,0},{-1,0,0,0},{-1,0,1,0},{-1,1,-1,0},{-1,1,0,0},{-1,1,1,0},
    { 0,-1,-1,0},{ 0,-1,0,0},{ 0,-1,1,0},{ 0,0,-1,0},{ 0,0,0,0},{ 0,0,1,0},{ 0,1,-1,0},{ 0,1,0,0},{ 0,1,1,0},
    { 1,-1,-1,0},{ 1,-1,0,0},{ 1,-1,1,0},{ 1,0,-1,0},{ 1,0,0,0},{ 1,0,1,0},{ 1,1,-1,0},{ 1,1,0,0},{ 1,1,1,0}
};
__constant__ int4 c_tap2[8] = {
    {-1,-1,-1,0},{-1,-1,0,0},{-1,0,-1,0},{-1,0,0,0},
    { 0,-1,-1,0},{ 0,-1,0,0},{ 0,0,-1,0},{ 0,0,0,0}
};

__device__ float g_y1[MTOT*CD], g_qb[MTOT*CD], g_kb[MTOT*CD], g_vb[MTOT*CD];
__device__ float g_attn[MTOT*CD], g_hb[MTOT*CD], g_a1[MTOT*CD], g_a2[MTOT*CD], g_a3[MTOT*CD];
__device__ float g_x2[MTOT*CD], g_y2[MTOT*CD], g_xm[MTOT];
__device__ float g_wv[CD*CD], g_wr3[CD*CD], g_wp[CD*CD];
__device__ float g_bnst[2][2][CD];
__device__ float g_part[9*2*MTOT*CD];
__device__ __nv_bfloat16 g_wqh[27*CD*CD], g_wql[27*CD*CD];
__device__ __nv_bfloat16 g_wr1h[27*CD*CD], g_wr1l[27*CD*CD];
__device__ __nv_bfloat16 g_wkh[8*CD*CD], g_wkl[8*CD*CD];
__device__ __nv_bfloat16 g_wr2h[8*CD*CD], g_wr2l[8*CD*CD];
__device__ __nv_bfloat16 g_y1h[MTOT*CD], g_y1l[MTOT*CD];
__device__ __nv_bfloat16 g_xh[MTOT*CD], g_xl[MTOT*CD];
__device__ __nv_bfloat16 g_a1h[MTOT*CD], g_a1l[MTOT*CD];
__device__ __nv_bfloat16 g_qbh[MTOT*CD], g_qbl[MTOT*CD];
__device__ __nv_bfloat16 g_kbh[MTOT*CD], g_kbl[MTOT*CD];
__device__ __nv_bfloat16 g_vbh[MTOT*CD], g_vbl[MTOT*CD];

// ---------------- mma.sync helpers ----------------
__device__ __forceinline__ uint32_t smem_u32(const void* p) {
    uint32_t a; asm("{ .reg .u64 t; cvta.to.shared.u64 t, %1; cvt.u32.u64 %0, t; }" : "=r"(a) : "l"(p));
    return a;
}
__device__ __forceinline__ void ldsm_x4(uint32_t* r, uint32_t a) {
    asm volatile("ldmatrix.sync.aligned.m8n8.x4.shared.b16 {%0,%1,%2,%3}, [%4];"
        : "=r"(r[0]), "=r"(r[1]), "=r"(r[2]), "=r"(r[3]) : "r"(a));
}
__device__ __forceinline__ void ldsm_x2(uint32_t* r, uint32_t a) {
    asm volatile("ldmatrix.sync.aligned.m8n8.x2.shared.b16 {%0,%1}, [%2];"
        : "=r"(r[0]), "=r"(r[1]) : "r"(a));
}
__device__ __forceinline__ void ldsm_x2t(uint32_t* r, uint32_t a) {
    asm volatile("ldmatrix.sync.aligned.m8n8.x2.trans.shared.b16 {%0,%1}, [%2];"
        : "=r"(r[0]), "=r"(r[1]) : "r"(a));
}
__device__ __forceinline__ void mma16816(float* d, const uint32_t* a, const uint32_t* b) {
    asm volatile("mma.sync.aligned.m16n8k16.row.col.f32.bf16.bf16.f32 "
        "{%0,%1,%2,%3},{%4,%5,%6,%7},{%8,%9},{%0,%1,%2,%3};"
        : "+f"(d[0]), "+f"(d[1]), "+f"(d[2]), "+f"(d[3])
        : "r"(a[0]), "r"(a[1]), "r"(a[2]), "r"(a[3]), "r"(b[0]), "r"(b[1]));
}
__device__ __forceinline__ uint32_t packbf(float lo, float hi) {
    uint32_t r; asm("cvt.rn.bf16x2.f32 %0, %1, %2;" : "=r"(r) : "f"(hi), "f"(lo)); return r;
}
__device__ __forceinline__ void cpa16(uint32_t dst, const void* src, int sz) {
    asm volatile("cp.async.ca.shared.global [%0], [%1], 16, %2;"
        :: "r"(dst), "l"(src), "r"(sz) : "memory");
}
__device__ __forceinline__ void cpa_commit() { asm volatile("cp.async.commit_group;" ::: "memory"); }
__device__ __forceinline__ void cpa_wait1() { asm volatile("cp.async.wait_group 1;" ::: "memory"); }
__device__ __forceinline__ void cpa_wait0() { asm volatile("cp.async.wait_group 0;" ::: "memory"); }

// ---------------- weight/bf16 prep ----------------
__global__ void wtrans_bf16(BWJob j0, BWJob j1, BWJob j2, BWJob j3,
                            const float* x, __nv_bfloat16* xh, __nv_bfloat16* xl, int nx,
                            float* zbuf, int zn) {
    int idx = blockIdx.x * 256 + threadIdx.x;
    if (zbuf && idx < zn) zbuf[idx] = 0.f;
    BWJob js[4] = {j0, j1, j2, j3};
    int base = 0;
    #pragma unroll
    for (int j = 0; j < 4; j++) {
        if (idx < base + js[j].n) {
            int t = idx - base;
            int K2 = js[j].KK * CD;
            int co = t / K2, k = t - co * K2;
            int tap = k >> 7, ci = k & 127;
            float v = js[j].src[(co*CD + ci) * js[j].KK + tap];
            __nv_bfloat16 h = __float2bfloat16(v);
            js[j].h[t] = h;
            js[j].l[t] = __float2bfloat16(v - __bfloat162float(h));
            return;
        }
        base += js[j].n;
    }
    int t = idx - base;
    if (t < nx) {
        float v = x[t];
        __nv_bfloat16 h = __float2bfloat16(v);
        xh[t] = h;
        xl[t] = __float2bfloat16(v - __bfloat162float(h));
    }
}

__global__ void wtrans_multi(WJobs J, float* zbuf, int zn) {
    int idx = blockIdx.x * 256 + threadIdx.x;
    if (zbuf && idx < zn) zbuf[idx] = 0.f;
    int base = 0;
    #pragma unroll
    for (int j = 0; j < 5; j++) {
        if (j >= J.nj) return;
        if (idx < base + J.n[j]) {
            int t = idx - base;
            int tap = t / (CD*CD); int rem = t - tap*(CD*CD);
            int ci = rem >> 7, co = rem & 127;
            J.dst[j][t] = J.src[j][(co*CD + ci)*J.KK[j] + tap];
            return;
        }
        base += J.n[j];
    }
}

__global__ void ln_kernel(const float* __restrict__ in, float* __restrict__ out,
                          const float* __restrict__ gam, const float* __restrict__ bet,
                          float* __restrict__ xm, float eps,
                          __nv_bfloat16* outh, __nv_bfloat16* outl) {
    int m = blockIdx.x, c = threadIdx.x, lane = c & 31, wid = c >> 5;
    float v = in[m*CD + c], s = v, sq = v*v;
    #pragma unroll
    for (int o = 16; o > 0; o >>= 1) { s += __shfl_xor_sync(~0u, s, o); sq += __shfl_xor_sync(~0u, sq, o); }
    __shared__ float ss[4], sqq[4], ys[4];
    if (lane == 0) { ss[wid] = s; sqq[wid] = sq; }
    __syncthreads();
    float S = ss[0]+ss[1]+ss[2]+ss[3], SQ = sqq[0]+sqq[1]+sqq[2]+sqq[3];
    float mean = S*(1.0f/CD), var = SQ*(1.0f/CD) - mean*mean, rs = rsqrtf(var + eps);
    float y = (v - mean)*rs*gam[c] + bet[c];
    out[m*CD + c] = y;
    if (outh) {
        __nv_bfloat16 h = __float2bfloat16(y);
        outh[m*CD + c] = h;
        outl[m*CD + c] = __float2bfloat16(y - __bfloat162float(h));
    }
    if (xm) {
        float t = y;
        #pragma unroll
        for (int o = 16; o > 0; o >>= 1) t += __shfl_xor_sync(~0u, t, o);
        if (lane == 0) ys[wid] = t;
        __syncthreads();
        if (c == 0) xm[m] = (ys[0]+ys[1]+ys[2]+ys[3])*(1.0f/CD);
    }
}

__global__ void bn_stats(const float* __restrict__ q, const float* __restrict__ k) {
    int buf = blockIdx.y;
    const float* src = buf ? k : q;
    int tid = threadIdx.x;
    int base = blockIdx.x * 128;
    float s = 0.f, sq = 0.f;
    for (int i = tid; i < 128*CD; i += 256) {
        float v = src[(base + (i >> 7))*CD + (i & 127)];
        s += v; sq += v*v;
    }
    __shared__ float sh[256];
    sh[tid] = s; __syncthreads();
    if (tid < 128) atomicAdd(&g_bnst[buf][0][tid], sh[tid] + sh[tid+128]);
    __syncthreads();
    sh[tid] = sq; __syncthreads();
    if (tid < 128) atomicAdd(&g_bnst[buf][1][tid], sh[tid] + sh[tid+128]);
}

__global__ void bn_apply(float* __restrict__ q, float* __restrict__ k,
                         const float* __restrict__ qg, const float* __restrict__ qb2,
                         const float* __restrict__ kg, const float* __restrict__ kb2,
                         __nv_bfloat16* qhh, __nv_bfloat16* qll,
                         __nv_bfloat16* khh, __nv_bfloat16* kll) {
    const float LOG2E = 1.4426950408889634f;
    int buf = blockIdx.y;
    float* dst = buf ? k : q;
    const float* gam = buf ? kg : qg;
    const float* bet = buf ? kb2 : qb2;
    int idx = blockIdx.x * 256 + threadIdx.x;
    int c = idx & 127;
    float S = g_bnst[buf][0][c], SQ = g_bnst[buf][1][c];
    float mean = S*(1.0f/MTOT), var = SQ*(1.0f/MTOT) - mean*mean;
    float sc = gam[c]*rsqrtf(var + 1e-5f), sh = bet[c] - mean*sc;
    float val = dst[idx]*sc + sh;
    dst[idx] = val;
    if (buf == 0) {
        float vs = val * LOG2E;
        __nv_bfloat16 h = __float2bfloat16(vs);
        qhh[idx] = h; qll[idx] = __float2bfloat16(vs - __bfloat162float(h));
    } else {
        __nv_bfloat16 h = __float2bfloat16(val);
        khh[idx] = h; kll[idx] = __float2bfloat16(val - __bfloat162float(h));
    }
}

// ---------- HMMA bf16 hi/lo conv: BM=128 BN=128 BK=32, cp.async double buffer ----------
template<int KS, int SPLIT>
__global__ __launch_bounds__(256, 2) void conv_mma(MJob j0, MJob j1) {
    constexpr int K = KS*KS*KS*CD;
    constexpr int KSP = K / SPLIT;
    constexpr int NIT = KSP / 32;
    constexpr int TOT = NIT * 3;
    constexpr int STG = 128*40;
    const int job = blockIdx.z, split = blockIdx.y;
    MJob jb = job ? j1 : j0;
    const int m0 = blockIdx.x << 7;
    const int kbase = split * KSP;
    __shared__ __align__(16) __nv_bfloat16 As[2][128][40];
    __shared__ __align__(16) __nv_bfloat16 Bs[2][128][40];
    const int tid = threadIdx.x, warp = tid >> 5, lane = tid & 31;
    const int wm = warp >> 2, wn = warp & 3;

    const int r0 = tid >> 2, q0 = tid & 3;
    int gm0 = m0 + r0, gm1 = m0 + r0 + 64;
    int bb0 = gm0 >> 11, p0 = gm0 & 2047;
    int tt0 = p0 >> 4, ii0 = (p0 >> 2) & 3, jj0 = p0 & 3;
    int bb1 = gm1 >> 11, p1 = gm1 & 2047;
    int tt1 = p1 >> 4, ii1 = (p1 >> 2) & 3, jj1 = p1 & 3;

    float acc[4][4][4];
    #pragma unroll
    for (int mf = 0; mf < 4; mf++)
        #pragma unroll
        for (int nf = 0; nf < 4; nf++)
            #pragma unroll
            for (int r = 0; r < 4; r++) acc[mf][nf][r] = 0.f;

    uint32_t abase = smem_u32(As), bbase = smem_u32(Bs);
    uint32_t aAddr[4][2], bAddr[4][2];
    #pragma unroll
    for (int mf = 0; mf < 4; mf++) {
        int arow = wm*64 + mf*16 + (lane & 7) + ((lane >> 3) & 1) * 8;
        int acol = ((lane >> 4) << 3);
        #pragma unroll
        for (int kk = 0; kk < 2; kk++)
            aAddr[mf][kk] = abase + (arow*40 + kk*16 + acol) * 2;
    }
    #pragma unroll
    for (int nf = 0; nf < 4; nf++) {
        int l = lane & 15;
        int brow = wn*32 + nf*8 + (l & 7);
        int bcol = ((l >> 3) << 3);
        #pragma unroll
        for (int kk = 0; kk < 2; kk++)
            bAddr[nf][kk] = bbase + (brow*40 + kk*16 + bcol) * 2;
    }
    uint32_t adst0 = smem_u32(&As[0][r0][q0*8]),    adst1 = smem_u32(&As[0][r0+64][q0*8]);
    uint32_t bdst0 = smem_u32(&Bs[0][r0][q0*8]),    bdst1 = smem_u32(&Bs[0][r0+64][q0*8]);

    auto load_tiles = [&](int it, int st) {
        int sec = it / NIT, itk = it - sec*NIT;
        int kc = kbase + itk*32;
        const __nv_bfloat16* Ap = (sec == 1) ? jb.inl : jb.inh;
        const __nv_bfloat16* Bp = (sec == 2) ? jb.wl  : jb.wh;
        int tap = kc >> 7;
        int4 d = (KS == 3) ? c_tap3[tap] : c_tap2[tap];
        int ci0 = (kc & 127) + q0*8;
        uint32_t so = st * STG * 2;
        {
            int t2 = tt0 + d.x, i2 = ii0 + d.y, j2 = jj0 + d.z;
            bool v = ((unsigned)t2 < 128u) & ((unsigned)i2 < 4u) & ((unsigned)j2 < 4u);
            size_t off = ((size_t)((bb0<<11) + (t2<<4) + (i2<<2) + j2) << 7) + ci0;
            cpa16(adst0 + so, v ? (const void*)(Ap + off) : (const void*)Ap, v ? 16 : 0);
        }
        {
            int t2 = tt1 + d.x, i2 = ii1 + d.y, j2 = jj1 + d.z;
            bool v = ((unsigned)t2 < 128u) & ((unsigned)i2 < 4u) & ((unsigned)j2 < 4u);
            size_t off = ((size_t)((bb1<<11) + (t2<<4) + (i2<<2) + j2) << 7) + ci0;
            cpa16(adst1 + so, v ? (const void*)(Ap + off) : (const void*)Ap, v ? 16 : 0);
        }
        cpa16(bdst0 + so, Bp + (size_t)r0*K + kc + q0*8, 16);
        cpa16(bdst1 + so, Bp + (size_t)(r0+64)*K + kc + q0*8, 16);
    };

    load_tiles(0, 0);
    cpa_commit();

    for (int it = 0; it < TOT; it++) {
        int s = it & 1;
        bool more = (it + 1 < TOT);
        if (more) { load_tiles(it + 1, s ^ 1); cpa_commit(); }
        if (more) cpa_wait1(); else cpa_wait0();
        __syncthreads();
        uint32_t so = s * STG * 2;
        #pragma unroll
        for (int kk = 0; kk < 2; kk++) {
            uint32_t af[4][4], bf[4][2];
            #pragma unroll
            for (int mf = 0; mf < 4; mf++) ldsm_x4(af[mf], aAddr[mf][kk] + so);
            #pragma unroll
            for (int nf = 0; nf < 4; nf++) ldsm_x2(bf[nf], bAddr[nf][kk] + so);
            #pragma unroll
            for (int mf = 0; mf < 4; mf++)
                #pragma unroll
                for (int nf = 0; nf < 4; nf++)
                    mma16816(acc[mf][nf], af[mf], bf[nf]);
        }
        __syncthreads();
    }

    float* pb = g_part + ((size_t)(split*2 + job) << 19);
    #pragma unroll
    for (int mf = 0; mf < 4; mf++) {
        int row = m0 + wm*64 + mf*16 + (lane >> 2);
        #pragma unroll
        for (int nf = 0; nf < 4; nf++) {
            int col = wn*32 + nf*8 + (lane & 3)*2;
            *(float2*)(pb + (size_t)row*CD + col)     = make_float2(acc[mf][nf][0], acc[mf][nf][1]);
            *(float2*)(pb + (size_t)(row+8)*CD + col) = make_float2(acc[mf][nf][2], acc[mf][nf][3]);
        }
    }
}

template<int SPLIT>
__global__ void reduce_split(RJob j0, RJob j1) {
    int idx = blockIdx.x * 256 + threadIdx.x;
    int job = idx >> 19, r = idx & ((1 << 19) - 1);
    RJob jb = job ? j1 : j0;
    float s = 0.f;
    #pragma unroll
    for (int sp = 0; sp < SPLIT; sp++)
        s += g_part[((size_t)(sp*2 + job) << 19) + r];
    if (jb.bias) s += jb.bias[r & 127];
    if (jb.res)  s += jb.res[r];
    jb.out[r] = s;
    if (jb.oh) {
        __nv_bfloat16 h = __float2bfloat16(s);
        jb.oh[r] = h;
        jb.ol[r] = __float2bfloat16(s - __bfloat162float(h));
    }
}

// ---------------- small conv (KS=1 paths) ----------------
__global__ __launch_bounds__(128, 4) void conv_gemm_small(Job j0, Job j1) {
    constexpr int K = CD;
    constexpr int NIT = K / 16;
    Job jb = (blockIdx.z == 0) ? j0 : j1;
    const int m0 = blockIdx.y << 6, n0 = blockIdx.x << 6;
    __shared__ float As[2][16][64], Bs[2][16][64];
    const int tid = threadIdx.x;
    const int am = tid & 63, kgA = tid >> 6;
    const int gm = m0 + am;
    const int br = tid >> 4, bc = (tid & 15) << 2;
    const int warp = tid >> 5, lane = tid & 31;
    const int ty = lane >> 2;
    const int tx = (warp << 2) + (lane & 3);
    u64 acc[4][4];
    #pragma unroll
    for (int r = 0; r < 4; r++)
        #pragma unroll
        for (int c = 0; c < 4; c++) acc[r][c] = 0ull;

    auto ldA = [&](int kgabs) -> float4 {
        int ci = (kgabs << 2) & 127;
        return *(const float4*)(jb.in + ((size_t)gm << 7) + ci);
    };
    {
        float4 a0 = ldA(kgA), a1 = ldA(kgA + 2);
        float4 b0 = *(const float4*)(jb.wt + (size_t)br*CD + n0 + bc);
        float4 b1 = *(const float4*)(jb.wt + (size_t)(br+8)*CD + n0 + bc);
        int k4 = kgA << 2;
        As[0][k4+0][am]=a0.x; As[0][k4+1][am]=a0.y; As[0][k4+2][am]=a0.z; As[0][k4+3][am]=a0.w;
        As[0][k4+8][am]=a1.x; As[0][k4+9][am]=a1.y; As[0][k4+10][am]=a1.z; As[0][k4+11][am]=a1.w;
        *(float4*)&Bs[0][br][bc]   = b0;
        *(float4*)&Bs[0][br+8][bc] = b1;
    }
    __syncthreads();

    for (int it = 0; it < NIT; it++) {
        int s = it & 1;
        float4 na0, na1, nb0, nb1;
        bool more = (it + 1 < NIT);
        if (more) {
            int kg = (it+1)*4;
            na0 = ldA(kg + kgA); na1 = ldA(kg + kgA + 2);
            nb0 = *(const float4*)(jb.wt + (size_t)((it+1)*16 + br)*CD + n0 + bc);
            nb1 = *(const float4*)(jb.wt + (size_t)((it+1)*16 + br + 8)*CD + n0 + bc);
        }
        #pragma unroll
        for (int kk = 0; kk < 16; kk++) {
            F4U u0, u1;
            u0.f = *(const float4*)&As[s][kk][ty << 3];
            u1.f = *(const float4*)(&As[s][kk][ty << 3] + 4);
            u64 ap[4] = {u0.u[0], u0.u[1], u1.u[0], u1.u[1]};
            float4 bq = *(const float4*)&Bs[s][kk][tx << 2];
            u64 b0 = pack2(bq.x, bq.x), b1 = pack2(bq.y, bq.y);
            u64 b2 = pack2(bq.z, bq.z), b3 = pack2(bq.w, bq.w);
            #pragma unroll
            for (int r = 0; r < 4; r++) {
                fma2(acc[r][0], ap[r], b0);
                fma2(acc[r][1], ap[r], b1);
                fma2(acc[r][2], ap[r], b2);
                fma2(acc[r][3], ap[r], b3);
            }
        }
        if (more) {
            int so = s ^ 1, k4 = kgA << 2;
            As[so][k4+0][am]=na0.x; As[so][k4+1][am]=na0.y; As[so][k4+2][am]=na0.z; As[so][k4+3][am]=na0.w;
            As[so][k4+8][am]=na1.x; As[so][k4+9][am]=na1.y; As[so][k4+10][am]=na1.z; As[so][k4+11][am]=na1.w;
            *(float4*)&Bs[so][br][bc]   = nb0;
            *(float4*)&Bs[so][br+8][bc] = nb1;
            __syncthreads();
        }
    }

    int c0 = n0 + (tx << 2);
    float4 bias4 = make_float4(0.f,0.f,0.f,0.f);
    if (jb.bias) bias4 = *(const float4*)(jb.bias + c0);
    #pragma unroll
    for (int rp = 0; rp < 4; rp++) {
        float2 p0 = unpack2(acc[rp][0]), p1 = unpack2(acc[rp][1]);
        float2 p2 = unpack2(acc[rp][2]), p3 = unpack2(acc[rp][3]);
        int mA = m0 + (ty << 3) + (rp << 1), mB = mA + 1;
        float4 oA = make_float4(p0.x+bias4.x, p1.x+bias4.y, p2.x+bias4.z, p3.x+bias4.w);
        float4 oB = make_float4(p0.y+bias4.x, p1.y+bias4.y, p2.y+bias4.z, p3.y+bias4.w);
        if (jb.res) {
            float4 rA = *(const float4*)(jb.res + (size_t)mA*CD + c0);
            float4 rB = *(const float4*)(jb.res + (size_t)mB*CD + c0);
            oA.x += rA.x; oA.y += rA.y; oA.z += rA.z; oA.w += rA.w;
            oB.x += rB.x; oB.y += rB.y; oB.z += rB.z; oB.w += rB.w;
        }
        *(float4*)(jb.out + (size_t)mA*CD + c0) = oA;
        *(float4*)(jb.out + (size_t)mB*CD + c0) = oB;
        if (jb.oh) {
            float va[8] = {oA.x,oA.y,oA.z,oA.w,oB.x,oB.y,oB.z,oB.w};
            #pragma unroll
            for (int e = 0; e < 8; e++) {
                size_t gi = (size_t)(e < 4 ? mA : mB)*CD + c0 + (e & 3);
                __nv_bfloat16 h = __float2bfloat16(va[e]);
                jb.oh[gi] = h;
                jb.ol[gi] = __float2bfloat16(va[e] - __bfloat162float(h));
            }
        }
    }
}

// ---------------- flash attention on mma.sync (hi/lo bf16 split) ----------------
__global__ __launch_bounds__(256, 2) void flash_mma(
    const __nv_bfloat16* __restrict__ qh, const __nv_bfloat16* __restrict__ ql,
    const __nv_bfloat16* __restrict__ kh, const __nv_bfloat16* __restrict__ kl,
    const __nv_bfloat16* __restrict__ vh, const __nv_bfloat16* __restrict__ vl,
    const float* __restrict__ qf, const float* __restrict__ kf, const float* __restrict__ vf,
    float* __restrict__ out)
{
    int bh_ = blockIdx.y, b = bh_ >> 3, h = bh_ & 7;
    int m0 = blockIdx.x << 7;
    __shared__ __align__(16) __nv_bfloat16 Qs[2][128][24];
    __shared__ __align__(16) __nv_bfloat16 Ks[2][2][64][24];
    __shared__ __align__(16) __nv_bfloat16 Vs[2][2][64][24];
    int tid = threadIdx.x, warp = tid >> 5, lane = tid & 31;

    {   // Q tile (hi/lo) load once
        int row = tid >> 1, half = tid & 1;
        size_t src = ((size_t)((b<<11) + m0 + row))*CD + h*16 + half*8;
        cpa16(smem_u32(&Qs[0][row][half*8]), qh + src, 16);
        cpa16(smem_u32(&Qs[1][row][half*8]), ql + src, 16);
    }
    cpa_commit(); cpa_wait0(); __syncthreads();

    uint32_t Qhf[4], Qlf[4];
    {
        int r = warp*16 + (lane & 7) + ((lane >> 3) & 1)*8;
        int cc = (lane >> 4) << 3;
        ldsm_x4(Qhf, smem_u32(&Qs[0][r][cc]));
        ldsm_x4(Qlf, smem_u32(&Qs[1][r][cc]));
    }

    float O[2][4] = {};
    float m0_ = -1e30f, m1_ = -1e30f, ls0 = 0.f, ls1 = 0.f;

    const int krow = tid >> 2, kpart = tid & 3, khl = kpart >> 1, khalf = kpart & 1;
    auto load_chunk = [&](int kt, int st) {
        size_t src = ((size_t)((b<<11) + kt + krow))*CD + h*16 + khalf*8;
        const __nv_bfloat16* ks = khl ? kl : kh;
        const __nv_bfloat16* vs = khl ? vl : vh;
        cpa16(smem_u32(&Ks[st][khl][krow][khalf*8]), ks + src, 16);
        cpa16(smem_u32(&Vs[st][khl][krow][khalf*8]), vs + src, 16);
    };

    load_chunk(0, 0); cpa_commit();

    for (int c = 0; c < 32; c++) {
        int st = c & 1;
        bool more = (c + 1 < 32);
        if (more) { load_chunk((c+1)*64, st^1); cpa_commit(); }
        if (more) cpa_wait1(); else cpa_wait0();
        __syncthreads();

        float S[8][4];
        int l2 = lane & 15;
        #pragma unroll
        for (int j = 0; j < 8; j++) {
            S[j][0]=0.f; S[j][1]=0.f; S[j][2]=0.f; S[j][3]=0.f;
            uint32_t bhf[2], blf[2];
            ldsm_x2(bhf, smem_u32(&Ks[st][0][ j*8 + (l2 & 7) ][ (l2 >> 3) << 3 ]));
            ldsm_x2(blf, smem_u32(&Ks[st][1][ j*8 + (l2 & 7) ][ (l2 >> 3) << 3 ]));
            mma16816(S[j], Qhf, bhf);
            mma16816(S[j], Qhf, blf);
            mma16816(S[j], Qlf, bhf);
        }
        float tm0 = -1e30f, tm1 = -1e30f;
        #pragma unroll
        for (int j = 0; j < 8; j++) {
            tm0 = fmaxf(tm0, fmaxf(S[j][0], S[j][1]));
            tm1 = fmaxf(tm1, fmaxf(S[j][2], S[j][3]));
        }
        tm0 = fmaxf(tm0, __shfl_xor_sync(~0u, tm0, 1));
        tm0 = fmaxf(tm0, __shfl_xor_sync(~0u, tm0, 2));
        tm1 = fmaxf(tm1, __shfl_xor_sync(~0u, tm1, 1));
        tm1 = fmaxf(tm1, __shfl_xor_sync(~0u, tm1, 2));
        float n0 = fmaxf(m0_, tm0), n1 = fmaxf(m1_, tm1);
        float c0 = exp2f(m0_ - n0), c1 = exp2f(m1_ - n1);
        m0_ = n0; m1_ = n1; ls0 *= c0; ls1 *= c1;
        #pragma unroll
        for (int nf = 0; nf < 2; nf++) {
            O[nf][0] *= c0; O[nf][1] *= c0; O[nf][2] *= c1; O[nf][3] *= c1;
        }
        uint32_t Ah[4][4], Al[4][4];
        #pragma unroll
        for (int j = 0; j < 8; j++) {
            float p0 = exp2f(S[j][0] - n0), p1 = exp2f(S[j][1] - n0);
            float p2 = exp2f(S[j][2] - n1), p3 = exp2f(S[j][3] - n1);
            ls0 += p0 + p1; ls1 += p2 + p3;
            __nv_bfloat16 h0 = __float2bfloat16(p0), h1 = __float2bfloat16(p1);
            __nv_bfloat16 h2 = __float2bfloat16(p2), h3 = __float2bfloat16(p3);
            int t = j >> 1, o = (j & 1) << 1;
            Ah[t][o]   = packbf(p0, p1);
            Ah[t][o+1] = packbf(p2, p3);
            Al[t][o]   = packbf(p0 - __bfloat162float(h0), p1 - __bfloat162float(h1));
            Al[t][o+1] = packbf(p2 - __bfloat162float(h2), p3 - __bfloat162float(h3));
        }
        #pragma unroll
        for (int t = 0; t < 4; t++) {
            #pragma unroll
            for (int nf = 0; nf < 2; nf++) {
                uint32_t vhf[2], vlf[2];
                ldsm_x2t(vhf, smem_u32(&Vs[st][0][ t*16 + (lane & 15) ][ nf*8 ]));
                ldsm_x2t(vlf, smem_u32(&Vs[st][1][ t*16 + (lane & 15) ][ nf*8 ]));
                mma16816(O[nf], Ah[t], vhf);
                mma16816(O[nf], Ah[t], vlf);
                mma16816(O[nf], Al[t], vhf);
            }
        }
        __syncthreads();
    }
    ls0 += __shfl_xor_sync(~0u, ls0, 1); ls0 += __shfl_xor_sync(~0u, ls0, 2);
    ls1 += __shfl_xor_sync(~0u, ls1, 1); ls1 += __shfl_xor_sync(~0u, ls1, 2);
    float inv0 = 1.f / ls0, inv1 = 1.f / ls1;
    int r0 = m0 + warp*16 + (lane >> 2), r1 = r0 + 8;
    auto catt = [&](int grow, int w2) -> float {
        size_t base = ((size_t)((b<<11) + grow))*CD + h*16;
        float s = 0.f;
        #pragma unroll
        for (int s2 = 0; s2 < 3; s2++) {
            int f = w2 + (s2 << 4);
            int sel = f % 3;
            const float* tp = (sel == 0) ? qf : ((sel == 1) ? kf : vf);
            s += tp[base + f/3];
        }
        return s * (1.0f/3.0f);
    };
    #pragma unroll
    for (int nf = 0; nf < 2; nf++) {
        int col = nf*8 + ((lane & 3) << 1);
        size_t o0 = ((size_t)((b<<11) + r0))*CD + h*16 + col;
        size_t o1 = ((size_t)((b<<11) + r1))*CD + h*16 + col;
        *(float2*)(out + o0) = make_float2(O[nf][0]*inv0 + catt(r0, col),
                                           O[nf][1]*inv0 + catt(r0, col+1));
        *(float2*)(out + o1) = make_float2(O[nf][2]*inv1 + catt(r1, col),
                                           O[nf][3]*inv1 + catt(r1, col+1));
    }
}

__global__ void combine_ln(const float* __restrict__ a1, const float* __restrict__ a2,
                           const float* __restrict__ a3, const float* __restrict__ hh,
                           const float* __restrict__ gam, const float* __restrict__ bet,
                           float* __restrict__ x2, float* __restrict__ y2,
                           float* __restrict__ xm) {
    int m = blockIdx.x, c = threadIdx.x, lane = c & 31, wid = c >> 5;
    float sacc = 0.f;
    #pragma unroll
    for (int s2 = 0; s2 < 3; s2++) {
        int f = c*3 + s2;
        const float* ap = (f >> 7) == 0 ? a1 : ((f >> 7) == 1 ? a2 : a3);
        sacc += ap[(m << 7) + (f & 127)];
    }
    float v = sacc*(1.0f/3.0f) + hh[m*CD + c];
    x2[m*CD + c] = v;
    float s = v, sq = v*v;
    #pragma unroll
    for (int o = 16; o > 0; o >>= 1) { s += __shfl_xor_sync(~0u, s, o); sq += __shfl_xor_sync(~0u, sq, o); }
    __shared__ float ss[4], sqq[4], ys[4];
    if (lane == 0) { ss[wid] = s; sqq[wid] = sq; }
    __syncthreads();
    float S = ss[0]+ss[1]+ss[2]+ss[3], SQ = sqq[0]+sqq[1]+sqq[2]+sqq[3];
    float mean = S*(1.0f/CD), var = SQ*(1.0f/CD) - mean*mean, rs = rsqrtf(var + 1e-6f);
    float y = (v - mean)*rs*gam[c] + bet[c];
    y2[m*CD + c] = y;
    float t = y;
    #pragma unroll
    for (int o = 16; o > 0; o >>= 1) t += __shfl_xor_sync(~0u, t, o);
    if (lane == 0) ys[wid] = t;
    __syncthreads();
    if (c == 0) xm[m] = (ys[0]+ys[1]+ys[2]+ys[3])*(1.0f/CD);
}

__global__ void final_kernel(const float* __restrict__ x2, const float* __restrict__ y2,
                             const float* __restrict__ xm, const float* __restrict__ st1,
                             const float* __restrict__ st2, const float* __restrict__ st3,
                             float* __restrict__ out) {
    int m = blockIdx.x, b = m >> 11, p = m & 2047;
    int t = p >> 4, ii = (p >> 2) & 3, jj = p & 3;
    __shared__ float sg;
    if (threadIdx.x == 0) {
        float gg = st1[0] * xm[m];
        #pragma unroll
        for (int kd = 0; kd < 2; kd++)
        for (int kh = 0; kh < 2; kh++)
        for (int kw = 0; kw < 2; kw++) {
            int t2 = t + kd - 1, i2 = ii + kh - 1, j2 = jj + kw - 1;
            if ((unsigned)t2 < 128u && (unsigned)i2 < 4u && (unsigned)j2 < 4u)
                gg += st2[kd*4 + kh*2 + kw] * xm[(b<<11) + (t2<<4) + (i2<<2) + j2];
        }
        #pragma unroll
        for (int kd = 0; kd < 3; kd++)
        for (int kh = 0; kh < 3; kh++)
        for (int kw = 0; kw < 3; kw++) {
            int t2 = t + kd - 1, i2 = ii + kh - 1, j2 = jj + kw - 1;
            if ((unsigned)t2 < 128u && (unsigned)i2 < 4u && (unsigned)j2 < 4u)
                gg += st3[kd*9 + kh*3 + kw] * xm[(b<<11) + (t2<<4) + (i2<<2) + j2];
        }
        sg = 1.0f / (1.0f + __expf(-gg));
    }
    __syncthreads();
    int idx = m*CD + threadIdx.x;
    out[idx] = x2[idx] + y2[idx]*sg;
}

extern "C" void kernel_launch(void* const* d_in, const int* in_sizes, int n_in,
                              void* d_out, int out_size) {
    const float* x      = (const float*)d_in[0];
    const float* n1g    = (const float*)d_in[1];
    const float* n1b    = (const float*)d_in[2];
    const float* q_w    = (const float*)d_in[3];
    const float* qbg    = (const float*)d_in[4];
    const float* qbb    = (const float*)d_in[5];
    const float* k_w    = (const float*)d_in[6];
    const float* kbg    = (const float*)d_in[7];
    const float* kbb    = (const float*)d_in[8];
    const float* v_w    = (const float*)d_in[9];
    const float* proj_w = (const float*)d_in[10];
    const float* proj_b = (const float*)d_in[11];
    const float* r1_w   = (const float*)d_in[12];
    const float* r2_w   = (const float*)d_in[13];
    const float* r3_w   = (const float*)d_in[14];
    const float* n2g    = (const float*)d_in[15];
    const float* n2b    = (const float*)d_in[16];
    const float* st1    = (const float*)d_in[17];
    const float* st2    = (const float*)d_in[18];
    const float* st3    = (const float*)d_in[19];
    float* out = (float*)d_out;

    float *y1,*qb,*kb,*vb,*attn,*hb,*a1,*a2,*a3,*x2,*y2,*xm;
    float *wv,*wr3,*wp,*bnst;
    __nv_bfloat16 *wqh,*wql,*wr1h,*wr1l,*wkh,*wkl,*wr2h,*wr2l;
    __nv_bfloat16 *y1h,*y1l,*xh,*xl,*a1h,*a1l;
    __nv_bfloat16 *qbh,*qbl,*kbh,*kbl,*vbh,*vbl;
    cudaGetSymbolAddress((void**)&y1, g_y1);     cudaGetSymbolAddress((void**)&qb, g_qb);
    cudaGetSymbolAddress((void**)&kb, g_kb);     cudaGetSymbolAddress((void**)&vb, g_vb);
    cudaGetSymbolAddress((void**)&attn, g_attn); cudaGetSymbolAddress((void**)&hb, g_hb);
    cudaGetSymbolAddress((void**)&a1, g_a1);     cudaGetSymbolAddress((void**)&a2, g_a2);
    cudaGetSymbolAddress((void**)&a3, g_a3);     cudaGetSymbolAddress((void**)&x2, g_x2);
    cudaGetSymbolAddress((void**)&y2, g_y2);     cudaGetSymbolAddress((void**)&xm, g_xm);
    cudaGetSymbolAddress((void**)&wv, g_wv);     cudaGetSymbolAddress((void**)&wr3, g_wr3);
    cudaGetSymbolAddress((void**)&wp, g_wp);     cudaGetSymbolAddress((void**)&bnst, g_bnst);
    cudaGetSymbolAddress((void**)&wqh, g_wqh);   cudaGetSymbolAddress((void**)&wql, g_wql);
    cudaGetSymbolAddress((void**)&wr1h, g_wr1h); cudaGetSymbolAddress((void**)&wr1l, g_wr1l);
    cudaGetSymbolAddress((void**)&wkh, g_wkh);   cudaGetSymbolAddress((void**)&wkl, g_wkl);
    cudaGetSymbolAddress((void**)&wr2h, g_wr2h); cudaGetSymbolAddress((void**)&wr2l, g_wr2l);
    cudaGetSymbolAddress((void**)&y1h, g_y1h);   cudaGetSymbolAddress((void**)&y1l, g_y1l);
    cudaGetSymbolAddress((void**)&xh, g_xh);     cudaGetSymbolAddress((void**)&xl, g_xl);
    cudaGetSymbolAddress((void**)&a1h, g_a1h);   cudaGetSymbolAddress((void**)&a1l, g_a1l);
    cudaGetSymbolAddress((void**)&qbh, g_qbh);   cudaGetSymbolAddress((void**)&qbl, g_qbl);
    cudaGetSymbolAddress((void**)&kbh, g_kbh);   cudaGetSymbolAddress((void**)&kbl, g_kbl);
    cudaGetSymbolAddress((void**)&vbh, g_vbh);   cudaGetSymbolAddress((void**)&vbl, g_vbl);

    auto cdiv = [](int a, int b){ return (a + b - 1) / b; };
    const int n27 = 27*CD*CD, n8 = 8*CD*CD, n1 = CD*CD, nx = MTOT*CD;

    BWJob bq  = { q_w,  wqh,  wql,  27, n27 };
    BWJob br1 = { r1_w, wr1h, wr1l, 27, n27 };
    BWJob bk  = { k_w,  wkh,  wkl,  8,  n8  };
    BWJob br2 = { r2_w, wr2h, wr2l, 8,  n8  };
    WJobs ws = {};
    ws.nj = 3;
    ws.src[0]=v_w;   ws.dst[0]=wv;  ws.KK[0]=1; ws.n[0]=n1;
    ws.src[1]=r3_w;  ws.dst[1]=wr3; ws.KK[1]=1; ws.n[1]=n1;
    ws.src[2]=proj_w;ws.dst[2]=wp;  ws.KK[2]=1; ws.n[2]=n1;

    wtrans_bf16<<<cdiv(2*n27 + 2*n8 + nx, 256), 256>>>(bq, br1, bk, br2, x, xh, xl, nx, bnst, 2*2*CD);
    wtrans_multi<<<cdiv(3*n1, 256), 256>>>(ws, nullptr, 0);
    ln_kernel<<<MTOT, 128>>>(x, y1, n1g, n1b, nullptr, 1e-6f, y1h, y1l);

    MJob mq  = { y1h, y1l, wqh,  wql  };
    MJob mr1 = { xh,  xl,  wr1h, wr1l };
    conv_mma<3,4><<<dim3(32,4,2), 256>>>(mq, mr1);
    RJob rq  = { nullptr, nullptr, qb, nullptr, nullptr };
    RJob rr1 = { x,       nullptr, a1, a1h,     a1l     };
    reduce_split<4><<<MTOT*CD*2/256, 256>>>(rq, rr1);

    MJob mk  = { y1h, y1l, wkh,  wkl  };
    MJob mr2 = { a1h, a1l, wr2h, wr2l };
    conv_mma<2,4><<<dim3(32,4,2), 256>>>(mk, mr2);
    RJob rk  = { nullptr, nullptr, kb, nullptr, nullptr };
    RJob rr2 = { a1,      nullptr, a2, nullptr, nullptr };
    reduce_split<4><<<MTOT*CD*2/256, 256>>>(rk, rr2);

    bn_stats<<<dim3(32,2), 256>>>(qb, kb);
    bn_apply<<<dim3(MTOT*CD/256,2), 256>>>(qb, kb, qbg, qbb, kbg, kbb, qbh, qbl, kbh, kbl);

    Job jv  = { y1, wv,  nullptr, nullptr, vb, vbh, vbl };
    Job jr3 = { a2, wr3, a2,      nullptr, a3, nullptr, nullptr };
    conv_gemm_small<<<dim3(2,64,2), 128>>>(jv, jr3);

    flash_mma<<<dim3(16,16), 256>>>(qbh, qbl, kbh, kbl, vbh, vbl, qb, kb, vb, attn);

    Job jp = { attn, wp, nullptr, proj_b, hb, nullptr, nullptr };
    conv_gemm_small<<<dim3(2,64,1), 128>>>(jp, jp);

    combine_ln<<<MTOT, 128>>>(a1, a2, a3, hb, n2g, n2b, x2, y2, xm);
    final_kernel<<<MTOT, 128>>>(x2, y2, xm, st1, st2, st3, out);
}